// round 8
// baseline (speedup 1.0000x reference)
#include <cuda_runtime.h>
#include <cuda_bf16.h>
#include <cstdint>

#define BATCH 4
#define SEQ   2048
#define NH    16
#define HD    64
#define HID   1024
#define QKV3  3072
#define MROWS (BATCH * SEQ)        // 8192

// 0.125 * log2(e): folded into Q at the QKV epilogue (softmax in base-2 domain)
#define QSF 0.18033688011112042f

// ---------------------------------------------------------------------------
// Scratch (static device globals — allocation-free per harness rules)
// ---------------------------------------------------------------------------
__device__ __nv_bfloat16 g_qh[MROWS * QKV3];           // qkv hi split (48 MB)
__device__ __nv_bfloat16 g_ql[MROWS * QKV3];           // qkv lo split
__device__ int           g_mask[BATCH * SEQ];
__device__ unsigned long long g_mbits[BATCH * 32];     // 64-key tile bitmasks
__device__ __nv_bfloat16 g_sh[MROWS * HID];            // attn-out hi split
__device__ __nv_bfloat16 g_sl[MROWS * HID];            // attn-out lo split
__device__ __nv_bfloat16 g_wh[HID * HID];              // Wout^T hi
__device__ __nv_bfloat16 g_wl[HID * HID];              // Wout^T lo
// int8 pair quantization (QKV projection)
__device__ signed char   g_a1[MROWS * HID];            // activation hi byte
__device__ signed char   g_a2[MROWS * HID];            // activation lo byte
__device__ signed char   g_b1[QKV3 * HID];             // Wqkv^T hi byte [N,K]
__device__ signed char   g_b2[QKV3 * HID];             // Wqkv^T lo byte
__device__ float         g_qsA[MROWS];                 // per-row activation scale
__device__ float         g_qwB[QKV3];                  // per-col weight scale
__device__ unsigned      g_qwbits[QKV3];               // colmax accumulator (fp bits)

// ---------------------------------------------------------------------------
// PTX helpers (arch-portable sm_80+; tcgen05 unavailable via compute_103)
// ---------------------------------------------------------------------------
__device__ __forceinline__ uint32_t smem_u32(const void* p) {
    uint32_t a;
    asm("{ .reg .u64 t; cvta.to.shared.u64 t, %1; cvt.u32.u64 %0, t; }" : "=r"(a) : "l"(p));
    return a;
}
__device__ __forceinline__ void ldsm_x4(uint32_t& r0, uint32_t& r1, uint32_t& r2, uint32_t& r3,
                                        uint32_t addr) {
    asm volatile("ldmatrix.sync.aligned.m8n8.x4.shared.b16 {%0,%1,%2,%3}, [%4];"
                 : "=r"(r0), "=r"(r1), "=r"(r2), "=r"(r3) : "r"(addr));
}
__device__ __forceinline__ void ldsm_x4t(uint32_t& r0, uint32_t& r1, uint32_t& r2, uint32_t& r3,
                                         uint32_t addr) {
    asm volatile("ldmatrix.sync.aligned.m8n8.x4.trans.shared.b16 {%0,%1,%2,%3}, [%4];"
                 : "=r"(r0), "=r"(r1), "=r"(r2), "=r"(r3) : "r"(addr));
}
__device__ __forceinline__ void mma_bf16(float* c, const uint32_t* a, uint32_t b0, uint32_t b1) {
    asm volatile(
        "mma.sync.aligned.m16n8k16.row.col.f32.bf16.bf16.f32 "
        "{%0,%1,%2,%3}, {%4,%5,%6,%7}, {%8,%9}, {%0,%1,%2,%3};"
        : "+f"(c[0]), "+f"(c[1]), "+f"(c[2]), "+f"(c[3])
        : "r"(a[0]), "r"(a[1]), "r"(a[2]), "r"(a[3]), "r"(b0), "r"(b1));
}
__device__ __forceinline__ void mma_s8(int* c, const uint32_t* a, uint32_t b0, uint32_t b1) {
    asm volatile(
        "mma.sync.aligned.m16n8k32.row.col.s32.s8.s8.s32 "
        "{%0,%1,%2,%3}, {%4,%5,%6,%7}, {%8,%9}, {%0,%1,%2,%3};"
        : "+r"(c[0]), "+r"(c[1]), "+r"(c[2]), "+r"(c[3])
        : "r"(a[0]), "r"(a[1]), "r"(a[2]), "r"(a[3]), "r"(b0), "r"(b1));
}
__device__ __forceinline__ float fexp2(float x) {
    float y; asm("ex2.approx.f32 %0, %1;" : "=f"(y) : "f"(x)); return y;
}
__device__ __forceinline__ void split_pack(float x, float y, uint32_t& hp, uint32_t& lp) {
    __nv_bfloat162 hv, lv;
    hv.x = __float2bfloat16(x);
    hv.y = __float2bfloat16(y);
    lv.x = __float2bfloat16(x - __bfloat162float(hv.x));
    lv.y = __float2bfloat16(y - __bfloat162float(hv.y));
    hp = *(uint32_t*)&hv;
    lp = *(uint32_t*)&lv;
}
#define CP_ASYNC16(dst, src) \
    asm volatile("cp.async.cg.shared.global [%0], [%1], 16;" :: "r"(dst), "l"(src))
#define CP_COMMIT() asm volatile("cp.async.commit_group;" ::: "memory")
#define CP_WAIT(n)  asm volatile("cp.async.wait_group %0;" :: "n"(n) : "memory")

// ---------------------------------------------------------------------------
// Mask canonicalizer + per-64-key-tile bitmasks
// ---------------------------------------------------------------------------
__global__ void mask_convert_kernel(const void* __restrict__ raw, int n) {
    __shared__ int mode;
    if (threadIdx.x == 0) {
        unsigned w0 = ((const unsigned*)raw)[0];
        if (w0 == 1u || w0 == 0u)    mode = 0;
        else if (w0 == 0x3F800000u)  mode = 1;
        else if (w0 == 0x01010101u)  mode = 2;
        else if (w0 == 0x3F803F80u)  mode = 3;
        else                          mode = 2;
    }
    __syncthreads();
    int m = mode;
    for (int i = threadIdx.x; i < n; i += blockDim.x) {
        int v;
        if (m == 0)      v = (((const int*)raw)[i] != 0);
        else if (m == 1) v = (((const float*)raw)[i] != 0.0f);
        else if (m == 2) v = (((const unsigned char*)raw)[i] != 0);
        else { unsigned short h = ((const unsigned short*)raw)[i]; v = ((h & 0x7FFF) != 0); }
        g_mask[i] = v;
    }
    __syncthreads();
    for (int t = threadIdx.x; t < BATCH * 32; t += blockDim.x) {
        int b = t >> 5, kt = t & 31;
        unsigned long long mb = 0ull;
        for (int j = 0; j < 64; j++)
            mb |= ((unsigned long long)(g_mask[b * SEQ + kt * 64 + j] & 1)) << j;
        g_mbits[t] = mb;
    }
}

// ---------------------------------------------------------------------------
// int8 pair quantization kernels
// ---------------------------------------------------------------------------
__global__ void zeroqw_kernel() {
    int i = blockIdx.x * blockDim.x + threadIdx.x;
    if (i < QKV3) g_qwbits[i] = 0u;
}

// per-column absmax of W [K,N]
__global__ void colmaxW_kernel(const float* __restrict__ W, int K, int N) {
    int n0 = blockIdx.x * 32, k0 = blockIdx.y * 32;
    int tx = threadIdx.x & 31, ty = threadIdx.x >> 5;
    float m = 0.0f;
    for (int r = ty; r < 32; r += 8)
        m = fmaxf(m, fabsf(W[(size_t)(k0 + r) * N + n0 + tx]));
    atomicMax(&g_qwbits[n0 + tx], __float_as_uint(m));
}

// activations: per-row amax + int8 pair quantize. 1 block per row (256 thr x 4 elems)
__global__ void quantA_kernel(const float* __restrict__ X) {
    __shared__ float wmax[8];
    __shared__ float am_s;
    const int row = blockIdx.x;
    const int tid = threadIdx.x;
    const float4 v = ((const float4*)(X + (size_t)row * HID))[tid];
    float m = fmaxf(fmaxf(fabsf(v.x), fabsf(v.y)), fmaxf(fabsf(v.z), fabsf(v.w)));
#pragma unroll
    for (int o = 16; o > 0; o >>= 1) m = fmaxf(m, __shfl_xor_sync(0xffffffffu, m, o));
    if ((tid & 31) == 0) wmax[tid >> 5] = m;
    __syncthreads();
    if (tid == 0) {
        float t = wmax[0];
#pragma unroll
        for (int i = 1; i < 8; i++) t = fmaxf(t, wmax[i]);
        am_s = fmaxf(t, 1e-20f);
        g_qsA[row] = am_s / 16200.0f;
    }
    __syncthreads();
    const float invq = 16200.0f / am_s;
    int q0 = __float2int_rn(v.x * invq);
    int q1 = __float2int_rn(v.y * invq);
    int q2 = __float2int_rn(v.z * invq);
    int q3 = __float2int_rn(v.w * invq);
    int h0 = (q0 + 64) >> 7, h1 = (q1 + 64) >> 7, h2 = (q2 + 64) >> 7, h3 = (q3 + 64) >> 7;
    char4 c1 = make_char4((signed char)h0, (signed char)h1, (signed char)h2, (signed char)h3);
    char4 c2 = make_char4((signed char)(q0 - (h0 << 7)), (signed char)(q1 - (h1 << 7)),
                          (signed char)(q2 - (h2 << 7)), (signed char)(q3 - (h3 << 7)));
    ((char4*)(g_a1 + (size_t)row * HID))[tid] = c1;
    ((char4*)(g_a2 + (size_t)row * HID))[tid] = c2;
}

// W [K,N] -> BT int8 pairs [N,K] using per-column scales
__global__ void quantBT_kernel(const float* __restrict__ W, int K, int N) {
    __shared__ float tile[32][33];
    int k0 = blockIdx.y * 32, n0 = blockIdx.x * 32;
    int tx = threadIdx.x & 31, ty = threadIdx.x >> 5;
    for (int r = ty; r < 32; r += 8)
        tile[r][tx] = W[(size_t)(k0 + r) * N + n0 + tx];
    __syncthreads();
    for (int r = ty; r < 32; r += 8) {
        const int n = n0 + r;
        const float am = fmaxf(__uint_as_float(g_qwbits[n]), 1e-20f);
        const float invq = 16200.0f / am;
        int q = __float2int_rn(tile[tx][r] * invq);
        int h = (q + 64) >> 7;
        size_t o = (size_t)n * K + k0 + tx;
        g_b1[o] = (signed char)h;
        g_b2[o] = (signed char)(q - (h << 7));
        if (k0 + tx == 0) g_qwB[n] = am / 16200.0f;
    }
}

// B [K,N] fp32 -> B^T [N,K] bf16 hi/lo (Wout only)
__global__ void splitBT_kernel(const float* __restrict__ B,
                               __nv_bfloat16* __restrict__ BTh,
                               __nv_bfloat16* __restrict__ BTl, int K, int N) {
    __shared__ float tile[32][33];
    int k0 = blockIdx.y * 32, n0 = blockIdx.x * 32;
    int tx = threadIdx.x & 31, ty = threadIdx.x >> 5;
    for (int r = ty; r < 32; r += 8)
        tile[r][tx] = B[(size_t)(k0 + r) * N + n0 + tx];
    __syncthreads();
    for (int r = ty; r < 32; r += 8) {
        float v = tile[tx][r];
        __nv_bfloat16 h = __float2bfloat16(v);
        __nv_bfloat16 l = __float2bfloat16(v - __bfloat162float(h));
        size_t o = (size_t)(n0 + r) * K + k0 + tx;
        BTh[o] = h;
        BTl[o] = l;
    }
}

// ---------------------------------------------------------------------------
// int8 pair GEMM (QKV projection): C = A @ BT^T, 15-bit fixed point, 3 s8 MMAs
// per k32 unit. CTA 128x128, 8 warps (4M x 2N), warp 32x64. K-chunks 64,
// 2-stage cp.async. Epilogue: fp32 reconstruct -> QSF fold -> bf16 hi/lo.
// ---------------------------------------------------------------------------
#define IKC     64
#define ITROW   80
#define ITILE   (128 * ITROW)       // 10240
#define ISTAGE  (4 * ITILE)         // 40960: A1 | A2 | B1 | B2
#define I_SMEM  (2 * ISTAGE)        // 81920

__global__ __launch_bounds__(256, 1)
void int8_gemm_qkv(const signed char* __restrict__ A1, const signed char* __restrict__ A2,
                   const signed char* __restrict__ B1, const signed char* __restrict__ B2,
                   const float* __restrict__ qsA, const float* __restrict__ qwB,
                   __nv_bfloat16* __restrict__ Ch, __nv_bfloat16* __restrict__ Cl,
                   int M, int N, int K) {
    extern __shared__ char smem[];
    const uint32_t sb = smem_u32(smem);
    const int tid   = threadIdx.x;
    const int lane  = tid & 31;
    const int wid   = tid >> 5;
    const int warpM = wid & 3;           // 4 warps in M (32 rows each)
    const int warpN = wid >> 2;          // 2 warps in N (64 cols each)
    const int m0 = blockIdx.y * 128;
    const int n0 = blockIdx.x * 128;
    const int nch = K / IKC;             // 16

    // 2048 x 16B per stage, 256 threads -> 8 ops each
    auto load_stage = [&](int kc0, int s) {
        const uint32_t stg = sb + s * ISTAGE;
#pragma unroll
        for (int t = 0; t < 8; t++) {
            const int id  = tid + t * 256;
            const int arr = id >> 9;             // 0:A1 1:A2 2:B1 3:B2
            const int rem = id & 511;
            const int row = rem >> 2;
            const int q   = rem & 3;
            const signed char* src;
            if (arr == 0)      src = A1 + (size_t)(m0 + row) * K + kc0 + q * 16;
            else if (arr == 1) src = A2 + (size_t)(m0 + row) * K + kc0 + q * 16;
            else if (arr == 2) src = B1 + (size_t)(n0 + row) * K + kc0 + q * 16;
            else               src = B2 + (size_t)(n0 + row) * K + kc0 + q * 16;
            CP_ASYNC16(stg + arr * ITILE + row * ITROW + q * 16, src);
        }
        CP_COMMIT();
    };

    int chi[2][8][4], cmid[2][8][4];
#pragma unroll
    for (int i = 0; i < 2; i++)
#pragma unroll
        for (int j = 0; j < 8; j++)
#pragma unroll
            for (int r = 0; r < 4; r++) { chi[i][j][r] = 0; cmid[i][j][r] = 0; }

    const int g  = lane >> 2;
    const int tq = lane & 3;

    load_stage(0, 0);
    load_stage(IKC, 1);

    for (int ch = 0; ch < nch; ch++) {
        CP_WAIT(1);
        __syncthreads();
        const uint32_t stg = sb + (ch & 1) * ISTAGE;

#pragma unroll
        for (int ks = 0; ks < 2; ks++) {
            // A fragments (plain LDS.32, conflict-free with ITROW=80)
            uint32_t a1f[2][4], a2f[2][4];
#pragma unroll
            for (int mt = 0; mt < 2; mt++) {
                const uint32_t ab = stg + (uint32_t)(warpM * 32 + mt * 16 + g) * ITROW
                                  + ks * 32 + tq * 4;
                a1f[mt][0] = *(const uint32_t*)(smem + (ab - sb));
                a1f[mt][1] = *(const uint32_t*)(smem + (ab - sb) + 8 * ITROW);
                a1f[mt][2] = *(const uint32_t*)(smem + (ab - sb) + 16);
                a1f[mt][3] = *(const uint32_t*)(smem + (ab - sb) + 8 * ITROW + 16);
                a2f[mt][0] = *(const uint32_t*)(smem + (ab - sb) + ITILE);
                a2f[mt][1] = *(const uint32_t*)(smem + (ab - sb) + ITILE + 8 * ITROW);
                a2f[mt][2] = *(const uint32_t*)(smem + (ab - sb) + ITILE + 16);
                a2f[mt][3] = *(const uint32_t*)(smem + (ab - sb) + ITILE + 8 * ITROW + 16);
            }
#pragma unroll
            for (int nt = 0; nt < 8; nt++) {
                const uint32_t bb = (uint32_t)(2 * ITILE)
                                  + (uint32_t)((ch & 1) * ISTAGE)
                                  + (uint32_t)(warpN * 64 + nt * 8 + g) * ITROW
                                  + ks * 32 + tq * 4;
                uint32_t b1f0 = *(const uint32_t*)(smem + bb);
                uint32_t b1f1 = *(const uint32_t*)(smem + bb + 16);
                uint32_t b2f0 = *(const uint32_t*)(smem + bb + ITILE);
                uint32_t b2f1 = *(const uint32_t*)(smem + bb + ITILE + 16);
#pragma unroll
                for (int mt = 0; mt < 2; mt++) {
                    mma_s8(chi[mt][nt],  a1f[mt], b1f0, b1f1);   // hi*hi   (w 16384)
                    mma_s8(cmid[mt][nt], a1f[mt], b2f0, b2f1);   // hi*lo   (w 128)
                    mma_s8(cmid[mt][nt], a2f[mt], b1f0, b1f1);   // lo*hi   (w 128)
                }
            }
        }
        __syncthreads();
        if (ch + 2 < nch) load_stage((ch + 2) * IKC, ch & 1);
        else CP_COMMIT();   // placeholder group keeps CP_WAIT(1) accounting exact
    }

    // epilogue: reconstruct fp32, fold Q scale, split to bf16 hi/lo
#pragma unroll
    for (int mt = 0; mt < 2; mt++) {
        const int row0 = m0 + warpM * 32 + mt * 16 + g;
        const float qs0 = qsA[row0];
        const float qs1 = qsA[row0 + 8];
#pragma unroll
        for (int nt = 0; nt < 8; nt++) {
            const int col = n0 + warpN * 64 + nt * 8 + tq * 2;
            const float qw0 = qwB[col];
            const float qw1 = qwB[col + 1];
            const float sc = (col < HID) ? QSF : 1.0f;   // Q pre-scale
            float f0 = (16384.0f * (float)chi[mt][nt][0] + 128.0f * (float)cmid[mt][nt][0]) * qs0 * qw0 * sc;
            float f1 = (16384.0f * (float)chi[mt][nt][1] + 128.0f * (float)cmid[mt][nt][1]) * qs0 * qw1 * sc;
            float f2 = (16384.0f * (float)chi[mt][nt][2] + 128.0f * (float)cmid[mt][nt][2]) * qs1 * qw0 * sc;
            float f3 = (16384.0f * (float)chi[mt][nt][3] + 128.0f * (float)cmid[mt][nt][3]) * qs1 * qw1 * sc;
            uint32_t hp, lp;
            split_pack(f0, f1, hp, lp);
            *(uint32_t*)(Ch + (size_t)row0 * N + col) = hp;
            *(uint32_t*)(Cl + (size_t)row0 * N + col) = lp;
            split_pack(f2, f3, hp, lp);
            *(uint32_t*)(Ch + (size_t)(row0 + 8) * N + col) = hp;
            *(uint32_t*)(Cl + (size_t)(row0 + 8) * N + col) = lp;
        }
    }
}

// ---------------------------------------------------------------------------
// mma.sync bf16x3 GEMM (out-projection). R7 structure, 4 warps, 64x64 tiles.
// ---------------------------------------------------------------------------
#define KC        32
#define TROW      80
#define TILE_B    (128 * TROW)
#define STAGE_B   (4 * TILE_B)
#define TC_SMEM   (2 * STAGE_B)         // 81920

__global__ __launch_bounds__(128, 2)
void mma_gemm_out(const __nv_bfloat16* __restrict__ Ah, const __nv_bfloat16* __restrict__ Al,
                  const __nv_bfloat16* __restrict__ BTh, const __nv_bfloat16* __restrict__ BTl,
                  const float* __restrict__ bias, float* __restrict__ C,
                  int M, int N, int K) {
    extern __shared__ char smem[];
    const uint32_t sb = smem_u32(smem);
    const int tid   = threadIdx.x;
    const int lane  = tid & 31;
    const int wid   = tid >> 5;
    const int warpM = wid & 1;
    const int warpN = wid >> 1;
    const int m0 = blockIdx.y * 128;
    const int n0 = blockIdx.x * 128;
    const int nch = K / KC;

    auto load_stage = [&](int kc0, int s) {
        const uint32_t stg = sb + s * STAGE_B;
#pragma unroll
        for (int t = 0; t < 16; t++) {
            const int id   = tid + t * 128;
            const int tile = id >> 9;
            const int rem  = id & 511;
            const int row  = rem >> 2;
            const int q    = rem & 3;
            const __nv_bfloat16* src;
            if (tile == 0)      src = Ah  + (size_t)(m0 + row) * K + kc0 + q * 8;
            else if (tile == 1) src = Al  + (size_t)(m0 + row) * K + kc0 + q * 8;
            else if (tile == 2) src = BTh + (size_t)(n0 + row) * K + kc0 + q * 8;
            else                src = BTl + (size_t)(n0 + row) * K + kc0 + q * 8;
            CP_ASYNC16(stg + tile * TILE_B + row * TROW + q * 16, src);
        }
        CP_COMMIT();
    };

    float c[4][8][4];
#pragma unroll
    for (int i = 0; i < 4; i++)
#pragma unroll
        for (int j = 0; j < 8; j++)
#pragma unroll
            for (int r = 0; r < 4; r++) c[i][j][r] = 0.0f;

    const int arow = warpM * 64 + (lane & 15);
    const int acol = (lane >> 4) * 8;
    const int brow = warpN * 64 + (lane & 7) + ((lane >> 4) << 3);
    const int bck  = ((lane >> 3) & 1) * 8;

    load_stage(0, 0);
    load_stage(KC, 1);

    for (int ch = 0; ch < nch; ch++) {
        CP_WAIT(1);
        __syncthreads();

        const uint32_t stg = sb + (ch & 1) * STAGE_B;
        const uint32_t ahb = stg;
        const uint32_t alb = stg + TILE_B;
        const uint32_t bhb = stg + 2 * TILE_B;
        const uint32_t blb = stg + 3 * TILE_B;

#pragma unroll
        for (int k16 = 0; k16 < 2; k16++) {
            uint32_t fah[4][4], fal[4][4];
#pragma unroll
            for (int mt = 0; mt < 4; mt++) {
                uint32_t off = (uint32_t)(arow + mt * 16) * TROW + (k16 * 16 + acol) * 2;
                ldsm_x4(fah[mt][0], fah[mt][1], fah[mt][2], fah[mt][3], ahb + off);
                ldsm_x4(fal[mt][0], fal[mt][1], fal[mt][2], fal[mt][3], alb + off);
            }
#pragma unroll
            for (int np = 0; np < 4; np++) {
                uint32_t bh[4], bl[4];
                uint32_t off = (uint32_t)(brow + np * 16) * TROW + (k16 * 16 + bck) * 2;
                ldsm_x4(bh[0], bh[1], bh[2], bh[3], bhb + off);
                ldsm_x4(bl[0], bl[1], bl[2], bl[3], blb + off);
#pragma unroll
                for (int mt = 0; mt < 4; mt++)
#pragma unroll
                    for (int half = 0; half < 2; half++) {
                        float* acc = c[mt][np * 2 + half];
                        mma_bf16(acc, fah[mt], bh[half * 2], bh[half * 2 + 1]);
                        mma_bf16(acc, fah[mt], bl[half * 2], bl[half * 2 + 1]);
                        mma_bf16(acc, fal[mt], bh[half * 2], bh[half * 2 + 1]);
                    }
            }
        }
        __syncthreads();
        if (ch + 2 < nch) load_stage((ch + 2) * KC, ch & 1);
        else CP_COMMIT();
    }

    const int g   = lane >> 2;
    const int tig = lane & 3;
#pragma unroll
    for (int mt = 0; mt < 4; mt++) {
        const int row = m0 + warpM * 64 + mt * 16 + g;
#pragma unroll
        for (int nt = 0; nt < 8; nt++) {
            const int col = n0 + warpN * 64 + nt * 8 + tig * 2;
            float2 v0 = make_float2(c[mt][nt][0] + bias[col], c[mt][nt][1] + bias[col + 1]);
            float2 v1 = make_float2(c[mt][nt][2] + bias[col], c[mt][nt][3] + bias[col + 1]);
            *(float2*)(C + (size_t)row * N + col)       = v0;
            *(float2*)(C + (size_t)(row + 8) * N + col) = v1;
        }
    }
}

// ---------------------------------------------------------------------------
// mma.sync flash attention (bf16x3 both products). R5/R7-proven core, unchanged.
// ---------------------------------------------------------------------------
#define ATROW 144
#define ATILE (64 * ATROW)
#define ASTAGE (4 * ATILE)
#define ATT_SMEM (2 * ASTAGE + 144)

__global__ __launch_bounds__(256, 1)
void mma_attn_kernel(const __nv_bfloat16* __restrict__ Qh, const __nv_bfloat16* __restrict__ Ql,
                     __nv_bfloat16* __restrict__ Oh, __nv_bfloat16* __restrict__ Ol) {
    extern __shared__ char sm[];
    const uint32_t sb = smem_u32(sm);
    int* list = (int*)(sm + 2 * ASTAGE);

    const int tid  = threadIdx.x;
    const int lane = tid & 31;
    const int w    = tid >> 5;
    const int b    = blockIdx.z;
    const int h    = blockIdx.y;
    const int q0   = blockIdx.x * 128;
    const int g    = lane >> 2;
    const int tq   = lane & 3;

    if (w == 0) {
        unsigned long long mb = g_mbits[b * 32 + lane];
        unsigned act = __ballot_sync(0xffffffffu, mb != 0ull);
        int pos = __popc(act & ((1u << lane) - 1));
        if (mb != 0ull) list[pos] = lane;
        if (lane == 0) list[32] = __popc(act);
    }
    __syncthreads();
    const int ncnt = list[32];

    uint32_t qfh[4][4], qfl[4][4];
    {
        const size_t qb = (size_t)(b * SEQ + q0 + w * 16) * QKV3 + h * HD;
#pragma unroll
        for (int kd = 0; kd < 4; kd++) {
            const int cc = kd * 16 + tq * 2;
            qfh[kd][0] = *(const uint32_t*)(Qh + qb + (size_t)g * QKV3 + cc);
            qfh[kd][1] = *(const uint32_t*)(Qh + qb + (size_t)(g + 8) * QKV3 + cc);
            qfh[kd][2] = *(const uint32_t*)(Qh + qb + (size_t)g * QKV3 + cc + 8);
            qfh[kd][3] = *(const uint32_t*)(Qh + qb + (size_t)(g + 8) * QKV3 + cc + 8);
            qfl[kd][0] = *(const uint32_t*)(Ql + qb + (size_t)g * QKV3 + cc);
            qfl[kd][1] = *(const uint32_t*)(Ql + qb + (size_t)(g + 8) * QKV3 + cc);
            qfl[kd][2] = *(const uint32_t*)(Ql + qb + (size_t)g * QKV3 + cc + 8);
            qfl[kd][3] = *(const uint32_t*)(Ql + qb + (size_t)(g + 8) * QKV3 + cc + 8);
        }
    }

    auto load_tile = [&](int kt, int stg) {
        const int tok0 = b * SEQ + kt * 64;
        const uint32_t base = sb + stg * ASTAGE;
#pragma unroll
        for (int t = 0; t < 8; t++) {
            const int id  = tid + t * 256;
            const int arr = id >> 9;
            const int rem = id & 511;
            const int r   = rem >> 3;
            const int q   = rem & 7;
            const size_t go = (size_t)(tok0 + r) * QKV3 + h * HD + q * 8;
            const __nv_bfloat16* src;
            if (arr == 0)      src = Qh + go + HID;
            else if (arr == 1) src = Ql + go + HID;
            else if (arr == 2) src = Qh + go + 2 * HID;
            else               src = Ql + go + 2 * HID;
            CP_ASYNC16(base + arr * ATILE + r * ATROW + q * 16, src);
        }
        CP_COMMIT();
    };

    float o[8][4];
#pragma unroll
    for (int j = 0; j < 8; j++)
#pragma unroll
        for (int r = 0; r < 4; r++) o[j][r] = 0.0f;
    float mi[2] = {-1e30f, -1e30f}, li[2] = {0.0f, 0.0f};

    if (ncnt > 0) load_tile(list[0], 0);

    for (int it = 0; it < ncnt; it++) {
        if (it + 1 < ncnt) { load_tile(list[it + 1], (it + 1) & 1); CP_WAIT(1); }
        else CP_WAIT(0);
        __syncthreads();
        const uint32_t st = sb + (it & 1) * ASTAGE;
        const int kt = list[it];

        float s[8][4];
#pragma unroll
        for (int j = 0; j < 8; j++)
#pragma unroll
            for (int r = 0; r < 4; r++) s[j][r] = 0.0f;

#pragma unroll
        for (int kd = 0; kd < 4; kd++) {
#pragma unroll
            for (int kg = 0; kg < 4; kg++) {
                uint32_t kh[4], kl[4];
                const uint32_t off = st + (uint32_t)(kg * 16 + (lane & 7) + ((lane >> 4) << 3)) * ATROW
                                        + (kd * 16 + ((lane >> 3) & 1) * 8) * 2;
                ldsm_x4(kh[0], kh[1], kh[2], kh[3], off);
                ldsm_x4(kl[0], kl[1], kl[2], kl[3], off + ATILE);
                mma_bf16(s[kg * 2],     qfh[kd], kh[0], kh[1]);
                mma_bf16(s[kg * 2],     qfh[kd], kl[0], kl[1]);
                mma_bf16(s[kg * 2],     qfl[kd], kh[0], kh[1]);
                mma_bf16(s[kg * 2 + 1], qfh[kd], kh[2], kh[3]);
                mma_bf16(s[kg * 2 + 1], qfh[kd], kl[2], kl[3]);
                mma_bf16(s[kg * 2 + 1], qfl[kd], kh[2], kh[3]);
            }
        }

        const unsigned long long mb = g_mbits[b * 32 + kt];
        if (mb != ~0ull) {
#pragma unroll
            for (int nf = 0; nf < 8; nf++) {
                const int c0 = nf * 8 + tq * 2;
                if (!((mb >> c0) & 1))       { s[nf][0] = -1e30f; s[nf][2] = -1e30f; }
                if (!((mb >> (c0 + 1)) & 1)) { s[nf][1] = -1e30f; s[nf][3] = -1e30f; }
            }
        }

#pragma unroll
        for (int r = 0; r < 2; r++) {
            float mx = -1e30f;
#pragma unroll
            for (int nf = 0; nf < 8; nf++)
                mx = fmaxf(mx, fmaxf(s[nf][2 * r], s[nf][2 * r + 1]));
            mx = fmaxf(mx, __shfl_xor_sync(0xffffffffu, mx, 1));
            mx = fmaxf(mx, __shfl_xor_sync(0xffffffffu, mx, 2));
            const float mnew = fmaxf(mi[r], mx);
            const float al = fexp2(mi[r] - mnew);
            mi[r] = mnew;
            li[r] *= al;
#pragma unroll
            for (int nf = 0; nf < 8; nf++) { o[nf][2 * r] *= al; o[nf][2 * r + 1] *= al; }
            float ls = 0.0f;
#pragma unroll
            for (int nf = 0; nf < 8; nf++) {
                const float p0 = fexp2(s[nf][2 * r] - mnew);
                const float p1 = fexp2(s[nf][2 * r + 1] - mnew);
                ls += p0 + p1;
                s[nf][2 * r] = p0;
                s[nf][2 * r + 1] = p1;
            }
            ls += __shfl_xor_sync(0xffffffffu, ls, 1);
            ls += __shfl_xor_sync(0xffffffffu, ls, 2);
            li[r] += ls;
        }

        uint32_t pah[4][4], pal[4][4];
#pragma unroll
        for (int ks = 0; ks < 4; ks++) {
            split_pack(s[2 * ks][0],     s[2 * ks][1],     pah[ks][0], pal[ks][0]);
            split_pack(s[2 * ks][2],     s[2 * ks][3],     pah[ks][1], pal[ks][1]);
            split_pack(s[2 * ks + 1][0], s[2 * ks + 1][1], pah[ks][2], pal[ks][2]);
            split_pack(s[2 * ks + 1][2], s[2 * ks + 1][3], pah[ks][3], pal[ks][3]);
        }

#pragma unroll
        for (int ks = 0; ks < 4; ks++) {
#pragma unroll
            for (int dg = 0; dg < 4; dg++) {
                uint32_t vh[4], vl[4];
                const uint32_t off = st + 2 * ATILE
                                   + (uint32_t)(ks * 16 + (lane & 15)) * ATROW
                                   + (dg * 16 + ((lane >> 4) << 3)) * 2;
                ldsm_x4t(vh[0], vh[1], vh[2], vh[3], off);
                ldsm_x4t(vl[0], vl[1], vl[2], vl[3], off + ATILE);
                mma_bf16(o[dg * 2],     pah[ks], vh[0], vh[1]);
                mma_bf16(o[dg * 2],     pah[ks], vl[0], vl[1]);
                mma_bf16(o[dg * 2],     pal[ks], vh[0], vh[1]);
                mma_bf16(o[dg * 2 + 1], pah[ks], vh[2], vh[3]);
                mma_bf16(o[dg * 2 + 1], pah[ks], vl[2], vl[3]);
                mma_bf16(o[dg * 2 + 1], pal[ks], vh[2], vh[3]);
            }
        }
        __syncthreads();
    }

#pragma unroll
    for (int r = 0; r < 2; r++) {
        const float inv = 1.0f / li[r];
        const size_t ob = (size_t)(b * SEQ + q0 + w * 16 + g + r * 8) * HID + h * HD;
#pragma unroll
        for (int nf = 0; nf < 8; nf++) {
            uint32_t hp, lp;
            split_pack(o[nf][2 * r] * inv, o[nf][2 * r + 1] * inv, hp, lp);
            *(uint32_t*)(Oh + ob + nf * 8 + tq * 2) = hp;
            *(uint32_t*)(Ol + ob + nf * 8 + tq * 2) = lp;
        }
    }
}

// ---------------------------------------------------------------------------
// Launch
// ---------------------------------------------------------------------------
extern "C" void kernel_launch(void* const* d_in, const int* in_sizes, int n_in,
                              void* d_out, int out_size) {
    const float* hidden = (const float*)d_in[0];
    const void*  maskp  = d_in[1];
    const float* Wqkv   = (const float*)d_in[2];
    const float* Wout   = (const float*)d_in[3];
    const float* bout   = (const float*)d_in[4];
    float*       out    = (float*)d_out;

    void *p_qh, *p_ql, *p_sh, *p_sl, *p_wh, *p_wl;
    void *p_a1, *p_a2, *p_b1, *p_b2, *p_qsA, *p_qwB;
    cudaGetSymbolAddress(&p_qh, g_qh);
    cudaGetSymbolAddress(&p_ql, g_ql);
    cudaGetSymbolAddress(&p_sh, g_sh);
    cudaGetSymbolAddress(&p_sl, g_sl);
    cudaGetSymbolAddress(&p_wh, g_wh);
    cudaGetSymbolAddress(&p_wl, g_wl);
    cudaGetSymbolAddress(&p_a1, g_a1);
    cudaGetSymbolAddress(&p_a2, g_a2);
    cudaGetSymbolAddress(&p_b1, g_b1);
    cudaGetSymbolAddress(&p_b2, g_b2);
    cudaGetSymbolAddress(&p_qsA, g_qsA);
    cudaGetSymbolAddress(&p_qwB, g_qwB);

    cudaFuncSetAttribute(int8_gemm_qkv,
                         cudaFuncAttributeMaxDynamicSharedMemorySize, I_SMEM);
    cudaFuncSetAttribute(mma_gemm_out,
                         cudaFuncAttributeMaxDynamicSharedMemorySize, TC_SMEM);
    cudaFuncSetAttribute(mma_attn_kernel,
                         cudaFuncAttributeMaxDynamicSharedMemorySize, ATT_SMEM);

    // 1. quantization prep
    zeroqw_kernel<<<(QKV3 + 255) / 256, 256>>>();
    colmaxW_kernel<<<dim3(QKV3 / 32, HID / 32), 256>>>(Wqkv, HID, QKV3);
    quantA_kernel<<<MROWS, 256>>>(hidden);
    quantBT_kernel<<<dim3(QKV3 / 32, HID / 32), 256>>>(Wqkv, HID, QKV3);
    splitBT_kernel<<<dim3(HID / 32, HID / 32), 256>>>(
        Wout, (__nv_bfloat16*)p_wh, (__nv_bfloat16*)p_wl, HID, HID);

    // 2. QKV projection (int8 pair, 3x s8 MMA) -> bf16 hi/lo (Q pre-scaled)
    int8_gemm_qkv<<<dim3(QKV3 / 128, MROWS / 128), 256, I_SMEM>>>(
        (const signed char*)p_a1, (const signed char*)p_a2,
        (const signed char*)p_b1, (const signed char*)p_b2,
        (const float*)p_qsA, (const float*)p_qwB,
        (__nv_bfloat16*)p_qh, (__nv_bfloat16*)p_ql, MROWS, QKV3, HID);

    // 3. mask canonicalize + tile bitmasks
    mask_convert_kernel<<<1, 256>>>(maskp, BATCH * SEQ);

    // 4. tensor-core flash attention -> bf16 hi/lo attention output
    mma_attn_kernel<<<dim3(SEQ / 128, NH, BATCH), 256, ATT_SMEM>>>(
        (const __nv_bfloat16*)p_qh, (const __nv_bfloat16*)p_ql,
        (__nv_bfloat16*)p_sh, (__nv_bfloat16*)p_sl);

    // 5. output projection (bf16x3, +bias)
    mma_gemm_out<<<dim3(HID / 128, MROWS / 128), 128, TC_SMEM>>>(
        (const __nv_bfloat16*)p_sh, (const __nv_bfloat16*)p_sl,
        (const __nv_bfloat16*)p_wh, (const __nv_bfloat16*)p_wl,
        bout, out, MROWS, HID, HID);
}

// round 9
// speedup vs baseline: 1.7367x; 1.7367x over previous
#include <cuda_runtime.h>
#include <cuda_bf16.h>
#include <cstdint>

#define BATCH 4
#define SEQ   2048
#define NH    16
#define HD    64
#define HID   1024
#define QKV3  3072
#define MROWS (BATCH * SEQ)        // 8192

// 0.125 * log2(e): folded into Q at the QKV epilogue (softmax in base-2 domain)
#define QSF 0.18033688011112042f

// ---------------------------------------------------------------------------
// Scratch (static device globals — allocation-free per harness rules)
// ---------------------------------------------------------------------------
__device__ __nv_bfloat16 g_qh[MROWS * QKV3];           // qkv hi split (48 MB)
__device__ __nv_bfloat16 g_ql[MROWS * QKV3];           // qkv lo split
__device__ int           g_mask[BATCH * SEQ];
__device__ unsigned long long g_mbits[BATCH * 32];     // 64-key tile bitmasks
__device__ __nv_bfloat16 g_sh[MROWS * HID];            // activation hi (hidden, then attn out)
__device__ __nv_bfloat16 g_sl[MROWS * HID];            // activation lo
__device__ __nv_bfloat16 g_wh[(QKV3 + HID) * HID];     // W^T hi
__device__ __nv_bfloat16 g_wl[(QKV3 + HID) * HID];     // W^T lo

// ---------------------------------------------------------------------------
// PTX helpers (arch-portable sm_80+; tcgen05 unavailable via compute_103;
// s8 mma.sync measured ~4-5x worse rt than HMMA on sm_103 — do not use)
// ---------------------------------------------------------------------------
__device__ __forceinline__ uint32_t smem_u32(const void* p) {
    uint32_t a;
    asm("{ .reg .u64 t; cvta.to.shared.u64 t, %1; cvt.u32.u64 %0, t; }" : "=r"(a) : "l"(p));
    return a;
}
__device__ __forceinline__ void ldsm_x4(uint32_t& r0, uint32_t& r1, uint32_t& r2, uint32_t& r3,
                                        uint32_t addr) {
    asm volatile("ldmatrix.sync.aligned.m8n8.x4.shared.b16 {%0,%1,%2,%3}, [%4];"
                 : "=r"(r0), "=r"(r1), "=r"(r2), "=r"(r3) : "r"(addr));
}
__device__ __forceinline__ void ldsm_x4t(uint32_t& r0, uint32_t& r1, uint32_t& r2, uint32_t& r3,
                                         uint32_t addr) {
    asm volatile("ldmatrix.sync.aligned.m8n8.x4.trans.shared.b16 {%0,%1,%2,%3}, [%4];"
                 : "=r"(r0), "=r"(r1), "=r"(r2), "=r"(r3) : "r"(addr));
}
__device__ __forceinline__ void mma_bf16(float* c, const uint32_t* a, uint32_t b0, uint32_t b1) {
    asm volatile(
        "mma.sync.aligned.m16n8k16.row.col.f32.bf16.bf16.f32 "
        "{%0,%1,%2,%3}, {%4,%5,%6,%7}, {%8,%9}, {%0,%1,%2,%3};"
        : "+f"(c[0]), "+f"(c[1]), "+f"(c[2]), "+f"(c[3])
        : "r"(a[0]), "r"(a[1]), "r"(a[2]), "r"(a[3]), "r"(b0), "r"(b1));
}
__device__ __forceinline__ float fexp2(float x) {
    float y; asm("ex2.approx.f32 %0, %1;" : "=f"(y) : "f"(x)); return y;
}
__device__ __forceinline__ void split_pack(float x, float y, uint32_t& hp, uint32_t& lp) {
    __nv_bfloat162 hv, lv;
    hv.x = __float2bfloat16(x);
    hv.y = __float2bfloat16(y);
    lv.x = __float2bfloat16(x - __bfloat162float(hv.x));
    lv.y = __float2bfloat16(y - __bfloat162float(hv.y));
    hp = *(uint32_t*)&hv;
    lp = *(uint32_t*)&lv;
}
#define CP_ASYNC16(dst, src) \
    asm volatile("cp.async.cg.shared.global [%0], [%1], 16;" :: "r"(dst), "l"(src))
#define CP_COMMIT() asm volatile("cp.async.commit_group;" ::: "memory")
#define CP_WAIT(n)  asm volatile("cp.async.wait_group %0;" :: "n"(n) : "memory")

// ---------------------------------------------------------------------------
// Mask canonicalizer + per-64-key-tile bitmasks
// ---------------------------------------------------------------------------
__global__ void mask_convert_kernel(const void* __restrict__ raw, int n) {
    __shared__ int mode;
    if (threadIdx.x == 0) {
        unsigned w0 = ((const unsigned*)raw)[0];
        if (w0 == 1u || w0 == 0u)    mode = 0;  // int32
        else if (w0 == 0x3F800000u)  mode = 1;  // float32
        else if (w0 == 0x01010101u)  mode = 2;  // uint8
        else if (w0 == 0x3F803F80u)  mode = 3;  // bf16 pair
        else                          mode = 2;
    }
    __syncthreads();
    int m = mode;
    for (int i = threadIdx.x; i < n; i += blockDim.x) {
        int v;
        if (m == 0)      v = (((const int*)raw)[i] != 0);
        else if (m == 1) v = (((const float*)raw)[i] != 0.0f);
        else if (m == 2) v = (((const unsigned char*)raw)[i] != 0);
        else { unsigned short h = ((const unsigned short*)raw)[i]; v = ((h & 0x7FFF) != 0); }
        g_mask[i] = v;
    }
    __syncthreads();
    for (int t = threadIdx.x; t < BATCH * 32; t += blockDim.x) {
        int b = t >> 5, kt = t & 31;
        unsigned long long mb = 0ull;
        for (int j = 0; j < 64; j++)
            mb |= ((unsigned long long)(g_mask[b * SEQ + kt * 64 + j] & 1)) << j;
        g_mbits[t] = mb;
    }
}

// ---------------------------------------------------------------------------
// bf16 split kernels (hidden input + weights)
// ---------------------------------------------------------------------------
__global__ void splitA_kernel(const float* __restrict__ A,
                              __nv_bfloat16* __restrict__ Ah,
                              __nv_bfloat16* __restrict__ Al, int n4) {
    int stride = gridDim.x * blockDim.x;
    for (int i = blockIdx.x * blockDim.x + threadIdx.x; i < n4; i += stride) {
        float4 v = ((const float4*)A)[i];
        uint32_t h0, l0, h1, l1;
        split_pack(v.x, v.y, h0, l0);
        split_pack(v.z, v.w, h1, l1);
        ((uint32_t*)Ah)[i * 2]     = h0;
        ((uint32_t*)Ah)[i * 2 + 1] = h1;
        ((uint32_t*)Al)[i * 2]     = l0;
        ((uint32_t*)Al)[i * 2 + 1] = l1;
    }
}

// B [K,N] fp32 -> B^T [N,K] bf16 hi/lo
__global__ void splitBT_kernel(const float* __restrict__ B,
                               __nv_bfloat16* __restrict__ BTh,
                               __nv_bfloat16* __restrict__ BTl, int K, int N) {
    __shared__ float tile[32][33];
    int k0 = blockIdx.y * 32, n0 = blockIdx.x * 32;
    int tx = threadIdx.x & 31, ty = threadIdx.x >> 5;
    for (int r = ty; r < 32; r += 8)
        tile[r][tx] = B[(size_t)(k0 + r) * N + n0 + tx];
    __syncthreads();
    for (int r = ty; r < 32; r += 8) {
        float v = tile[tx][r];
        __nv_bfloat16 h = __float2bfloat16(v);
        __nv_bfloat16 l = __float2bfloat16(v - __bfloat162float(h));
        size_t o = (size_t)(n0 + r) * K + k0 + tx;
        BTh[o] = h;
        BTl[o] = l;
    }
}

// ---------------------------------------------------------------------------
// mma.sync bf16x3 GEMM (R5 champion config). 8 warps 32x64, 2-stage, occ 2.
// MODE 0: bf16 hi/lo output + Q-scale on cols < HID. MODE 1: fp32 + bias.
// ---------------------------------------------------------------------------
#define KC        32
#define TROW      80
#define TILE_B    (128 * TROW)
#define STAGE_B   (4 * TILE_B)          // 40960: Ah | Al | Bh | Bl
#define TC_SMEM   (2 * STAGE_B)         // 81920 -> 2 CTAs/SM

template <int MODE>
__global__ __launch_bounds__(256, 2)
void mma_gemm_kernel(const __nv_bfloat16* __restrict__ Ah, const __nv_bfloat16* __restrict__ Al,
                     const __nv_bfloat16* __restrict__ BTh, const __nv_bfloat16* __restrict__ BTl,
                     const float* __restrict__ bias, float* __restrict__ C,
                     __nv_bfloat16* __restrict__ Ch, __nv_bfloat16* __restrict__ Cl,
                     int M, int N, int K) {
    extern __shared__ char smem[];
    const uint32_t sb = smem_u32(smem);
    const int tid   = threadIdx.x;
    const int lane  = tid & 31;
    const int wid   = tid >> 5;
    const int warpM = wid & 3;
    const int warpN = wid >> 2;
    const int m0 = blockIdx.y * 128;
    const int n0 = blockIdx.x * 128;
    const int nch = K / KC;

    auto load_stage = [&](int kc0, int s) {
        const uint32_t stg = sb + s * STAGE_B;
#pragma unroll
        for (int t = 0; t < 8; t++) {
            const int tile = t >> 1;
            const int rem  = tid + (t & 1) * 256;
            const int row  = rem >> 2;
            const int q    = rem & 3;
            const __nv_bfloat16* src;
            if (tile == 0)      src = Ah  + (size_t)(m0 + row) * K + kc0 + q * 8;
            else if (tile == 1) src = Al  + (size_t)(m0 + row) * K + kc0 + q * 8;
            else if (tile == 2) src = BTh + (size_t)(n0 + row) * K + kc0 + q * 8;
            else                src = BTl + (size_t)(n0 + row) * K + kc0 + q * 8;
            CP_ASYNC16(stg + tile * TILE_B + row * TROW + q * 16, src);
        }
        CP_COMMIT();
    };

    float c[2][8][4];
#pragma unroll
    for (int i = 0; i < 2; i++)
#pragma unroll
        for (int j = 0; j < 8; j++)
#pragma unroll
            for (int r = 0; r < 4; r++) c[i][j][r] = 0.0f;

    const int arow = warpM * 32 + (lane & 15);
    const int acol = (lane >> 4) * 8;
    const int brow = warpN * 64 + (lane & 7) + ((lane >> 4) << 3);
    const int bck  = ((lane >> 3) & 1) * 8;

    load_stage(0, 0);
    load_stage(KC, 1);

    for (int ch = 0; ch < nch; ch++) {
        CP_WAIT(1);
        __syncthreads();

        const uint32_t stg = sb + (ch & 1) * STAGE_B;
        const uint32_t ahb = stg;
        const uint32_t alb = stg + TILE_B;
        const uint32_t bhb = stg + 2 * TILE_B;
        const uint32_t blb = stg + 3 * TILE_B;

#pragma unroll
        for (int k16 = 0; k16 < 2; k16++) {
            uint32_t fah[2][4], fal[2][4];
#pragma unroll
            for (int mt = 0; mt < 2; mt++) {
                uint32_t off = (uint32_t)(arow + mt * 16) * TROW + (k16 * 16 + acol) * 2;
                ldsm_x4(fah[mt][0], fah[mt][1], fah[mt][2], fah[mt][3], ahb + off);
                ldsm_x4(fal[mt][0], fal[mt][1], fal[mt][2], fal[mt][3], alb + off);
            }
#pragma unroll
            for (int np = 0; np < 4; np++) {
                uint32_t bh[4], bl[4];
                uint32_t off = (uint32_t)(brow + np * 16) * TROW + (k16 * 16 + bck) * 2;
                ldsm_x4(bh[0], bh[1], bh[2], bh[3], bhb + off);
                ldsm_x4(bl[0], bl[1], bl[2], bl[3], blb + off);
#pragma unroll
                for (int mt = 0; mt < 2; mt++)
#pragma unroll
                    for (int half = 0; half < 2; half++) {
                        float* acc = c[mt][np * 2 + half];
                        mma_bf16(acc, fah[mt], bh[half * 2], bh[half * 2 + 1]);
                        mma_bf16(acc, fah[mt], bl[half * 2], bl[half * 2 + 1]);
                        mma_bf16(acc, fal[mt], bh[half * 2], bh[half * 2 + 1]);
                    }
            }
        }
        __syncthreads();
        if (ch + 2 < nch) load_stage((ch + 2) * KC, ch & 1);
        else CP_COMMIT();   // placeholder group: keeps CP_WAIT(1) accounting exact
    }

    const int g   = lane >> 2;
    const int tig = lane & 3;
#pragma unroll
    for (int mt = 0; mt < 2; mt++) {
        const int row = m0 + warpM * 32 + mt * 16 + g;
#pragma unroll
        for (int nt = 0; nt < 8; nt++) {
            const int col = n0 + warpN * 64 + nt * 8 + tig * 2;
            if (MODE == 1) {
                float2 v0 = make_float2(c[mt][nt][0] + bias[col], c[mt][nt][1] + bias[col + 1]);
                float2 v1 = make_float2(c[mt][nt][2] + bias[col], c[mt][nt][3] + bias[col + 1]);
                *(float2*)(C + (size_t)row * N + col)       = v0;
                *(float2*)(C + (size_t)(row + 8) * N + col) = v1;
            } else {
                const float sc = (col < HID) ? QSF : 1.0f;
                uint32_t hp, lp;
                split_pack(c[mt][nt][0] * sc, c[mt][nt][1] * sc, hp, lp);
                *(uint32_t*)(Ch + (size_t)row * N + col) = hp;
                *(uint32_t*)(Cl + (size_t)row * N + col) = lp;
                split_pack(c[mt][nt][2] * sc, c[mt][nt][3] * sc, hp, lp);
                *(uint32_t*)(Ch + (size_t)(row + 8) * N + col) = hp;
                *(uint32_t*)(Cl + (size_t)(row + 8) * N + col) = lp;
            }
        }
    }
}

// ---------------------------------------------------------------------------
// mma.sync flash attention (bf16x3 both products). R5 core + Q staged in smem
// (regs ~105) so 2 CTAs/SM co-schedule: softmax bubbles of one CTA overlap
// the other CTA's HMMA work.
// ---------------------------------------------------------------------------
#define ATROW 144
#define ATILE (64 * ATROW)                 // 9216
#define ASTAGE (4 * ATILE)                 // 36864: Kh | Kl | Vh | Vl
#define QTILE (128 * ATROW)                // 18432
#define ATT_SMEM (2 * ASTAGE + 2 * QTILE + 160)   // 110752 -> 2 CTAs/SM

__global__ __launch_bounds__(256, 2)
void mma_attn_kernel(const __nv_bfloat16* __restrict__ Qh, const __nv_bfloat16* __restrict__ Ql,
                     __nv_bfloat16* __restrict__ Oh, __nv_bfloat16* __restrict__ Ol) {
    extern __shared__ char sm[];
    const uint32_t sb  = smem_u32(sm);
    const uint32_t qsm = sb + 2 * ASTAGE;          // Qh tile | Ql tile
    int* list = (int*)(sm + 2 * ASTAGE + 2 * QTILE);

    const int tid  = threadIdx.x;
    const int lane = tid & 31;
    const int w    = tid >> 5;
    const int b    = blockIdx.z;
    const int h    = blockIdx.y;
    const int q0   = blockIdx.x * 128;
    const int g    = lane >> 2;
    const int tq   = lane & 3;

    if (w == 0) {
        unsigned long long mb = g_mbits[b * 32 + lane];
        unsigned act = __ballot_sync(0xffffffffu, mb != 0ull);
        int pos = __popc(act & ((1u << lane) - 1));
        if (mb != 0ull) list[pos] = lane;
        if (lane == 0) list[32] = __popc(act);
    }
    __syncthreads();
    const int ncnt = list[32];

    // stage Q tile (128 rows x 64 bf16, hi+lo) into smem via cp.async
    {
        const int tok0 = b * SEQ + q0;
#pragma unroll
        for (int t = 0; t < 8; t++) {
            const int id  = tid + t * 256;
            const int arr = id >> 10;             // 0:Qh 1:Ql
            const int rem = id & 1023;
            const int r   = rem >> 3;
            const int seg = rem & 7;
            const size_t go = (size_t)(tok0 + r) * QKV3 + h * HD + seg * 8;
            const __nv_bfloat16* src = arr ? (Ql + go) : (Qh + go);
            CP_ASYNC16(qsm + arr * QTILE + r * ATROW + seg * 16, src);
        }
        CP_COMMIT();
    }

    auto load_tile = [&](int kt, int stg) {
        const int tok0 = b * SEQ + kt * 64;
        const uint32_t base = sb + stg * ASTAGE;
#pragma unroll
        for (int t = 0; t < 8; t++) {
            const int id  = tid + t * 256;
            const int arr = id >> 9;
            const int rem = id & 511;
            const int r   = rem >> 3;
            const int q   = rem & 7;
            const size_t go = (size_t)(tok0 + r) * QKV3 + h * HD + q * 8;
            const __nv_bfloat16* src;
            if (arr == 0)      src = Qh + go + HID;       // Kh
            else if (arr == 1) src = Ql + go + HID;       // Kl
            else if (arr == 2) src = Qh + go + 2 * HID;   // Vh
            else               src = Ql + go + 2 * HID;   // Vl
            CP_ASYNC16(base + arr * ATILE + r * ATROW + q * 16, src);
        }
        CP_COMMIT();
    };

    float o[8][4];
#pragma unroll
    for (int j = 0; j < 8; j++)
#pragma unroll
        for (int r = 0; r < 4; r++) o[j][r] = 0.0f;
    float mi[2] = {-1e30f, -1e30f}, li[2] = {0.0f, 0.0f};

    if (ncnt > 0) load_tile(list[0], 0);

    // per-warp Q fragment smem address (A-operand layout)
    const uint32_t qrowoff = qsm + (uint32_t)(w * 16 + (lane & 15)) * ATROW
                           + ((lane >> 4) << 3) * 2;

    for (int it = 0; it < ncnt; it++) {
        if (it + 1 < ncnt) { load_tile(list[it + 1], (it + 1) & 1); CP_WAIT(1); }
        else CP_WAIT(0);
        __syncthreads();
        const uint32_t st = sb + (it & 1) * ASTAGE;
        const int kt = list[it];

        // ---- S = Q @ K^T (3-term; Q frags reloaded from smem per kd) ----
        float s[8][4];
#pragma unroll
        for (int j = 0; j < 8; j++)
#pragma unroll
            for (int r = 0; r < 4; r++) s[j][r] = 0.0f;

#pragma unroll
        for (int kd = 0; kd < 4; kd++) {
            uint32_t qh4[4], ql4[4];
            const uint32_t qoff = qrowoff + kd * 32;   // kd*16 cols * 2B
            ldsm_x4(qh4[0], qh4[1], qh4[2], qh4[3], qoff);
            ldsm_x4(ql4[0], ql4[1], ql4[2], ql4[3], qoff + QTILE);
#pragma unroll
            for (int kg = 0; kg < 4; kg++) {
                uint32_t kh[4], kl[4];
                const uint32_t off = st + (uint32_t)(kg * 16 + (lane & 7) + ((lane >> 4) << 3)) * ATROW
                                        + (kd * 16 + ((lane >> 3) & 1) * 8) * 2;
                ldsm_x4(kh[0], kh[1], kh[2], kh[3], off);
                ldsm_x4(kl[0], kl[1], kl[2], kl[3], off + ATILE);
                mma_bf16(s[kg * 2],     qh4, kh[0], kh[1]);
                mma_bf16(s[kg * 2],     qh4, kl[0], kl[1]);
                mma_bf16(s[kg * 2],     ql4, kh[0], kh[1]);
                mma_bf16(s[kg * 2 + 1], qh4, kh[2], kh[3]);
                mma_bf16(s[kg * 2 + 1], qh4, kl[2], kl[3]);
                mma_bf16(s[kg * 2 + 1], ql4, kh[2], kh[3]);
            }
        }

        // ---- key-padding mask ----
        const unsigned long long mb = g_mbits[b * 32 + kt];
        if (mb != ~0ull) {
#pragma unroll
            for (int nf = 0; nf < 8; nf++) {
                const int c0 = nf * 8 + tq * 2;
                if (!((mb >> c0) & 1))       { s[nf][0] = -1e30f; s[nf][2] = -1e30f; }
                if (!((mb >> (c0 + 1)) & 1)) { s[nf][1] = -1e30f; s[nf][3] = -1e30f; }
            }
        }

        // ---- online softmax (base-2; Q pre-scaled) ----
#pragma unroll
        for (int r = 0; r < 2; r++) {
            float mx = -1e30f;
#pragma unroll
            for (int nf = 0; nf < 8; nf++)
                mx = fmaxf(mx, fmaxf(s[nf][2 * r], s[nf][2 * r + 1]));
            mx = fmaxf(mx, __shfl_xor_sync(0xffffffffu, mx, 1));
            mx = fmaxf(mx, __shfl_xor_sync(0xffffffffu, mx, 2));
            const float mnew = fmaxf(mi[r], mx);
            const float al = fexp2(mi[r] - mnew);
            mi[r] = mnew;
            li[r] *= al;
#pragma unroll
            for (int nf = 0; nf < 8; nf++) { o[nf][2 * r] *= al; o[nf][2 * r + 1] *= al; }
            float ls = 0.0f;
#pragma unroll
            for (int nf = 0; nf < 8; nf++) {
                const float p0 = fexp2(s[nf][2 * r] - mnew);
                const float p1 = fexp2(s[nf][2 * r + 1] - mnew);
                ls += p0 + p1;
                s[nf][2 * r] = p0;
                s[nf][2 * r + 1] = p1;
            }
            ls += __shfl_xor_sync(0xffffffffu, ls, 1);
            ls += __shfl_xor_sync(0xffffffffu, ls, 2);
            li[r] += ls;
        }

        // ---- pack P into A-fragments (hi/lo) ----
        uint32_t pah[4][4], pal[4][4];
#pragma unroll
        for (int ks = 0; ks < 4; ks++) {
            split_pack(s[2 * ks][0],     s[2 * ks][1],     pah[ks][0], pal[ks][0]);
            split_pack(s[2 * ks][2],     s[2 * ks][3],     pah[ks][1], pal[ks][1]);
            split_pack(s[2 * ks + 1][0], s[2 * ks + 1][1], pah[ks][2], pal[ks][2]);
            split_pack(s[2 * ks + 1][2], s[2 * ks + 1][3], pah[ks][3], pal[ks][3]);
        }

        // ---- O += P @ V (3-term) ----
#pragma unroll
        for (int ks = 0; ks < 4; ks++) {
#pragma unroll
            for (int dg = 0; dg < 4; dg++) {
                uint32_t vh[4], vl[4];
                const uint32_t off = st + 2 * ATILE
                                   + (uint32_t)(ks * 16 + (lane & 15)) * ATROW
                                   + (dg * 16 + ((lane >> 4) << 3)) * 2;
                ldsm_x4t(vh[0], vh[1], vh[2], vh[3], off);
                ldsm_x4t(vl[0], vl[1], vl[2], vl[3], off + ATILE);
                mma_bf16(o[dg * 2],     pah[ks], vh[0], vh[1]);
                mma_bf16(o[dg * 2],     pah[ks], vl[0], vl[1]);
                mma_bf16(o[dg * 2],     pal[ks], vh[0], vh[1]);
                mma_bf16(o[dg * 2 + 1], pah[ks], vh[2], vh[3]);
                mma_bf16(o[dg * 2 + 1], pah[ks], vl[2], vl[3]);
                mma_bf16(o[dg * 2 + 1], pal[ks], vh[2], vh[3]);
            }
        }
        __syncthreads();
    }

    // ---- epilogue: normalize, split to bf16 hi/lo ----
#pragma unroll
    for (int r = 0; r < 2; r++) {
        const float inv = 1.0f / li[r];
        const size_t ob = (size_t)(b * SEQ + q0 + w * 16 + g + r * 8) * HID + h * HD;
#pragma unroll
        for (int nf = 0; nf < 8; nf++) {
            uint32_t hp, lp;
            split_pack(o[nf][2 * r] * inv, o[nf][2 * r + 1] * inv, hp, lp);
            *(uint32_t*)(Oh + ob + nf * 8 + tq * 2) = hp;
            *(uint32_t*)(Ol + ob + nf * 8 + tq * 2) = lp;
        }
    }
}

// ---------------------------------------------------------------------------
// Launch
// ---------------------------------------------------------------------------
extern "C" void kernel_launch(void* const* d_in, const int* in_sizes, int n_in,
                              void* d_out, int out_size) {
    const float* hidden = (const float*)d_in[0];
    const void*  maskp  = d_in[1];
    const float* Wqkv   = (const float*)d_in[2];
    const float* Wout   = (const float*)d_in[3];
    const float* bout   = (const float*)d_in[4];
    float*       out    = (float*)d_out;

    void *p_qh, *p_ql, *p_sh, *p_sl, *p_wh, *p_wl;
    cudaGetSymbolAddress(&p_qh, g_qh);
    cudaGetSymbolAddress(&p_ql, g_ql);
    cudaGetSymbolAddress(&p_sh, g_sh);
    cudaGetSymbolAddress(&p_sl, g_sl);
    cudaGetSymbolAddress(&p_wh, g_wh);
    cudaGetSymbolAddress(&p_wl, g_wl);

    cudaFuncSetAttribute(mma_gemm_kernel<0>,
                         cudaFuncAttributeMaxDynamicSharedMemorySize, TC_SMEM);
    cudaFuncSetAttribute(mma_gemm_kernel<1>,
                         cudaFuncAttributeMaxDynamicSharedMemorySize, TC_SMEM);
    cudaFuncSetAttribute(mma_attn_kernel,
                         cudaFuncAttributeMaxDynamicSharedMemorySize, ATT_SMEM);

    // 1. mask canonicalize + tile bitmasks
    mask_convert_kernel<<<1, 256>>>(maskp, BATCH * SEQ);

    // 2. split inputs to bf16 hi/lo
    splitA_kernel<<<592, 256>>>(hidden, (__nv_bfloat16*)p_sh, (__nv_bfloat16*)p_sl,
                                MROWS * HID / 4);
    splitBT_kernel<<<dim3(QKV3 / 32, HID / 32), 256>>>(
        Wqkv, (__nv_bfloat16*)p_wh, (__nv_bfloat16*)p_wl, HID, QKV3);
    splitBT_kernel<<<dim3(HID / 32, HID / 32), 256>>>(
        Wout, (__nv_bfloat16*)p_wh + (size_t)QKV3 * HID,
        (__nv_bfloat16*)p_wl + (size_t)QKV3 * HID, HID, HID);

    // 3. QKV projection -> bf16 hi/lo splits (Q pre-scaled by 0.125*log2e)
    mma_gemm_kernel<0><<<dim3(QKV3 / 128, MROWS / 128), 256, TC_SMEM>>>(
        (const __nv_bfloat16*)p_sh, (const __nv_bfloat16*)p_sl,
        (const __nv_bfloat16*)p_wh, (const __nv_bfloat16*)p_wl,
        nullptr, nullptr, (__nv_bfloat16*)p_qh, (__nv_bfloat16*)p_ql,
        MROWS, QKV3, HID);

    // 4. tensor-core flash attention -> bf16 hi/lo attention output
    mma_attn_kernel<<<dim3(SEQ / 128, NH, BATCH), 256, ATT_SMEM>>>(
        (const __nv_bfloat16*)p_qh, (const __nv_bfloat16*)p_ql,
        (__nv_bfloat16*)p_sh, (__nv_bfloat16*)p_sl);

    // 5. output projection (+bias)
    mma_gemm_kernel<1><<<dim3(HID / 128, MROWS / 128), 256, TC_SMEM>>>(
        (const __nv_bfloat16*)p_sh, (const __nv_bfloat16*)p_sl,
        (const __nv_bfloat16*)p_wh + (size_t)QKV3 * HID,
        (const __nv_bfloat16*)p_wl + (size_t)QKV3 * HID,
        bout, out, nullptr, nullptr, MROWS, HID, HID);
}

// round 10
// speedup vs baseline: 2.0112x; 1.1581x over previous
#include <cuda_runtime.h>
#include <cuda_bf16.h>
#include <cuda_fp16.h>
#include <cstdint>

#define BATCH 4
#define SEQ   2048
#define NH    16
#define HD    64
#define HID   1024
#define QKV3  3072
#define MROWS (BATCH * SEQ)        // 8192

// 0.125 * log2(e): folded into Q at the QKV epilogue (softmax in base-2 domain)
#define QSF 0.18033688011112042f

// ---------------------------------------------------------------------------
// Scratch (static device globals — allocation-free per harness rules)
// ---------------------------------------------------------------------------
__device__ __nv_bfloat16 g_qh[MROWS * QKV3];           // qkv hi split, bf16 (attention input)
__device__ __nv_bfloat16 g_ql[MROWS * QKV3];           // qkv lo split, bf16
__device__ int           g_mask[BATCH * SEQ];
__device__ unsigned long long g_mbits[BATCH * 32];     // 64-key tile bitmasks
__device__ __half        g_ah[MROWS * HID];            // activation hi fp16 (hidden, then attn out)
__device__ __half        g_al[MROWS * HID];            // activation lo fp16
__device__ __half        g_wq[QKV3 * HID];             // Wqkv^T single fp16 [N,K]
__device__ __half        g_wo[HID * HID];              // Wout^T single fp16 [N,K]

// ---------------------------------------------------------------------------
// PTX helpers (arch-portable sm_80+; tcgen05 unavailable via compute_103;
// s8 mma.sync measured ~4-5x worse rt than HMMA on sm_103 — do not use)
// ---------------------------------------------------------------------------
__device__ __forceinline__ uint32_t smem_u32(const void* p) {
    uint32_t a;
    asm("{ .reg .u64 t; cvta.to.shared.u64 t, %1; cvt.u32.u64 %0, t; }" : "=r"(a) : "l"(p));
    return a;
}
__device__ __forceinline__ void ldsm_x4(uint32_t& r0, uint32_t& r1, uint32_t& r2, uint32_t& r3,
                                        uint32_t addr) {
    asm volatile("ldmatrix.sync.aligned.m8n8.x4.shared.b16 {%0,%1,%2,%3}, [%4];"
                 : "=r"(r0), "=r"(r1), "=r"(r2), "=r"(r3) : "r"(addr));
}
__device__ __forceinline__ void ldsm_x4t(uint32_t& r0, uint32_t& r1, uint32_t& r2, uint32_t& r3,
                                         uint32_t addr) {
    asm volatile("ldmatrix.sync.aligned.m8n8.x4.trans.shared.b16 {%0,%1,%2,%3}, [%4];"
                 : "=r"(r0), "=r"(r1), "=r"(r2), "=r"(r3) : "r"(addr));
}
__device__ __forceinline__ void mma_bf16(float* c, const uint32_t* a, uint32_t b0, uint32_t b1) {
    asm volatile(
        "mma.sync.aligned.m16n8k16.row.col.f32.bf16.bf16.f32 "
        "{%0,%1,%2,%3}, {%4,%5,%6,%7}, {%8,%9}, {%0,%1,%2,%3};"
        : "+f"(c[0]), "+f"(c[1]), "+f"(c[2]), "+f"(c[3])
        : "r"(a[0]), "r"(a[1]), "r"(a[2]), "r"(a[3]), "r"(b0), "r"(b1));
}
__device__ __forceinline__ void mma_f16(float* c, const uint32_t* a, uint32_t b0, uint32_t b1) {
    asm volatile(
        "mma.sync.aligned.m16n8k16.row.col.f32.f16.f16.f32 "
        "{%0,%1,%2,%3}, {%4,%5,%6,%7}, {%8,%9}, {%0,%1,%2,%3};"
        : "+f"(c[0]), "+f"(c[1]), "+f"(c[2]), "+f"(c[3])
        : "r"(a[0]), "r"(a[1]), "r"(a[2]), "r"(a[3]), "r"(b0), "r"(b1));
}
__device__ __forceinline__ float fexp2(float x) {
    float y; asm("ex2.approx.f32 %0, %1;" : "=f"(y) : "f"(x)); return y;
}
// bf16 hi/lo split-pack (attention internals + QKV epilogue)
__device__ __forceinline__ void split_pack(float x, float y, uint32_t& hp, uint32_t& lp) {
    __nv_bfloat162 hv, lv;
    hv.x = __float2bfloat16(x);
    hv.y = __float2bfloat16(y);
    lv.x = __float2bfloat16(x - __bfloat162float(hv.x));
    lv.y = __float2bfloat16(y - __bfloat162float(hv.y));
    hp = *(uint32_t*)&hv;
    lp = *(uint32_t*)&lv;
}
// fp16 hi/lo split-pack (projection activations)
__device__ __forceinline__ void split_pack_h(float x, float y, uint32_t& hp, uint32_t& lp) {
    __half2 hv, lv;
    hv.x = __float2half(x);
    hv.y = __float2half(y);
    lv.x = __float2half(x - __half2float(hv.x));
    lv.y = __float2half(y - __half2float(hv.y));
    hp = *(uint32_t*)&hv;
    lp = *(uint32_t*)&lv;
}
#define CP_ASYNC16(dst, src) \
    asm volatile("cp.async.cg.shared.global [%0], [%1], 16;" :: "r"(dst), "l"(src))
#define CP_COMMIT() asm volatile("cp.async.commit_group;" ::: "memory")
#define CP_WAIT(n)  asm volatile("cp.async.wait_group %0;" :: "n"(n) : "memory")

// ---------------------------------------------------------------------------
// Mask canonicalizer + per-64-key-tile bitmasks
// ---------------------------------------------------------------------------
__global__ void mask_convert_kernel(const void* __restrict__ raw, int n) {
    __shared__ int mode;
    if (threadIdx.x == 0) {
        unsigned w0 = ((const unsigned*)raw)[0];
        if (w0 == 1u || w0 == 0u)    mode = 0;  // int32
        else if (w0 == 0x3F800000u)  mode = 1;  // float32
        else if (w0 == 0x01010101u)  mode = 2;  // uint8
        else if (w0 == 0x3F803F80u)  mode = 3;  // bf16 pair
        else                          mode = 2;
    }
    __syncthreads();
    int m = mode;
    for (int i = threadIdx.x; i < n; i += blockDim.x) {
        int v;
        if (m == 0)      v = (((const int*)raw)[i] != 0);
        else if (m == 1) v = (((const float*)raw)[i] != 0.0f);
        else if (m == 2) v = (((const unsigned char*)raw)[i] != 0);
        else { unsigned short h = ((const unsigned short*)raw)[i]; v = ((h & 0x7FFF) != 0); }
        g_mask[i] = v;
    }
    __syncthreads();
    for (int t = threadIdx.x; t < BATCH * 32; t += blockDim.x) {
        int b = t >> 5, kt = t & 31;
        unsigned long long mb = 0ull;
        for (int j = 0; j < 64; j++)
            mb |= ((unsigned long long)(g_mask[b * SEQ + kt * 64 + j] & 1)) << j;
        g_mbits[t] = mb;
    }
}

// ---------------------------------------------------------------------------
// fp16 prep kernels
// ---------------------------------------------------------------------------
// fp32 -> fp16 hi/lo pairs (hidden activations)
__global__ void splitA_f16_kernel(const float* __restrict__ A,
                                  __half* __restrict__ Ah,
                                  __half* __restrict__ Al, int n4) {
    int stride = gridDim.x * blockDim.x;
    for (int i = blockIdx.x * blockDim.x + threadIdx.x; i < n4; i += stride) {
        float4 v = ((const float4*)A)[i];
        uint32_t h0, l0, h1, l1;
        split_pack_h(v.x, v.y, h0, l0);
        split_pack_h(v.z, v.w, h1, l1);
        ((uint32_t*)Ah)[i * 2]     = h0;
        ((uint32_t*)Ah)[i * 2 + 1] = h1;
        ((uint32_t*)Al)[i * 2]     = l0;
        ((uint32_t*)Al)[i * 2 + 1] = l1;
    }
}

// W [K,N] fp32 -> W^T [N,K] single fp16
__global__ void quantWT_f16_kernel(const float* __restrict__ W,
                                   __half* __restrict__ WT, int K, int N) {
    __shared__ float tile[32][33];
    int k0 = blockIdx.y * 32, n0 = blockIdx.x * 32;
    int tx = threadIdx.x & 31, ty = threadIdx.x >> 5;
    for (int r = ty; r < 32; r += 8)
        tile[r][tx] = W[(size_t)(k0 + r) * N + n0 + tx];
    __syncthreads();
    for (int r = ty; r < 32; r += 8)
        WT[(size_t)(n0 + r) * K + k0 + tx] = __float2half(tile[tx][r]);
}

// ---------------------------------------------------------------------------
// fp16 2-term GEMM: C = A @ WT^T. A split fp16 pair (exact), W single fp16.
// 2 MMAs per k16 (-33% vs bf16x3). CTA 128x128, 8 warps 32x64, 2-stage.
// MODE 0: bf16 hi/lo output + Q-scale on cols < HID. MODE 1: fp32 + bias.
// ---------------------------------------------------------------------------
#define KC        32
#define TROW      80
#define TILE_B    (128 * TROW)          // 10240
#define STAGE_B   (3 * TILE_B)          // 30720: Ah | Al | B
#define TC_SMEM   (2 * STAGE_B)         // 61440 -> 2+ CTAs/SM

template <int MODE>
__global__ __launch_bounds__(256, 2)
void f16_gemm_kernel(const __half* __restrict__ Ah, const __half* __restrict__ Al,
                     const __half* __restrict__ WT,
                     const float* __restrict__ bias, float* __restrict__ C,
                     __nv_bfloat16* __restrict__ Ch, __nv_bfloat16* __restrict__ Cl,
                     int M, int N, int K) {
    extern __shared__ char smem[];
    const uint32_t sb = smem_u32(smem);
    const int tid   = threadIdx.x;
    const int lane  = tid & 31;
    const int wid   = tid >> 5;
    const int warpM = wid & 3;
    const int warpN = wid >> 2;
    const int m0 = blockIdx.y * 128;
    const int n0 = blockIdx.x * 128;
    const int nch = K / KC;

    // 1536 x 16B per stage, 256 threads -> 6 ops each
    auto load_stage = [&](int kc0, int s) {
        const uint32_t stg = sb + s * STAGE_B;
#pragma unroll
        for (int t = 0; t < 6; t++) {
            const int id   = tid + t * 256;
            const int tile = id >> 9;             // 0:Ah 1:Al 2:B
            const int rem  = id & 511;
            const int row  = rem >> 2;
            const int q    = rem & 3;
            const __half* src;
            if (tile == 0)      src = Ah + (size_t)(m0 + row) * K + kc0 + q * 8;
            else if (tile == 1) src = Al + (size_t)(m0 + row) * K + kc0 + q * 8;
            else                src = WT + (size_t)(n0 + row) * K + kc0 + q * 8;
            CP_ASYNC16(stg + tile * TILE_B + row * TROW + q * 16, src);
        }
        CP_COMMIT();
    };

    float c[2][8][4];
#pragma unroll
    for (int i = 0; i < 2; i++)
#pragma unroll
        for (int j = 0; j < 8; j++)
#pragma unroll
            for (int r = 0; r < 4; r++) c[i][j][r] = 0.0f;

    const int arow = warpM * 32 + (lane & 15);
    const int acol = (lane >> 4) * 8;
    const int brow = warpN * 64 + (lane & 7) + ((lane >> 4) << 3);
    const int bck  = ((lane >> 3) & 1) * 8;

    load_stage(0, 0);
    load_stage(KC, 1);

    for (int ch = 0; ch < nch; ch++) {
        CP_WAIT(1);
        __syncthreads();

        const uint32_t stg = sb + (ch & 1) * STAGE_B;
        const uint32_t ahb = stg;
        const uint32_t alb = stg + TILE_B;
        const uint32_t bbb = stg + 2 * TILE_B;

#pragma unroll
        for (int k16 = 0; k16 < 2; k16++) {
            uint32_t fah[2][4], fal[2][4];
#pragma unroll
            for (int mt = 0; mt < 2; mt++) {
                uint32_t off = (uint32_t)(arow + mt * 16) * TROW + (k16 * 16 + acol) * 2;
                ldsm_x4(fah[mt][0], fah[mt][1], fah[mt][2], fah[mt][3], ahb + off);
                ldsm_x4(fal[mt][0], fal[mt][1], fal[mt][2], fal[mt][3], alb + off);
            }
#pragma unroll
            for (int np = 0; np < 4; np++) {
                uint32_t bf[4];
                uint32_t off = (uint32_t)(brow + np * 16) * TROW + (k16 * 16 + bck) * 2;
                ldsm_x4(bf[0], bf[1], bf[2], bf[3], bbb + off);
#pragma unroll
                for (int mt = 0; mt < 2; mt++)
#pragma unroll
                    for (int half = 0; half < 2; half++) {
                        float* acc = c[mt][np * 2 + half];
                        mma_f16(acc, fah[mt], bf[half * 2], bf[half * 2 + 1]);
                        mma_f16(acc, fal[mt], bf[half * 2], bf[half * 2 + 1]);
                    }
            }
        }
        __syncthreads();
        if (ch + 2 < nch) load_stage((ch + 2) * KC, ch & 1);
        else CP_COMMIT();   // placeholder group: keeps CP_WAIT(1) accounting exact
    }

    const int g   = lane >> 2;
    const int tig = lane & 3;
#pragma unroll
    for (int mt = 0; mt < 2; mt++) {
        const int row = m0 + warpM * 32 + mt * 16 + g;
#pragma unroll
        for (int nt = 0; nt < 8; nt++) {
            const int col = n0 + warpN * 64 + nt * 8 + tig * 2;
            if (MODE == 1) {
                float2 v0 = make_float2(c[mt][nt][0] + bias[col], c[mt][nt][1] + bias[col + 1]);
                float2 v1 = make_float2(c[mt][nt][2] + bias[col], c[mt][nt][3] + bias[col + 1]);
                *(float2*)(C + (size_t)row * N + col)       = v0;
                *(float2*)(C + (size_t)(row + 8) * N + col) = v1;
            } else {
                const float sc = (col < HID) ? QSF : 1.0f;
                uint32_t hp, lp;
                split_pack(c[mt][nt][0] * sc, c[mt][nt][1] * sc, hp, lp);
                *(uint32_t*)(Ch + (size_t)row * N + col) = hp;
                *(uint32_t*)(Cl + (size_t)row * N + col) = lp;
                split_pack(c[mt][nt][2] * sc, c[mt][nt][3] * sc, hp, lp);
                *(uint32_t*)(Ch + (size_t)(row + 8) * N + col) = hp;
                *(uint32_t*)(Cl + (size_t)(row + 8) * N + col) = lp;
            }
        }
    }
}

// ---------------------------------------------------------------------------
// mma.sync flash attention (bf16x3 both products). R9-proven core (occ 2,
// Q staged in smem). Epilogue now emits fp16 hi/lo for the fp16 out-proj.
// ---------------------------------------------------------------------------
#define ATROW 144
#define ATILE (64 * ATROW)                 // 9216
#define ASTAGE (4 * ATILE)                 // 36864: Kh | Kl | Vh | Vl
#define QTILE (128 * ATROW)                // 18432
#define ATT_SMEM (2 * ASTAGE + 2 * QTILE + 160)   // 110752 -> 2 CTAs/SM

__global__ __launch_bounds__(256, 2)
void mma_attn_kernel(const __nv_bfloat16* __restrict__ Qh, const __nv_bfloat16* __restrict__ Ql,
                     __half* __restrict__ Oh, __half* __restrict__ Ol) {
    extern __shared__ char sm[];
    const uint32_t sb  = smem_u32(sm);
    const uint32_t qsm = sb + 2 * ASTAGE;
    int* list = (int*)(sm + 2 * ASTAGE + 2 * QTILE);

    const int tid  = threadIdx.x;
    const int lane = tid & 31;
    const int w    = tid >> 5;
    const int b    = blockIdx.z;
    const int h    = blockIdx.y;
    const int q0   = blockIdx.x * 128;
    const int g    = lane >> 2;
    const int tq   = lane & 3;

    if (w == 0) {
        unsigned long long mb = g_mbits[b * 32 + lane];
        unsigned act = __ballot_sync(0xffffffffu, mb != 0ull);
        int pos = __popc(act & ((1u << lane) - 1));
        if (mb != 0ull) list[pos] = lane;
        if (lane == 0) list[32] = __popc(act);
    }
    __syncthreads();
    const int ncnt = list[32];

    // stage Q tile (128 rows x 64 bf16, hi+lo) into smem via cp.async
    {
        const int tok0 = b * SEQ + q0;
#pragma unroll
        for (int t = 0; t < 8; t++) {
            const int id  = tid + t * 256;
            const int arr = id >> 10;
            const int rem = id & 1023;
            const int r   = rem >> 3;
            const int seg = rem & 7;
            const size_t go = (size_t)(tok0 + r) * QKV3 + h * HD + seg * 8;
            const __nv_bfloat16* src = arr ? (Ql + go) : (Qh + go);
            CP_ASYNC16(qsm + arr * QTILE + r * ATROW + seg * 16, src);
        }
        CP_COMMIT();
    }

    auto load_tile = [&](int kt, int stg) {
        const int tok0 = b * SEQ + kt * 64;
        const uint32_t base = sb + stg * ASTAGE;
#pragma unroll
        for (int t = 0; t < 8; t++) {
            const int id  = tid + t * 256;
            const int arr = id >> 9;
            const int rem = id & 511;
            const int r   = rem >> 3;
            const int q   = rem & 7;
            const size_t go = (size_t)(tok0 + r) * QKV3 + h * HD + q * 8;
            const __nv_bfloat16* src;
            if (arr == 0)      src = Qh + go + HID;
            else if (arr == 1) src = Ql + go + HID;
            else if (arr == 2) src = Qh + go + 2 * HID;
            else               src = Ql + go + 2 * HID;
            CP_ASYNC16(base + arr * ATILE + r * ATROW + q * 16, src);
        }
        CP_COMMIT();
    };

    float o[8][4];
#pragma unroll
    for (int j = 0; j < 8; j++)
#pragma unroll
        for (int r = 0; r < 4; r++) o[j][r] = 0.0f;
    float mi[2] = {-1e30f, -1e30f}, li[2] = {0.0f, 0.0f};

    if (ncnt > 0) load_tile(list[0], 0);

    const uint32_t qrowoff = qsm + (uint32_t)(w * 16 + (lane & 15)) * ATROW
                           + ((lane >> 4) << 3) * 2;

    for (int it = 0; it < ncnt; it++) {
        if (it + 1 < ncnt) { load_tile(list[it + 1], (it + 1) & 1); CP_WAIT(1); }
        else CP_WAIT(0);
        __syncthreads();
        const uint32_t st = sb + (it & 1) * ASTAGE;
        const int kt = list[it];

        float s[8][4];
#pragma unroll
        for (int j = 0; j < 8; j++)
#pragma unroll
            for (int r = 0; r < 4; r++) s[j][r] = 0.0f;

#pragma unroll
        for (int kd = 0; kd < 4; kd++) {
            uint32_t qh4[4], ql4[4];
            const uint32_t qoff = qrowoff + kd * 32;
            ldsm_x4(qh4[0], qh4[1], qh4[2], qh4[3], qoff);
            ldsm_x4(ql4[0], ql4[1], ql4[2], ql4[3], qoff + QTILE);
#pragma unroll
            for (int kg = 0; kg < 4; kg++) {
                uint32_t kh[4], kl[4];
                const uint32_t off = st + (uint32_t)(kg * 16 + (lane & 7) + ((lane >> 4) << 3)) * ATROW
                                        + (kd * 16 + ((lane >> 3) & 1) * 8) * 2;
                ldsm_x4(kh[0], kh[1], kh[2], kh[3], off);
                ldsm_x4(kl[0], kl[1], kl[2], kl[3], off + ATILE);
                mma_bf16(s[kg * 2],     qh4, kh[0], kh[1]);
                mma_bf16(s[kg * 2],     qh4, kl[0], kl[1]);
                mma_bf16(s[kg * 2],     ql4, kh[0], kh[1]);
                mma_bf16(s[kg * 2 + 1], qh4, kh[2], kh[3]);
                mma_bf16(s[kg * 2 + 1], qh4, kl[2], kl[3]);
                mma_bf16(s[kg * 2 + 1], ql4, kh[2], kh[3]);
            }
        }

        const unsigned long long mb = g_mbits[b * 32 + kt];
        if (mb != ~0ull) {
#pragma unroll
            for (int nf = 0; nf < 8; nf++) {
                const int c0 = nf * 8 + tq * 2;
                if (!((mb >> c0) & 1))       { s[nf][0] = -1e30f; s[nf][2] = -1e30f; }
                if (!((mb >> (c0 + 1)) & 1)) { s[nf][1] = -1e30f; s[nf][3] = -1e30f; }
            }
        }

#pragma unroll
        for (int r = 0; r < 2; r++) {
            float mx = -1e30f;
#pragma unroll
            for (int nf = 0; nf < 8; nf++)
                mx = fmaxf(mx, fmaxf(s[nf][2 * r], s[nf][2 * r + 1]));
            mx = fmaxf(mx, __shfl_xor_sync(0xffffffffu, mx, 1));
            mx = fmaxf(mx, __shfl_xor_sync(0xffffffffu, mx, 2));
            const float mnew = fmaxf(mi[r], mx);
            const float al = fexp2(mi[r] - mnew);
            mi[r] = mnew;
            li[r] *= al;
#pragma unroll
            for (int nf = 0; nf < 8; nf++) { o[nf][2 * r] *= al; o[nf][2 * r + 1] *= al; }
            float ls = 0.0f;
#pragma unroll
            for (int nf = 0; nf < 8; nf++) {
                const float p0 = fexp2(s[nf][2 * r] - mnew);
                const float p1 = fexp2(s[nf][2 * r + 1] - mnew);
                ls += p0 + p1;
                s[nf][2 * r] = p0;
                s[nf][2 * r + 1] = p1;
            }
            ls += __shfl_xor_sync(0xffffffffu, ls, 1);
            ls += __shfl_xor_sync(0xffffffffu, ls, 2);
            li[r] += ls;
        }

        uint32_t pah[4][4], pal[4][4];
#pragma unroll
        for (int ks = 0; ks < 4; ks++) {
            split_pack(s[2 * ks][0],     s[2 * ks][1],     pah[ks][0], pal[ks][0]);
            split_pack(s[2 * ks][2],     s[2 * ks][3],     pah[ks][1], pal[ks][1]);
            split_pack(s[2 * ks + 1][0], s[2 * ks + 1][1], pah[ks][2], pal[ks][2]);
            split_pack(s[2 * ks + 1][2], s[2 * ks + 1][3], pah[ks][3], pal[ks][3]);
        }

#pragma unroll
        for (int ks = 0; ks < 4; ks++) {
#pragma unroll
            for (int dg = 0; dg < 4; dg++) {
                uint32_t vh[4], vl[4];
                const uint32_t off = st + 2 * ATILE
                                   + (uint32_t)(ks * 16 + (lane & 15)) * ATROW
                                   + (dg * 16 + ((lane >> 4) << 3)) * 2;
                ldsm_x4t(vh[0], vh[1], vh[2], vh[3], off);
                ldsm_x4t(vl[0], vl[1], vl[2], vl[3], off + ATILE);
                mma_bf16(o[dg * 2],     pah[ks], vh[0], vh[1]);
                mma_bf16(o[dg * 2],     pah[ks], vl[0], vl[1]);
                mma_bf16(o[dg * 2],     pal[ks], vh[0], vh[1]);
                mma_bf16(o[dg * 2 + 1], pah[ks], vh[2], vh[3]);
                mma_bf16(o[dg * 2 + 1], pah[ks], vl[2], vl[3]);
                mma_bf16(o[dg * 2 + 1], pal[ks], vh[2], vh[3]);
            }
        }
        __syncthreads();
    }

    // epilogue: normalize, split to fp16 hi/lo (out-proj input format)
#pragma unroll
    for (int r = 0; r < 2; r++) {
        const float inv = 1.0f / li[r];
        const size_t ob = (size_t)(b * SEQ + q0 + w * 16 + g + r * 8) * HID + h * HD;
#pragma unroll
        for (int nf = 0; nf < 8; nf++) {
            uint32_t hp, lp;
            split_pack_h(o[nf][2 * r] * inv, o[nf][2 * r + 1] * inv, hp, lp);
            *(uint32_t*)(Oh + ob + nf * 8 + tq * 2) = hp;
            *(uint32_t*)(Ol + ob + nf * 8 + tq * 2) = lp;
        }
    }
}

// ---------------------------------------------------------------------------
// Launch
// ---------------------------------------------------------------------------
extern "C" void kernel_launch(void* const* d_in, const int* in_sizes, int n_in,
                              void* d_out, int out_size) {
    const float* hidden = (const float*)d_in[0];
    const void*  maskp  = d_in[1];
    const float* Wqkv   = (const float*)d_in[2];
    const float* Wout   = (const float*)d_in[3];
    const float* bout   = (const float*)d_in[4];
    float*       out    = (float*)d_out;

    void *p_qh, *p_ql, *p_ah, *p_al, *p_wq, *p_wo;
    cudaGetSymbolAddress(&p_qh, g_qh);
    cudaGetSymbolAddress(&p_ql, g_ql);
    cudaGetSymbolAddress(&p_ah, g_ah);
    cudaGetSymbolAddress(&p_al, g_al);
    cudaGetSymbolAddress(&p_wq, g_wq);
    cudaGetSymbolAddress(&p_wo, g_wo);

    cudaFuncSetAttribute(f16_gemm_kernel<0>,
                         cudaFuncAttributeMaxDynamicSharedMemorySize, TC_SMEM);
    cudaFuncSetAttribute(f16_gemm_kernel<1>,
                         cudaFuncAttributeMaxDynamicSharedMemorySize, TC_SMEM);
    cudaFuncSetAttribute(mma_attn_kernel,
                         cudaFuncAttributeMaxDynamicSharedMemorySize, ATT_SMEM);

    // 1. mask canonicalize + tile bitmasks
    mask_convert_kernel<<<1, 256>>>(maskp, BATCH * SEQ);

    // 2. fp16 prep: hidden -> fp16 pairs; weights -> fp16 single (transposed)
    splitA_f16_kernel<<<592, 256>>>(hidden, (__half*)p_ah, (__half*)p_al,
                                    MROWS * HID / 4);
    quantWT_f16_kernel<<<dim3(QKV3 / 32, HID / 32), 256>>>(Wqkv, (__half*)p_wq, HID, QKV3);
    quantWT_f16_kernel<<<dim3(HID / 32, HID / 32), 256>>>(Wout, (__half*)p_wo, HID, HID);

    // 3. QKV projection (fp16 2-term) -> bf16 hi/lo splits (Q pre-scaled)
    f16_gemm_kernel<0><<<dim3(QKV3 / 128, MROWS / 128), 256, TC_SMEM>>>(
        (const __half*)p_ah, (const __half*)p_al, (const __half*)p_wq,
        nullptr, nullptr, (__nv_bfloat16*)p_qh, (__nv_bfloat16*)p_ql,
        MROWS, QKV3, HID);

    // 4. tensor-core flash attention (bf16x3) -> fp16 hi/lo attention output
    mma_attn_kernel<<<dim3(SEQ / 128, NH, BATCH), 256, ATT_SMEM>>>(
        (const __nv_bfloat16*)p_qh, (const __nv_bfloat16*)p_ql,
        (__half*)p_ah, (__half*)p_al);

    // 5. output projection (fp16 2-term, +bias)
    f16_gemm_kernel<1><<<dim3(HID / 128, MROWS / 128), 256, TC_SMEM>>>(
        (const __half*)p_ah, (const __half*)p_al, (const __half*)p_wo,
        bout, out, nullptr, nullptr, MROWS, HID, HID);
}

// round 11
// speedup vs baseline: 2.4035x; 1.1951x over previous
#include <cuda_runtime.h>
#include <cuda_bf16.h>
#include <cuda_fp16.h>
#include <cstdint>

#define BATCH 4
#define SEQ   2048
#define NH    16
#define HD    64
#define HID   1024
#define QKV3  3072
#define MROWS (BATCH * SEQ)        // 8192

// 0.125 * log2(e): folded into Q at the QKV epilogue (softmax in base-2 domain)
#define QSF 0.18033688011112042f

// ---------------------------------------------------------------------------
// Scratch (static device globals — allocation-free per harness rules)
// ---------------------------------------------------------------------------
__device__ __half        g_qh[MROWS * QKV3];           // Q hi pair | K single | V single (fp16)
__device__ __half        g_ql[MROWS * QKV3];           // Q lo pair (cols < HID only)
__device__ int           g_mask[BATCH * SEQ];
__device__ unsigned long long g_mbits[BATCH * 32];     // 64-key tile bitmasks
__device__ __half        g_ah[MROWS * HID];            // activation hi fp16 (hidden, then attn out)
__device__ __half        g_al[MROWS * HID];            // activation lo fp16
__device__ __half        g_wq[QKV3 * HID];             // Wqkv^T single fp16 [N,K]
__device__ __half        g_wo[HID * HID];              // Wout^T single fp16 [N,K]

// ---------------------------------------------------------------------------
// PTX helpers (arch-portable sm_80+; tcgen05 unavailable via compute_103;
// s8 mma.sync measured ~4-5x worse rt than HMMA on sm_103 — do not use)
// ---------------------------------------------------------------------------
__device__ __forceinline__ uint32_t smem_u32(const void* p) {
    uint32_t a;
    asm("{ .reg .u64 t; cvta.to.shared.u64 t, %1; cvt.u32.u64 %0, t; }" : "=r"(a) : "l"(p));
    return a;
}
__device__ __forceinline__ void ldsm_x4(uint32_t& r0, uint32_t& r1, uint32_t& r2, uint32_t& r3,
                                        uint32_t addr) {
    asm volatile("ldmatrix.sync.aligned.m8n8.x4.shared.b16 {%0,%1,%2,%3}, [%4];"
                 : "=r"(r0), "=r"(r1), "=r"(r2), "=r"(r3) : "r"(addr));
}
__device__ __forceinline__ void ldsm_x4t(uint32_t& r0, uint32_t& r1, uint32_t& r2, uint32_t& r3,
                                         uint32_t addr) {
    asm volatile("ldmatrix.sync.aligned.m8n8.x4.trans.shared.b16 {%0,%1,%2,%3}, [%4];"
                 : "=r"(r0), "=r"(r1), "=r"(r2), "=r"(r3) : "r"(addr));
}
__device__ __forceinline__ void mma_f16(float* c, const uint32_t* a, uint32_t b0, uint32_t b1) {
    asm volatile(
        "mma.sync.aligned.m16n8k16.row.col.f32.f16.f16.f32 "
        "{%0,%1,%2,%3}, {%4,%5,%6,%7}, {%8,%9}, {%0,%1,%2,%3};"
        : "+f"(c[0]), "+f"(c[1]), "+f"(c[2]), "+f"(c[3])
        : "r"(a[0]), "r"(a[1]), "r"(a[2]), "r"(a[3]), "r"(b0), "r"(b1));
}
__device__ __forceinline__ float fexp2(float x) {
    float y; asm("ex2.approx.f32 %0, %1;" : "=f"(y) : "f"(x)); return y;
}
// fp16 hi/lo split-pack
__device__ __forceinline__ void split_pack_h(float x, float y, uint32_t& hp, uint32_t& lp) {
    __half2 hv, lv;
    hv.x = __float2half(x);
    hv.y = __float2half(y);
    lv.x = __float2half(x - __half2float(hv.x));
    lv.y = __float2half(y - __half2float(hv.y));
    hp = *(uint32_t*)&hv;
    lp = *(uint32_t*)&lv;
}
#define CP_ASYNC16(dst, src) \
    asm volatile("cp.async.cg.shared.global [%0], [%1], 16;" :: "r"(dst), "l"(src))
#define CP_COMMIT() asm volatile("cp.async.commit_group;" ::: "memory")
#define CP_WAIT(n)  asm volatile("cp.async.wait_group %0;" :: "n"(n) : "memory")

// ---------------------------------------------------------------------------
// Mask canonicalizer + per-64-key-tile bitmasks
// ---------------------------------------------------------------------------
__global__ void mask_convert_kernel(const void* __restrict__ raw, int n) {
    __shared__ int mode;
    if (threadIdx.x == 0) {
        unsigned w0 = ((const unsigned*)raw)[0];
        if (w0 == 1u || w0 == 0u)    mode = 0;  // int32
        else if (w0 == 0x3F800000u)  mode = 1;  // float32
        else if (w0 == 0x01010101u)  mode = 2;  // uint8
        else if (w0 == 0x3F803F80u)  mode = 3;  // bf16 pair
        else                          mode = 2;
    }
    __syncthreads();
    int m = mode;
    for (int i = threadIdx.x; i < n; i += blockDim.x) {
        int v;
        if (m == 0)      v = (((const int*)raw)[i] != 0);
        else if (m == 1) v = (((const float*)raw)[i] != 0.0f);
        else if (m == 2) v = (((const unsigned char*)raw)[i] != 0);
        else { unsigned short h = ((const unsigned short*)raw)[i]; v = ((h & 0x7FFF) != 0); }
        g_mask[i] = v;
    }
    __syncthreads();
    for (int t = threadIdx.x; t < BATCH * 32; t += blockDim.x) {
        int b = t >> 5, kt = t & 31;
        unsigned long long mb = 0ull;
        for (int j = 0; j < 64; j++)
            mb |= ((unsigned long long)(g_mask[b * SEQ + kt * 64 + j] & 1)) << j;
        g_mbits[t] = mb;
    }
}

// ---------------------------------------------------------------------------
// fp16 prep kernels
// ---------------------------------------------------------------------------
__global__ void splitA_f16_kernel(const float* __restrict__ A,
                                  __half* __restrict__ Ah,
                                  __half* __restrict__ Al, int n4) {
    int stride = gridDim.x * blockDim.x;
    for (int i = blockIdx.x * blockDim.x + threadIdx.x; i < n4; i += stride) {
        float4 v = ((const float4*)A)[i];
        uint32_t h0, l0, h1, l1;
        split_pack_h(v.x, v.y, h0, l0);
        split_pack_h(v.z, v.w, h1, l1);
        ((uint32_t*)Ah)[i * 2]     = h0;
        ((uint32_t*)Ah)[i * 2 + 1] = h1;
        ((uint32_t*)Al)[i * 2]     = l0;
        ((uint32_t*)Al)[i * 2 + 1] = l1;
    }
}

// W [K,N] fp32 -> W^T [N,K] single fp16
__global__ void quantWT_f16_kernel(const float* __restrict__ W,
                                   __half* __restrict__ WT, int K, int N) {
    __shared__ float tile[32][33];
    int k0 = blockIdx.y * 32, n0 = blockIdx.x * 32;
    int tx = threadIdx.x & 31, ty = threadIdx.x >> 5;
    for (int r = ty; r < 32; r += 8)
        tile[r][tx] = W[(size_t)(k0 + r) * N + n0 + tx];
    __syncthreads();
    for (int r = ty; r < 32; r += 8)
        WT[(size_t)(n0 + r) * K + k0 + tx] = __float2half(tile[tx][r]);
}

// ---------------------------------------------------------------------------
// fp16 2-term GEMM: C = A @ WT^T. A split fp16 pair (exact), W single fp16.
// MODE 0 (QKV): Q cols -> fp16 pair (pre-scaled by QSF); K/V cols -> single fp16.
// MODE 1 (out-proj): fp32 + bias.
// ---------------------------------------------------------------------------
#define KC        32
#define TROW      80
#define TILE_B    (128 * TROW)          // 10240
#define STAGE_B   (3 * TILE_B)          // 30720: Ah | Al | B
#define TC_SMEM   (2 * STAGE_B)         // 61440

template <int MODE>
__global__ __launch_bounds__(256, 2)
void f16_gemm_kernel(const __half* __restrict__ Ah, const __half* __restrict__ Al,
                     const __half* __restrict__ WT,
                     const float* __restrict__ bias, float* __restrict__ C,
                     __half* __restrict__ Ch, __half* __restrict__ Cl,
                     int M, int N, int K) {
    extern __shared__ char smem[];
    const uint32_t sb = smem_u32(smem);
    const int tid   = threadIdx.x;
    const int lane  = tid & 31;
    const int wid   = tid >> 5;
    const int warpM = wid & 3;
    const int warpN = wid >> 2;
    const int m0 = blockIdx.y * 128;
    const int n0 = blockIdx.x * 128;
    const int nch = K / KC;

    auto load_stage = [&](int kc0, int s) {
        const uint32_t stg = sb + s * STAGE_B;
#pragma unroll
        for (int t = 0; t < 6; t++) {
            const int id   = tid + t * 256;
            const int tile = id >> 9;             // 0:Ah 1:Al 2:B
            const int rem  = id & 511;
            const int row  = rem >> 2;
            const int q    = rem & 3;
            const __half* src;
            if (tile == 0)      src = Ah + (size_t)(m0 + row) * K + kc0 + q * 8;
            else if (tile == 1) src = Al + (size_t)(m0 + row) * K + kc0 + q * 8;
            else                src = WT + (size_t)(n0 + row) * K + kc0 + q * 8;
            CP_ASYNC16(stg + tile * TILE_B + row * TROW + q * 16, src);
        }
        CP_COMMIT();
    };

    float c[2][8][4];
#pragma unroll
    for (int i = 0; i < 2; i++)
#pragma unroll
        for (int j = 0; j < 8; j++)
#pragma unroll
            for (int r = 0; r < 4; r++) c[i][j][r] = 0.0f;

    const int arow = warpM * 32 + (lane & 15);
    const int acol = (lane >> 4) * 8;
    const int brow = warpN * 64 + (lane & 7) + ((lane >> 4) << 3);
    const int bck  = ((lane >> 3) & 1) * 8;

    load_stage(0, 0);
    load_stage(KC, 1);

    for (int ch = 0; ch < nch; ch++) {
        CP_WAIT(1);
        __syncthreads();

        const uint32_t stg = sb + (ch & 1) * STAGE_B;
        const uint32_t ahb = stg;
        const uint32_t alb = stg + TILE_B;
        const uint32_t bbb = stg + 2 * TILE_B;

#pragma unroll
        for (int k16 = 0; k16 < 2; k16++) {
            uint32_t fah[2][4], fal[2][4];
#pragma unroll
            for (int mt = 0; mt < 2; mt++) {
                uint32_t off = (uint32_t)(arow + mt * 16) * TROW + (k16 * 16 + acol) * 2;
                ldsm_x4(fah[mt][0], fah[mt][1], fah[mt][2], fah[mt][3], ahb + off);
                ldsm_x4(fal[mt][0], fal[mt][1], fal[mt][2], fal[mt][3], alb + off);
            }
#pragma unroll
            for (int np = 0; np < 4; np++) {
                uint32_t bf[4];
                uint32_t off = (uint32_t)(brow + np * 16) * TROW + (k16 * 16 + bck) * 2;
                ldsm_x4(bf[0], bf[1], bf[2], bf[3], bbb + off);
#pragma unroll
                for (int mt = 0; mt < 2; mt++)
#pragma unroll
                    for (int half = 0; half < 2; half++) {
                        float* acc = c[mt][np * 2 + half];
                        mma_f16(acc, fah[mt], bf[half * 2], bf[half * 2 + 1]);
                        mma_f16(acc, fal[mt], bf[half * 2], bf[half * 2 + 1]);
                    }
            }
        }
        __syncthreads();
        if (ch + 2 < nch) load_stage((ch + 2) * KC, ch & 1);
        else CP_COMMIT();   // placeholder group: keeps CP_WAIT(1) accounting exact
    }

    const int g   = lane >> 2;
    const int tig = lane & 3;
#pragma unroll
    for (int mt = 0; mt < 2; mt++) {
        const int row = m0 + warpM * 32 + mt * 16 + g;
#pragma unroll
        for (int nt = 0; nt < 8; nt++) {
            const int col = n0 + warpN * 64 + nt * 8 + tig * 2;
            if (MODE == 1) {
                float2 v0 = make_float2(c[mt][nt][0] + bias[col], c[mt][nt][1] + bias[col + 1]);
                float2 v1 = make_float2(c[mt][nt][2] + bias[col], c[mt][nt][3] + bias[col + 1]);
                *(float2*)(C + (size_t)row * N + col)       = v0;
                *(float2*)(C + (size_t)(row + 8) * N + col) = v1;
            } else {
                if (col < HID) {
                    // Q: fp16 pair, pre-scaled
                    uint32_t hp, lp;
                    split_pack_h(c[mt][nt][0] * QSF, c[mt][nt][1] * QSF, hp, lp);
                    *(uint32_t*)(Ch + (size_t)row * N + col) = hp;
                    *(uint32_t*)(Cl + (size_t)row * N + col) = lp;
                    split_pack_h(c[mt][nt][2] * QSF, c[mt][nt][3] * QSF, hp, lp);
                    *(uint32_t*)(Ch + (size_t)(row + 8) * N + col) = hp;
                    *(uint32_t*)(Cl + (size_t)(row + 8) * N + col) = lp;
                } else {
                    // K/V: single fp16
                    __half2 v0; v0.x = __float2half(c[mt][nt][0]); v0.y = __float2half(c[mt][nt][1]);
                    __half2 v1; v1.x = __float2half(c[mt][nt][2]); v1.y = __float2half(c[mt][nt][3]);
                    *(__half2*)(Ch + (size_t)row * N + col)       = v0;
                    *(__half2*)(Ch + (size_t)(row + 8) * N + col) = v1;
                }
            }
        }
    }
}

// ---------------------------------------------------------------------------
// fp16 flash attention: Q fp16 pair (smem-staged), K/V single fp16.
// QK: 2 MMAs/k16 (Qh.K + Ql.K); PV: 2 MMAs/k16 (Ph.V + Pl.V).
// Occupancy 2; smem 73.9 KB.
// ---------------------------------------------------------------------------
#define ATROW 144
#define ATILE (64 * ATROW)                 // 9216
#define ASTAGE (2 * ATILE)                 // 18432: K | V (singles)
#define QTILE (128 * ATROW)                // 18432
#define ATT_SMEM (2 * ASTAGE + 2 * QTILE + 160)   // 73888

__global__ __launch_bounds__(256, 2)
void mma_attn_kernel(const __half* __restrict__ Qh, const __half* __restrict__ Ql,
                     __half* __restrict__ Oh, __half* __restrict__ Ol) {
    extern __shared__ char sm[];
    const uint32_t sb  = smem_u32(sm);
    const uint32_t qsm = sb + 2 * ASTAGE;
    int* list = (int*)(sm + 2 * ASTAGE + 2 * QTILE);

    const int tid  = threadIdx.x;
    const int lane = tid & 31;
    const int w    = tid >> 5;
    const int b    = blockIdx.z;
    const int h    = blockIdx.y;
    const int q0   = blockIdx.x * 128;
    const int g    = lane >> 2;
    const int tq   = lane & 3;

    if (w == 0) {
        unsigned long long mb = g_mbits[b * 32 + lane];
        unsigned act = __ballot_sync(0xffffffffu, mb != 0ull);
        int pos = __popc(act & ((1u << lane) - 1));
        if (mb != 0ull) list[pos] = lane;
        if (lane == 0) list[32] = __popc(act);
    }
    __syncthreads();
    const int ncnt = list[32];

    // stage Q tile (128 rows x 64 fp16, hi+lo) into smem
    {
        const int tok0 = b * SEQ + q0;
#pragma unroll
        for (int t = 0; t < 8; t++) {
            const int id  = tid + t * 256;
            const int arr = id >> 10;             // 0:Qh 1:Ql
            const int rem = id & 1023;
            const int r   = rem >> 3;
            const int seg = rem & 7;
            const size_t go = (size_t)(tok0 + r) * QKV3 + h * HD + seg * 8;
            const __half* src = arr ? (Ql + go) : (Qh + go);
            CP_ASYNC16(qsm + arr * QTILE + r * ATROW + seg * 16, src);
        }
        CP_COMMIT();
    }

    auto load_tile = [&](int kt, int stg) {
        const int tok0 = b * SEQ + kt * 64;
        const uint32_t base = sb + stg * ASTAGE;
#pragma unroll
        for (int t = 0; t < 4; t++) {
            const int id  = tid + t * 256;
            const int arr = id >> 9;              // 0:K 1:V
            const int rem = id & 511;
            const int r   = rem >> 3;
            const int q   = rem & 7;
            const size_t go = (size_t)(tok0 + r) * QKV3 + h * HD + q * 8;
            const __half* src = arr ? (Qh + go + 2 * HID) : (Qh + go + HID);
            CP_ASYNC16(base + arr * ATILE + r * ATROW + q * 16, src);
        }
        CP_COMMIT();
    };

    float o[8][4];
#pragma unroll
    for (int j = 0; j < 8; j++)
#pragma unroll
        for (int r = 0; r < 4; r++) o[j][r] = 0.0f;
    float mi[2] = {-1e30f, -1e30f}, li[2] = {0.0f, 0.0f};

    if (ncnt > 0) load_tile(list[0], 0);

    const uint32_t qrowoff = qsm + (uint32_t)(w * 16 + (lane & 15)) * ATROW
                           + ((lane >> 4) << 3) * 2;

    for (int it = 0; it < ncnt; it++) {
        if (it + 1 < ncnt) { load_tile(list[it + 1], (it + 1) & 1); CP_WAIT(1); }
        else CP_WAIT(0);
        __syncthreads();
        const uint32_t st = sb + (it & 1) * ASTAGE;
        const int kt = list[it];

        // ---- S = Q @ K^T (2-term) ----
        float s[8][4];
#pragma unroll
        for (int j = 0; j < 8; j++)
#pragma unroll
            for (int r = 0; r < 4; r++) s[j][r] = 0.0f;

#pragma unroll
        for (int kd = 0; kd < 4; kd++) {
            uint32_t qh4[4], ql4[4];
            const uint32_t qoff = qrowoff + kd * 32;
            ldsm_x4(qh4[0], qh4[1], qh4[2], qh4[3], qoff);
            ldsm_x4(ql4[0], ql4[1], ql4[2], ql4[3], qoff + QTILE);
#pragma unroll
            for (int kg = 0; kg < 4; kg++) {
                uint32_t kh[4];
                const uint32_t off = st + (uint32_t)(kg * 16 + (lane & 7) + ((lane >> 4) << 3)) * ATROW
                                        + (kd * 16 + ((lane >> 3) & 1) * 8) * 2;
                ldsm_x4(kh[0], kh[1], kh[2], kh[3], off);
                mma_f16(s[kg * 2],     qh4, kh[0], kh[1]);
                mma_f16(s[kg * 2],     ql4, kh[0], kh[1]);
                mma_f16(s[kg * 2 + 1], qh4, kh[2], kh[3]);
                mma_f16(s[kg * 2 + 1], ql4, kh[2], kh[3]);
            }
        }

        // ---- key-padding mask ----
        const unsigned long long mb = g_mbits[b * 32 + kt];
        if (mb != ~0ull) {
#pragma unroll
            for (int nf = 0; nf < 8; nf++) {
                const int c0 = nf * 8 + tq * 2;
                if (!((mb >> c0) & 1))       { s[nf][0] = -1e30f; s[nf][2] = -1e30f; }
                if (!((mb >> (c0 + 1)) & 1)) { s[nf][1] = -1e30f; s[nf][3] = -1e30f; }
            }
        }

        // ---- online softmax (base-2; Q pre-scaled) ----
#pragma unroll
        for (int r = 0; r < 2; r++) {
            float mx = -1e30f;
#pragma unroll
            for (int nf = 0; nf < 8; nf++)
                mx = fmaxf(mx, fmaxf(s[nf][2 * r], s[nf][2 * r + 1]));
            mx = fmaxf(mx, __shfl_xor_sync(0xffffffffu, mx, 1));
            mx = fmaxf(mx, __shfl_xor_sync(0xffffffffu, mx, 2));
            const float mnew = fmaxf(mi[r], mx);
            const float al = fexp2(mi[r] - mnew);
            mi[r] = mnew;
            li[r] *= al;
#pragma unroll
            for (int nf = 0; nf < 8; nf++) { o[nf][2 * r] *= al; o[nf][2 * r + 1] *= al; }
            float ls = 0.0f;
#pragma unroll
            for (int nf = 0; nf < 8; nf++) {
                const float p0 = fexp2(s[nf][2 * r] - mnew);
                const float p1 = fexp2(s[nf][2 * r + 1] - mnew);
                ls += p0 + p1;
                s[nf][2 * r] = p0;
                s[nf][2 * r + 1] = p1;
            }
            ls += __shfl_xor_sync(0xffffffffu, ls, 1);
            ls += __shfl_xor_sync(0xffffffffu, ls, 2);
            li[r] += ls;
        }

        // ---- pack P into fp16 A-fragments (hi/lo) ----
        uint32_t pah[4][4], pal[4][4];
#pragma unroll
        for (int ks = 0; ks < 4; ks++) {
            split_pack_h(s[2 * ks][0],     s[2 * ks][1],     pah[ks][0], pal[ks][0]);
            split_pack_h(s[2 * ks][2],     s[2 * ks][3],     pah[ks][1], pal[ks][1]);
            split_pack_h(s[2 * ks + 1][0], s[2 * ks + 1][1], pah[ks][2], pal[ks][2]);
            split_pack_h(s[2 * ks + 1][2], s[2 * ks + 1][3], pah[ks][3], pal[ks][3]);
        }

        // ---- O += P @ V (2-term; V single fp16) ----
#pragma unroll
        for (int ks = 0; ks < 4; ks++) {
#pragma unroll
            for (int dg = 0; dg < 4; dg++) {
                uint32_t vh[4];
                const uint32_t off = st + ATILE
                                   + (uint32_t)(ks * 16 + (lane & 15)) * ATROW
                                   + (dg * 16 + ((lane >> 4) << 3)) * 2;
                ldsm_x4t(vh[0], vh[1], vh[2], vh[3], off);
                mma_f16(o[dg * 2],     pah[ks], vh[0], vh[1]);
                mma_f16(o[dg * 2],     pal[ks], vh[0], vh[1]);
                mma_f16(o[dg * 2 + 1], pah[ks], vh[2], vh[3]);
                mma_f16(o[dg * 2 + 1], pal[ks], vh[2], vh[3]);
            }
        }
        __syncthreads();
    }

    // epilogue: normalize, split to fp16 hi/lo (out-proj input format)
#pragma unroll
    for (int r = 0; r < 2; r++) {
        const float inv = 1.0f / li[r];
        const size_t ob = (size_t)(b * SEQ + q0 + w * 16 + g + r * 8) * HID + h * HD;
#pragma unroll
        for (int nf = 0; nf < 8; nf++) {
            uint32_t hp, lp;
            split_pack_h(o[nf][2 * r] * inv, o[nf][2 * r + 1] * inv, hp, lp);
            *(uint32_t*)(Oh + ob + nf * 8 + tq * 2) = hp;
            *(uint32_t*)(Ol + ob + nf * 8 + tq * 2) = lp;
        }
    }
}

// ---------------------------------------------------------------------------
// Launch
// ---------------------------------------------------------------------------
extern "C" void kernel_launch(void* const* d_in, const int* in_sizes, int n_in,
                              void* d_out, int out_size) {
    const float* hidden = (const float*)d_in[0];
    const void*  maskp  = d_in[1];
    const float* Wqkv   = (const float*)d_in[2];
    const float* Wout   = (const float*)d_in[3];
    const float* bout   = (const float*)d_in[4];
    float*       out    = (float*)d_out;

    void *p_qh, *p_ql, *p_ah, *p_al, *p_wq, *p_wo;
    cudaGetSymbolAddress(&p_qh, g_qh);
    cudaGetSymbolAddress(&p_ql, g_ql);
    cudaGetSymbolAddress(&p_ah, g_ah);
    cudaGetSymbolAddress(&p_al, g_al);
    cudaGetSymbolAddress(&p_wq, g_wq);
    cudaGetSymbolAddress(&p_wo, g_wo);

    cudaFuncSetAttribute(f16_gemm_kernel<0>,
                         cudaFuncAttributeMaxDynamicSharedMemorySize, TC_SMEM);
    cudaFuncSetAttribute(f16_gemm_kernel<1>,
                         cudaFuncAttributeMaxDynamicSharedMemorySize, TC_SMEM);
    cudaFuncSetAttribute(mma_attn_kernel,
                         cudaFuncAttributeMaxDynamicSharedMemorySize, ATT_SMEM);

    // 1. mask canonicalize + tile bitmasks
    mask_convert_kernel<<<1, 256>>>(maskp, BATCH * SEQ);

    // 2. fp16 prep
    splitA_f16_kernel<<<592, 256>>>(hidden, (__half*)p_ah, (__half*)p_al,
                                    MROWS * HID / 4);
    quantWT_f16_kernel<<<dim3(QKV3 / 32, HID / 32), 256>>>(Wqkv, (__half*)p_wq, HID, QKV3);
    quantWT_f16_kernel<<<dim3(HID / 32, HID / 32), 256>>>(Wout, (__half*)p_wo, HID, HID);

    // 3. QKV projection (fp16 2-term) -> Q fp16 pair (pre-scaled) + K/V single fp16
    f16_gemm_kernel<0><<<dim3(QKV3 / 128, MROWS / 128), 256, TC_SMEM>>>(
        (const __half*)p_ah, (const __half*)p_al, (const __half*)p_wq,
        nullptr, nullptr, (__half*)p_qh, (__half*)p_ql,
        MROWS, QKV3, HID);

    // 4. fp16 flash attention -> fp16 hi/lo attention output
    mma_attn_kernel<<<dim3(SEQ / 128, NH, BATCH), 256, ATT_SMEM>>>(
        (const __half*)p_qh, (const __half*)p_ql,
        (__half*)p_ah, (__half*)p_al);

    // 5. output projection (fp16 2-term, +bias)
    f16_gemm_kernel<1><<<dim3(HID / 128, MROWS / 128), 256, TC_SMEM>>>(
        (const __half*)p_ah, (const __half*)p_al, (const __half*)p_wo,
        bout, out, nullptr, nullptr, MROWS, HID, HID);
}

// round 12
// speedup vs baseline: 2.9003x; 1.2067x over previous
#include <cuda_runtime.h>
#include <cuda_bf16.h>
#include <cuda_fp16.h>
#include <cstdint>

#define BATCH 4
#define SEQ   2048
#define NH    16
#define HD    64
#define HID   1024
#define QKV3  3072
#define MROWS (BATCH * SEQ)        // 8192

// 0.125 * log2(e): folded into Q at the QKV epilogue (softmax in base-2 domain)
#define QSF 0.18033688011112042f

// ---------------------------------------------------------------------------
// Scratch (static device globals — allocation-free per harness rules)
// ---------------------------------------------------------------------------
__device__ __half        g_qh[MROWS * QKV3];           // Q hi pair | K single | V single (fp16)
__device__ __half        g_ql[MROWS * QKV3];           // Q lo pair (cols < HID only)
__device__ int           g_mask[BATCH * SEQ];
__device__ unsigned long long g_mbits[BATCH * 32];     // 64-key tile bitmasks
__device__ __half        g_ah[MROWS * HID];            // activation hi fp16 (hidden single, then attn-out hi)
__device__ __half        g_al[MROWS * HID];            // activation lo fp16 (attn-out lo)
__device__ __half        g_wq[QKV3 * HID];             // Wqkv^T single fp16 [N,K]
__device__ __half        g_wo[HID * HID];              // Wout^T single fp16 [N,K]

// ---------------------------------------------------------------------------
// PTX helpers (arch-portable sm_80+; tcgen05 unavailable via compute_103;
// s8 mma.sync measured ~4-5x worse rt than HMMA on sm_103 — do not use)
// ---------------------------------------------------------------------------
__device__ __forceinline__ uint32_t smem_u32(const void* p) {
    uint32_t a;
    asm("{ .reg .u64 t; cvta.to.shared.u64 t, %1; cvt.u32.u64 %0, t; }" : "=r"(a) : "l"(p));
    return a;
}
__device__ __forceinline__ void ldsm_x4(uint32_t& r0, uint32_t& r1, uint32_t& r2, uint32_t& r3,
                                        uint32_t addr) {
    asm volatile("ldmatrix.sync.aligned.m8n8.x4.shared.b16 {%0,%1,%2,%3}, [%4];"
                 : "=r"(r0), "=r"(r1), "=r"(r2), "=r"(r3) : "r"(addr));
}
__device__ __forceinline__ void ldsm_x4t(uint32_t& r0, uint32_t& r1, uint32_t& r2, uint32_t& r3,
                                         uint32_t addr) {
    asm volatile("ldmatrix.sync.aligned.m8n8.x4.trans.shared.b16 {%0,%1,%2,%3}, [%4];"
                 : "=r"(r0), "=r"(r1), "=r"(r2), "=r"(r3) : "r"(addr));
}
__device__ __forceinline__ void mma_f16(float* c, const uint32_t* a, uint32_t b0, uint32_t b1) {
    asm volatile(
        "mma.sync.aligned.m16n8k16.row.col.f32.f16.f16.f32 "
        "{%0,%1,%2,%3}, {%4,%5,%6,%7}, {%8,%9}, {%0,%1,%2,%3};"
        : "+f"(c[0]), "+f"(c[1]), "+f"(c[2]), "+f"(c[3])
        : "r"(a[0]), "r"(a[1]), "r"(a[2]), "r"(a[3]), "r"(b0), "r"(b1));
}
__device__ __forceinline__ float fexp2(float x) {
    float y; asm("ex2.approx.f32 %0, %1;" : "=f"(y) : "f"(x)); return y;
}
// fp16 hi/lo split-pack
__device__ __forceinline__ void split_pack_h(float x, float y, uint32_t& hp, uint32_t& lp) {
    __half2 hv, lv;
    hv.x = __float2half(x);
    hv.y = __float2half(y);
    lv.x = __float2half(x - __half2float(hv.x));
    lv.y = __float2half(y - __half2float(hv.y));
    hp = *(uint32_t*)&hv;
    lp = *(uint32_t*)&lv;
}
#define CP_ASYNC16(dst, src) \
    asm volatile("cp.async.cg.shared.global [%0], [%1], 16;" :: "r"(dst), "l"(src))
#define CP_COMMIT() asm volatile("cp.async.commit_group;" ::: "memory")
#define CP_WAIT(n)  asm volatile("cp.async.wait_group %0;" :: "n"(n) : "memory")

// ---------------------------------------------------------------------------
// Mask canonicalizer + per-64-key-tile bitmasks
// ---------------------------------------------------------------------------
__global__ void mask_convert_kernel(const void* __restrict__ raw, int n) {
    __shared__ int mode;
    if (threadIdx.x == 0) {
        unsigned w0 = ((const unsigned*)raw)[0];
        if (w0 == 1u || w0 == 0u)    mode = 0;  // int32
        else if (w0 == 0x3F800000u)  mode = 1;  // float32
        else if (w0 == 0x01010101u)  mode = 2;  // uint8
        else if (w0 == 0x3F803F80u)  mode = 3;  // bf16 pair
        else                          mode = 2;
    }
    __syncthreads();
    int m = mode;
    for (int i = threadIdx.x; i < n; i += blockDim.x) {
        int v;
        if (m == 0)      v = (((const int*)raw)[i] != 0);
        else if (m == 1) v = (((const float*)raw)[i] != 0.0f);
        else if (m == 2) v = (((const unsigned char*)raw)[i] != 0);
        else { unsigned short h = ((const unsigned short*)raw)[i]; v = ((h & 0x7FFF) != 0); }
        g_mask[i] = v;
    }
    __syncthreads();
    for (int t = threadIdx.x; t < BATCH * 32; t += blockDim.x) {
        int b = t >> 5, kt = t & 31;
        unsigned long long mb = 0ull;
        for (int j = 0; j < 64; j++)
            mb |= ((unsigned long long)(g_mask[b * SEQ + kt * 64 + j] & 1)) << j;
        g_mbits[t] = mb;
    }
}

// ---------------------------------------------------------------------------
// fp16 prep kernels
// ---------------------------------------------------------------------------
// fp32 -> single fp16 (hidden activations for QKV GEMM)
__global__ void convA_f16_kernel(const float* __restrict__ A,
                                 __half* __restrict__ Ah, int n4) {
    int stride = gridDim.x * blockDim.x;
    for (int i = blockIdx.x * blockDim.x + threadIdx.x; i < n4; i += stride) {
        float4 v = ((const float4*)A)[i];
        __half2 h0; h0.x = __float2half(v.x); h0.y = __float2half(v.y);
        __half2 h1; h1.x = __float2half(v.z); h1.y = __float2half(v.w);
        ((__half2*)Ah)[i * 2]     = h0;
        ((__half2*)Ah)[i * 2 + 1] = h1;
    }
}

// W [K,N] fp32 -> W^T [N,K] single fp16
__global__ void quantWT_f16_kernel(const float* __restrict__ W,
                                   __half* __restrict__ WT, int K, int N) {
    __shared__ float tile[32][33];
    int k0 = blockIdx.y * 32, n0 = blockIdx.x * 32;
    int tx = threadIdx.x & 31, ty = threadIdx.x >> 5;
    for (int r = ty; r < 32; r += 8)
        tile[r][tx] = W[(size_t)(k0 + r) * N + n0 + tx];
    __syncthreads();
    for (int r = ty; r < 32; r += 8)
        WT[(size_t)(n0 + r) * K + k0 + tx] = __float2half(tile[tx][r]);
}

// ---------------------------------------------------------------------------
// fp16 GEMM: C = A @ WT^T. W single fp16.
// APAIR=1: A is an exact fp16 hi/lo pair (2 MMAs/k16). APAIR=0: A single (1 MMA).
// MODE 0 (QKV, APAIR=0): Q cols -> fp16 pair (pre-scaled); K/V cols -> single.
// MODE 1 (out-proj, APAIR=1): fp32 + bias.
// ---------------------------------------------------------------------------
#define KC        32
#define TROW      80
#define TILE_B    (128 * TROW)          // 10240

template <int MODE, int APAIR>
__global__ __launch_bounds__(256, 2)
void f16_gemm_kernel(const __half* __restrict__ Ah, const __half* __restrict__ Al,
                     const __half* __restrict__ WT,
                     const float* __restrict__ bias, float* __restrict__ C,
                     __half* __restrict__ Ch, __half* __restrict__ Cl,
                     int M, int N, int K) {
    constexpr int NTILES  = APAIR ? 3 : 2;          // [Ah, (Al), B]
    constexpr int STAGE_B = NTILES * TILE_B;
    extern __shared__ char smem[];
    const uint32_t sb = smem_u32(smem);
    const int tid   = threadIdx.x;
    const int lane  = tid & 31;
    const int wid   = tid >> 5;
    const int warpM = wid & 3;
    const int warpN = wid >> 2;
    const int m0 = blockIdx.y * 128;
    const int n0 = blockIdx.x * 128;
    const int nch = K / KC;

    auto load_stage = [&](int kc0, int s) {
        const uint32_t stg = sb + s * STAGE_B;
#pragma unroll
        for (int t = 0; t < NTILES * 2; t++) {
            const int id   = tid + t * 256;
            const int tile = id >> 9;
            const int rem  = id & 511;
            const int row  = rem >> 2;
            const int q    = rem & 3;
            const __half* src;
            if (tile == 0)                 src = Ah + (size_t)(m0 + row) * K + kc0 + q * 8;
            else if (APAIR && tile == 1)   src = Al + (size_t)(m0 + row) * K + kc0 + q * 8;
            else                           src = WT + (size_t)(n0 + row) * K + kc0 + q * 8;
            CP_ASYNC16(stg + tile * TILE_B + row * TROW + q * 16, src);
        }
        CP_COMMIT();
    };

    float c[2][8][4];
#pragma unroll
    for (int i = 0; i < 2; i++)
#pragma unroll
        for (int j = 0; j < 8; j++)
#pragma unroll
            for (int r = 0; r < 4; r++) c[i][j][r] = 0.0f;

    const int arow = warpM * 32 + (lane & 15);
    const int acol = (lane >> 4) * 8;
    const int brow = warpN * 64 + (lane & 7) + ((lane >> 4) << 3);
    const int bck  = ((lane >> 3) & 1) * 8;

    load_stage(0, 0);
    load_stage(KC, 1);

    for (int ch = 0; ch < nch; ch++) {
        CP_WAIT(1);
        __syncthreads();

        const uint32_t stg = sb + (ch & 1) * STAGE_B;
        const uint32_t ahb = stg;
        const uint32_t alb = stg + TILE_B;                       // valid iff APAIR
        const uint32_t bbb = stg + (NTILES - 1) * TILE_B;

#pragma unroll
        for (int k16 = 0; k16 < 2; k16++) {
            uint32_t fah[2][4], fal[2][4];
#pragma unroll
            for (int mt = 0; mt < 2; mt++) {
                uint32_t off = (uint32_t)(arow + mt * 16) * TROW + (k16 * 16 + acol) * 2;
                ldsm_x4(fah[mt][0], fah[mt][1], fah[mt][2], fah[mt][3], ahb + off);
                if (APAIR)
                    ldsm_x4(fal[mt][0], fal[mt][1], fal[mt][2], fal[mt][3], alb + off);
            }
#pragma unroll
            for (int np = 0; np < 4; np++) {
                uint32_t bf[4];
                uint32_t off = (uint32_t)(brow + np * 16) * TROW + (k16 * 16 + bck) * 2;
                ldsm_x4(bf[0], bf[1], bf[2], bf[3], bbb + off);
#pragma unroll
                for (int mt = 0; mt < 2; mt++)
#pragma unroll
                    for (int half = 0; half < 2; half++) {
                        float* acc = c[mt][np * 2 + half];
                        mma_f16(acc, fah[mt], bf[half * 2], bf[half * 2 + 1]);
                        if (APAIR)
                            mma_f16(acc, fal[mt], bf[half * 2], bf[half * 2 + 1]);
                    }
            }
        }
        __syncthreads();
        if (ch + 2 < nch) load_stage((ch + 2) * KC, ch & 1);
        else CP_COMMIT();   // placeholder group: keeps CP_WAIT(1) accounting exact
    }

    const int g   = lane >> 2;
    const int tig = lane & 3;
#pragma unroll
    for (int mt = 0; mt < 2; mt++) {
        const int row = m0 + warpM * 32 + mt * 16 + g;
#pragma unroll
        for (int nt = 0; nt < 8; nt++) {
            const int col = n0 + warpN * 64 + nt * 8 + tig * 2;
            if (MODE == 1) {
                float2 v0 = make_float2(c[mt][nt][0] + bias[col], c[mt][nt][1] + bias[col + 1]);
                float2 v1 = make_float2(c[mt][nt][2] + bias[col], c[mt][nt][3] + bias[col + 1]);
                *(float2*)(C + (size_t)row * N + col)       = v0;
                *(float2*)(C + (size_t)(row + 8) * N + col) = v1;
            } else {
                if (col < HID) {
                    uint32_t hp, lp;
                    split_pack_h(c[mt][nt][0] * QSF, c[mt][nt][1] * QSF, hp, lp);
                    *(uint32_t*)(Ch + (size_t)row * N + col) = hp;
                    *(uint32_t*)(Cl + (size_t)row * N + col) = lp;
                    split_pack_h(c[mt][nt][2] * QSF, c[mt][nt][3] * QSF, hp, lp);
                    *(uint32_t*)(Ch + (size_t)(row + 8) * N + col) = hp;
                    *(uint32_t*)(Cl + (size_t)(row + 8) * N + col) = lp;
                } else {
                    __half2 v0; v0.x = __float2half(c[mt][nt][0]); v0.y = __float2half(c[mt][nt][1]);
                    __half2 v1; v1.x = __float2half(c[mt][nt][2]); v1.y = __float2half(c[mt][nt][3]);
                    *(__half2*)(Ch + (size_t)row * N + col)       = v0;
                    *(__half2*)(Ch + (size_t)(row + 8) * N + col) = v1;
                }
            }
        }
    }
}

#define QKV_SMEM (2 * 2 * TILE_B)       // 40960
#define OUT_SMEM (2 * 3 * TILE_B)       // 61440

// ---------------------------------------------------------------------------
// fp16 flash attention: Q fp16 pair (smem-staged), K/V single fp16.
// QK: 2 MMAs/k16; PV: 2 MMAs/k16. Occupancy 2; smem 73.9 KB. (R11-proven.)
// ---------------------------------------------------------------------------
#define ATROW 144
#define ATILE (64 * ATROW)                 // 9216
#define ASTAGE (2 * ATILE)                 // 18432: K | V
#define QTILE (128 * ATROW)                // 18432
#define ATT_SMEM (2 * ASTAGE + 2 * QTILE + 160)   // 73888

__global__ __launch_bounds__(256, 2)
void mma_attn_kernel(const __half* __restrict__ Qh, const __half* __restrict__ Ql,
                     __half* __restrict__ Oh, __half* __restrict__ Ol) {
    extern __shared__ char sm[];
    const uint32_t sb  = smem_u32(sm);
    const uint32_t qsm = sb + 2 * ASTAGE;
    int* list = (int*)(sm + 2 * ASTAGE + 2 * QTILE);

    const int tid  = threadIdx.x;
    const int lane = tid & 31;
    const int w    = tid >> 5;
    const int b    = blockIdx.z;
    const int h    = blockIdx.y;
    const int q0   = blockIdx.x * 128;
    const int g    = lane >> 2;
    const int tq   = lane & 3;

    if (w == 0) {
        unsigned long long mb = g_mbits[b * 32 + lane];
        unsigned act = __ballot_sync(0xffffffffu, mb != 0ull);
        int pos = __popc(act & ((1u << lane) - 1));
        if (mb != 0ull) list[pos] = lane;
        if (lane == 0) list[32] = __popc(act);
    }
    __syncthreads();
    const int ncnt = list[32];

    // stage Q tile (128 rows x 64 fp16, hi+lo) into smem
    {
        const int tok0 = b * SEQ + q0;
#pragma unroll
        for (int t = 0; t < 8; t++) {
            const int id  = tid + t * 256;
            const int arr = id >> 10;             // 0:Qh 1:Ql
            const int rem = id & 1023;
            const int r   = rem >> 3;
            const int seg = rem & 7;
            const size_t go = (size_t)(tok0 + r) * QKV3 + h * HD + seg * 8;
            const __half* src = arr ? (Ql + go) : (Qh + go);
            CP_ASYNC16(qsm + arr * QTILE + r * ATROW + seg * 16, src);
        }
        CP_COMMIT();
    }

    auto load_tile = [&](int kt, int stg) {
        const int tok0 = b * SEQ + kt * 64;
        const uint32_t base = sb + stg * ASTAGE;
#pragma unroll
        for (int t = 0; t < 4; t++) {
            const int id  = tid + t * 256;
            const int arr = id >> 9;              // 0:K 1:V
            const int rem = id & 511;
            const int r   = rem >> 3;
            const int q   = rem & 7;
            const size_t go = (size_t)(tok0 + r) * QKV3 + h * HD + q * 8;
            const __half* src = arr ? (Qh + go + 2 * HID) : (Qh + go + HID);
            CP_ASYNC16(base + arr * ATILE + r * ATROW + q * 16, src);
        }
        CP_COMMIT();
    };

    float o[8][4];
#pragma unroll
    for (int j = 0; j < 8; j++)
#pragma unroll
        for (int r = 0; r < 4; r++) o[j][r] = 0.0f;
    float mi[2] = {-1e30f, -1e30f}, li[2] = {0.0f, 0.0f};

    if (ncnt > 0) load_tile(list[0], 0);

    const uint32_t qrowoff = qsm + (uint32_t)(w * 16 + (lane & 15)) * ATROW
                           + ((lane >> 4) << 3) * 2;

    for (int it = 0; it < ncnt; it++) {
        if (it + 1 < ncnt) { load_tile(list[it + 1], (it + 1) & 1); CP_WAIT(1); }
        else CP_WAIT(0);
        __syncthreads();
        const uint32_t st = sb + (it & 1) * ASTAGE;
        const int kt = list[it];

        float s[8][4];
#pragma unroll
        for (int j = 0; j < 8; j++)
#pragma unroll
            for (int r = 0; r < 4; r++) s[j][r] = 0.0f;

#pragma unroll
        for (int kd = 0; kd < 4; kd++) {
            uint32_t qh4[4], ql4[4];
            const uint32_t qoff = qrowoff + kd * 32;
            ldsm_x4(qh4[0], qh4[1], qh4[2], qh4[3], qoff);
            ldsm_x4(ql4[0], ql4[1], ql4[2], ql4[3], qoff + QTILE);
#pragma unroll
            for (int kg = 0; kg < 4; kg++) {
                uint32_t kh[4];
                const uint32_t off = st + (uint32_t)(kg * 16 + (lane & 7) + ((lane >> 4) << 3)) * ATROW
                                        + (kd * 16 + ((lane >> 3) & 1) * 8) * 2;
                ldsm_x4(kh[0], kh[1], kh[2], kh[3], off);
                mma_f16(s[kg * 2],     qh4, kh[0], kh[1]);
                mma_f16(s[kg * 2],     ql4, kh[0], kh[1]);
                mma_f16(s[kg * 2 + 1], qh4, kh[2], kh[3]);
                mma_f16(s[kg * 2 + 1], ql4, kh[2], kh[3]);
            }
        }

        const unsigned long long mb = g_mbits[b * 32 + kt];
        if (mb != ~0ull) {
#pragma unroll
            for (int nf = 0; nf < 8; nf++) {
                const int c0 = nf * 8 + tq * 2;
                if (!((mb >> c0) & 1))       { s[nf][0] = -1e30f; s[nf][2] = -1e30f; }
                if (!((mb >> (c0 + 1)) & 1)) { s[nf][1] = -1e30f; s[nf][3] = -1e30f; }
            }
        }

#pragma unroll
        for (int r = 0; r < 2; r++) {
            float mx = -1e30f;
#pragma unroll
            for (int nf = 0; nf < 8; nf++)
                mx = fmaxf(mx, fmaxf(s[nf][2 * r], s[nf][2 * r + 1]));
            mx = fmaxf(mx, __shfl_xor_sync(0xffffffffu, mx, 1));
            mx = fmaxf(mx, __shfl_xor_sync(0xffffffffu, mx, 2));
            const float mnew = fmaxf(mi[r], mx);
            const float al = fexp2(mi[r] - mnew);
            mi[r] = mnew;
            li[r] *= al;
#pragma unroll
            for (int nf = 0; nf < 8; nf++) { o[nf][2 * r] *= al; o[nf][2 * r + 1] *= al; }
            float ls = 0.0f;
#pragma unroll
            for (int nf = 0; nf < 8; nf++) {
                const float p0 = fexp2(s[nf][2 * r] - mnew);
                const float p1 = fexp2(s[nf][2 * r + 1] - mnew);
                ls += p0 + p1;
                s[nf][2 * r] = p0;
                s[nf][2 * r + 1] = p1;
            }
            ls += __shfl_xor_sync(0xffffffffu, ls, 1);
            ls += __shfl_xor_sync(0xffffffffu, ls, 2);
            li[r] += ls;
        }

        uint32_t pah[4][4], pal[4][4];
#pragma unroll
        for (int ks = 0; ks < 4; ks++) {
            split_pack_h(s[2 * ks][0],     s[2 * ks][1],     pah[ks][0], pal[ks][0]);
            split_pack_h(s[2 * ks][2],     s[2 * ks][3],     pah[ks][1], pal[ks][1]);
            split_pack_h(s[2 * ks + 1][0], s[2 * ks + 1][1], pah[ks][2], pal[ks][2]);
            split_pack_h(s[2 * ks + 1][2], s[2 * ks + 1][3], pah[ks][3], pal[ks][3]);
        }

#pragma unroll
        for (int ks = 0; ks < 4; ks++) {
#pragma unroll
            for (int dg = 0; dg < 4; dg++) {
                uint32_t vh[4];
                const uint32_t off = st + ATILE
                                   + (uint32_t)(ks * 16 + (lane & 15)) * ATROW
                                   + (dg * 16 + ((lane >> 4) << 3)) * 2;
                ldsm_x4t(vh[0], vh[1], vh[2], vh[3], off);
                mma_f16(o[dg * 2],     pah[ks], vh[0], vh[1]);
                mma_f16(o[dg * 2],     pal[ks], vh[0], vh[1]);
                mma_f16(o[dg * 2 + 1], pah[ks], vh[2], vh[3]);
                mma_f16(o[dg * 2 + 1], pal[ks], vh[2], vh[3]);
            }
        }
        __syncthreads();
    }

    // epilogue: normalize, split to fp16 hi/lo (out-proj input format)
#pragma unroll
    for (int r = 0; r < 2; r++) {
        const float inv = 1.0f / li[r];
        const size_t ob = (size_t)(b * SEQ + q0 + w * 16 + g + r * 8) * HID + h * HD;
#pragma unroll
        for (int nf = 0; nf < 8; nf++) {
            uint32_t hp, lp;
            split_pack_h(o[nf][2 * r] * inv, o[nf][2 * r + 1] * inv, hp, lp);
            *(uint32_t*)(Oh + ob + nf * 8 + tq * 2) = hp;
            *(uint32_t*)(Ol + ob + nf * 8 + tq * 2) = lp;
        }
    }
}

// ---------------------------------------------------------------------------
// Launch
// ---------------------------------------------------------------------------
extern "C" void kernel_launch(void* const* d_in, const int* in_sizes, int n_in,
                              void* d_out, int out_size) {
    const float* hidden = (const float*)d_in[0];
    const void*  maskp  = d_in[1];
    const float* Wqkv   = (const float*)d_in[2];
    const float* Wout   = (const float*)d_in[3];
    const float* bout   = (const float*)d_in[4];
    float*       out    = (float*)d_out;

    void *p_qh, *p_ql, *p_ah, *p_al, *p_wq, *p_wo;
    cudaGetSymbolAddress(&p_qh, g_qh);
    cudaGetSymbolAddress(&p_ql, g_ql);
    cudaGetSymbolAddress(&p_ah, g_ah);
    cudaGetSymbolAddress(&p_al, g_al);
    cudaGetSymbolAddress(&p_wq, g_wq);
    cudaGetSymbolAddress(&p_wo, g_wo);

    cudaFuncSetAttribute((const void*)f16_gemm_kernel<0, 0>,
                         cudaFuncAttributeMaxDynamicSharedMemorySize, QKV_SMEM);
    cudaFuncSetAttribute((const void*)f16_gemm_kernel<1, 1>,
                         cudaFuncAttributeMaxDynamicSharedMemorySize, OUT_SMEM);
    cudaFuncSetAttribute(mma_attn_kernel,
                         cudaFuncAttributeMaxDynamicSharedMemorySize, ATT_SMEM);

    // 1. mask canonicalize + tile bitmasks
    mask_convert_kernel<<<1, 256>>>(maskp, BATCH * SEQ);

    // 2. fp16 prep: hidden -> single fp16; weights -> single fp16 transposed
    convA_f16_kernel<<<592, 256>>>(hidden, (__half*)p_ah, MROWS * HID / 4);
    quantWT_f16_kernel<<<dim3(QKV3 / 32, HID / 32), 256>>>(Wqkv, (__half*)p_wq, HID, QKV3);
    quantWT_f16_kernel<<<dim3(HID / 32, HID / 32), 256>>>(Wout, (__half*)p_wo, HID, HID);

    // 3. QKV projection (fp16 single-A, 1 MMA/k16) -> Q pair + K/V single
    f16_gemm_kernel<0, 0><<<dim3(QKV3 / 128, MROWS / 128), 256, QKV_SMEM>>>(
        (const __half*)p_ah, nullptr, (const __half*)p_wq,
        nullptr, nullptr, (__half*)p_qh, (__half*)p_ql,
        MROWS, QKV3, HID);

    // 4. fp16 flash attention -> fp16 hi/lo attention output
    mma_attn_kernel<<<dim3(SEQ / 128, NH, BATCH), 256, ATT_SMEM>>>(
        (const __half*)p_qh, (const __half*)p_ql,
        (__half*)p_ah, (__half*)p_al);

    // 5. output projection (fp16 pair-A, 2 MMAs/k16, +bias)
    f16_gemm_kernel<1, 1><<<dim3(HID / 128, MROWS / 128), 256, OUT_SMEM>>>(
        (const __half*)p_ah, (const __half*)p_al, (const __half*)p_wo,
        bout, out, nullptr, nullptr, MROWS, HID, HID);
}

// round 13
// speedup vs baseline: 3.5339x; 1.2185x over previous
#include <cuda_runtime.h>
#include <cuda_bf16.h>
#include <cuda_fp16.h>
#include <cstdint>

#define BATCH 4
#define SEQ   2048
#define NH    16
#define HD    64
#define HID   1024
#define QKV3  3072
#define MROWS (BATCH * SEQ)        // 8192

// 0.125 * log2(e): folded into Q at the QKV epilogue (softmax in base-2 domain)
#define QSF 0.18033688011112042f

// ---------------------------------------------------------------------------
// Scratch (static device globals — allocation-free per harness rules)
// ---------------------------------------------------------------------------
__device__ __half        g_qkv[MROWS * QKV3];          // Q (pre-scaled) | K | V, all single fp16
__device__ int           g_mask[BATCH * SEQ];
__device__ unsigned long long g_mbits[BATCH * 32];     // 64-key tile bitmasks
__device__ __half        g_ah[MROWS * HID];            // activation hi fp16 (hidden single, then attn-out hi)
__device__ __half        g_al[MROWS * HID];            // activation lo fp16 (attn-out lo)
__device__ __half        g_wq[QKV3 * HID];             // Wqkv^T single fp16 [N,K]
__device__ __half        g_wo[HID * HID];              // Wout^T single fp16 [N,K]

// ---------------------------------------------------------------------------
// PTX helpers (arch-portable sm_80+; tcgen05 unavailable via compute_103;
// s8 mma.sync measured ~4-5x worse rt than HMMA on sm_103 — do not use)
// ---------------------------------------------------------------------------
__device__ __forceinline__ uint32_t smem_u32(const void* p) {
    uint32_t a;
    asm("{ .reg .u64 t; cvta.to.shared.u64 t, %1; cvt.u32.u64 %0, t; }" : "=r"(a) : "l"(p));
    return a;
}
__device__ __forceinline__ void ldsm_x4(uint32_t& r0, uint32_t& r1, uint32_t& r2, uint32_t& r3,
                                        uint32_t addr) {
    asm volatile("ldmatrix.sync.aligned.m8n8.x4.shared.b16 {%0,%1,%2,%3}, [%4];"
                 : "=r"(r0), "=r"(r1), "=r"(r2), "=r"(r3) : "r"(addr));
}
__device__ __forceinline__ void ldsm_x4t(uint32_t& r0, uint32_t& r1, uint32_t& r2, uint32_t& r3,
                                         uint32_t addr) {
    asm volatile("ldmatrix.sync.aligned.m8n8.x4.trans.shared.b16 {%0,%1,%2,%3}, [%4];"
                 : "=r"(r0), "=r"(r1), "=r"(r2), "=r"(r3) : "r"(addr));
}
__device__ __forceinline__ void mma_f16(float* c, const uint32_t* a, uint32_t b0, uint32_t b1) {
    asm volatile(
        "mma.sync.aligned.m16n8k16.row.col.f32.f16.f16.f32 "
        "{%0,%1,%2,%3}, {%4,%5,%6,%7}, {%8,%9}, {%0,%1,%2,%3};"
        : "+f"(c[0]), "+f"(c[1]), "+f"(c[2]), "+f"(c[3])
        : "r"(a[0]), "r"(a[1]), "r"(a[2]), "r"(a[3]), "r"(b0), "r"(b1));
}
__device__ __forceinline__ float fexp2(float x) {
    float y; asm("ex2.approx.f32 %0, %1;" : "=f"(y) : "f"(x)); return y;
}
// fp16 hi/lo split-pack
__device__ __forceinline__ void split_pack_h(float x, float y, uint32_t& hp, uint32_t& lp) {
    __half2 hv, lv;
    hv.x = __float2half(x);
    hv.y = __float2half(y);
    lv.x = __float2half(x - __half2float(hv.x));
    lv.y = __float2half(y - __half2float(hv.y));
    hp = *(uint32_t*)&hv;
    lp = *(uint32_t*)&lv;
}
// fp16 single pack
__device__ __forceinline__ uint32_t pack_h2(float x, float y) {
    __half2 v; v.x = __float2half(x); v.y = __float2half(y);
    return *(uint32_t*)&v;
}
#define CP_ASYNC16(dst, src) \
    asm volatile("cp.async.cg.shared.global [%0], [%1], 16;" :: "r"(dst), "l"(src))
#define CP_COMMIT() asm volatile("cp.async.commit_group;" ::: "memory")
#define CP_WAIT(n)  asm volatile("cp.async.wait_group %0;" :: "n"(n) : "memory")

// ---------------------------------------------------------------------------
// Mask canonicalizer + per-64-key-tile bitmasks
// ---------------------------------------------------------------------------
__global__ void mask_convert_kernel(const void* __restrict__ raw, int n) {
    __shared__ int mode;
    if (threadIdx.x == 0) {
        unsigned w0 = ((const unsigned*)raw)[0];
        if (w0 == 1u || w0 == 0u)    mode = 0;  // int32
        else if (w0 == 0x3F800000u)  mode = 1;  // float32
        else if (w0 == 0x01010101u)  mode = 2;  // uint8
        else if (w0 == 0x3F803F80u)  mode = 3;  // bf16 pair
        else                          mode = 2;
    }
    __syncthreads();
    int m = mode;
    for (int i = threadIdx.x; i < n; i += blockDim.x) {
        int v;
        if (m == 0)      v = (((const int*)raw)[i] != 0);
        else if (m == 1) v = (((const float*)raw)[i] != 0.0f);
        else if (m == 2) v = (((const unsigned char*)raw)[i] != 0);
        else { unsigned short h = ((const unsigned short*)raw)[i]; v = ((h & 0x7FFF) != 0); }
        g_mask[i] = v;
    }
    __syncthreads();
    for (int t = threadIdx.x; t < BATCH * 32; t += blockDim.x) {
        int b = t >> 5, kt = t & 31;
        unsigned long long mb = 0ull;
        for (int j = 0; j < 64; j++)
            mb |= ((unsigned long long)(g_mask[b * SEQ + kt * 64 + j] & 1)) << j;
        g_mbits[t] = mb;
    }
}

// ---------------------------------------------------------------------------
// fp16 prep kernels
// ---------------------------------------------------------------------------
__global__ void convA_f16_kernel(const float* __restrict__ A,
                                 __half* __restrict__ Ah, int n4) {
    int stride = gridDim.x * blockDim.x;
    for (int i = blockIdx.x * blockDim.x + threadIdx.x; i < n4; i += stride) {
        float4 v = ((const float4*)A)[i];
        ((uint32_t*)Ah)[i * 2]     = pack_h2(v.x, v.y);
        ((uint32_t*)Ah)[i * 2 + 1] = pack_h2(v.z, v.w);
    }
}

// W [K,N] fp32 -> W^T [N,K] single fp16
__global__ void quantWT_f16_kernel(const float* __restrict__ W,
                                   __half* __restrict__ WT, int K, int N) {
    __shared__ float tile[32][33];
    int k0 = blockIdx.y * 32, n0 = blockIdx.x * 32;
    int tx = threadIdx.x & 31, ty = threadIdx.x >> 5;
    for (int r = ty; r < 32; r += 8)
        tile[r][tx] = W[(size_t)(k0 + r) * N + n0 + tx];
    __syncthreads();
    for (int r = ty; r < 32; r += 8)
        WT[(size_t)(n0 + r) * K + k0 + tx] = __float2half(tile[tx][r]);
}

// ---------------------------------------------------------------------------
// fp16 GEMM: C = A @ WT^T. W single fp16.
// APAIR=1: A exact fp16 pair (2 MMAs/k16). APAIR=0: A single (1 MMA/k16).
// MODE 0 (QKV, APAIR=0): all cols single fp16; Q cols pre-scaled by QSF.
// MODE 1 (out-proj, APAIR=1): fp32 + bias.
// ---------------------------------------------------------------------------
#define KC        32
#define TROW      80
#define TILE_B    (128 * TROW)          // 10240

template <int MODE, int APAIR>
__global__ __launch_bounds__(256, 2)
void f16_gemm_kernel(const __half* __restrict__ Ah, const __half* __restrict__ Al,
                     const __half* __restrict__ WT,
                     const float* __restrict__ bias, float* __restrict__ C,
                     __half* __restrict__ Ch,
                     int M, int N, int K) {
    constexpr int NTILES  = APAIR ? 3 : 2;          // [Ah, (Al), B]
    constexpr int STAGE_B = NTILES * TILE_B;
    extern __shared__ char smem[];
    const uint32_t sb = smem_u32(smem);
    const int tid   = threadIdx.x;
    const int lane  = tid & 31;
    const int wid   = tid >> 5;
    const int warpM = wid & 3;
    const int warpN = wid >> 2;
    const int m0 = blockIdx.y * 128;
    const int n0 = blockIdx.x * 128;
    const int nch = K / KC;

    auto load_stage = [&](int kc0, int s) {
        const uint32_t stg = sb + s * STAGE_B;
#pragma unroll
        for (int t = 0; t < NTILES * 2; t++) {
            const int id   = tid + t * 256;
            const int tile = id >> 9;
            const int rem  = id & 511;
            const int row  = rem >> 2;
            const int q    = rem & 3;
            const __half* src;
            if (tile == 0)                 src = Ah + (size_t)(m0 + row) * K + kc0 + q * 8;
            else if (APAIR && tile == 1)   src = Al + (size_t)(m0 + row) * K + kc0 + q * 8;
            else                           src = WT + (size_t)(n0 + row) * K + kc0 + q * 8;
            CP_ASYNC16(stg + tile * TILE_B + row * TROW + q * 16, src);
        }
        CP_COMMIT();
    };

    float c[2][8][4];
#pragma unroll
    for (int i = 0; i < 2; i++)
#pragma unroll
        for (int j = 0; j < 8; j++)
#pragma unroll
            for (int r = 0; r < 4; r++) c[i][j][r] = 0.0f;

    const int arow = warpM * 32 + (lane & 15);
    const int acol = (lane >> 4) * 8;
    const int brow = warpN * 64 + (lane & 7) + ((lane >> 4) << 3);
    const int bck  = ((lane >> 3) & 1) * 8;

    load_stage(0, 0);
    load_stage(KC, 1);

    for (int ch = 0; ch < nch; ch++) {
        CP_WAIT(1);
        __syncthreads();

        const uint32_t stg = sb + (ch & 1) * STAGE_B;
        const uint32_t ahb = stg;
        const uint32_t alb = stg + TILE_B;                       // valid iff APAIR
        const uint32_t bbb = stg + (NTILES - 1) * TILE_B;

#pragma unroll
        for (int k16 = 0; k16 < 2; k16++) {
            uint32_t fah[2][4], fal[2][4];
#pragma unroll
            for (int mt = 0; mt < 2; mt++) {
                uint32_t off = (uint32_t)(arow + mt * 16) * TROW + (k16 * 16 + acol) * 2;
                ldsm_x4(fah[mt][0], fah[mt][1], fah[mt][2], fah[mt][3], ahb + off);
                if (APAIR)
                    ldsm_x4(fal[mt][0], fal[mt][1], fal[mt][2], fal[mt][3], alb + off);
            }
#pragma unroll
            for (int np = 0; np < 4; np++) {
                uint32_t bf[4];
                uint32_t off = (uint32_t)(brow + np * 16) * TROW + (k16 * 16 + bck) * 2;
                ldsm_x4(bf[0], bf[1], bf[2], bf[3], bbb + off);
#pragma unroll
                for (int mt = 0; mt < 2; mt++)
#pragma unroll
                    for (int half = 0; half < 2; half++) {
                        float* acc = c[mt][np * 2 + half];
                        mma_f16(acc, fah[mt], bf[half * 2], bf[half * 2 + 1]);
                        if (APAIR)
                            mma_f16(acc, fal[mt], bf[half * 2], bf[half * 2 + 1]);
                    }
            }
        }
        __syncthreads();
        if (ch + 2 < nch) load_stage((ch + 2) * KC, ch & 1);
        else CP_COMMIT();   // placeholder group: keeps CP_WAIT(1) accounting exact
    }

    const int g   = lane >> 2;
    const int tig = lane & 3;
#pragma unroll
    for (int mt = 0; mt < 2; mt++) {
        const int row = m0 + warpM * 32 + mt * 16 + g;
#pragma unroll
        for (int nt = 0; nt < 8; nt++) {
            const int col = n0 + warpN * 64 + nt * 8 + tig * 2;
            if (MODE == 1) {
                float2 v0 = make_float2(c[mt][nt][0] + bias[col], c[mt][nt][1] + bias[col + 1]);
                float2 v1 = make_float2(c[mt][nt][2] + bias[col], c[mt][nt][3] + bias[col + 1]);
                *(float2*)(C + (size_t)row * N + col)       = v0;
                *(float2*)(C + (size_t)(row + 8) * N + col) = v1;
            } else {
                const float sc = (col < HID) ? QSF : 1.0f;    // Q pre-scale
                *(uint32_t*)(Ch + (size_t)row * N + col) =
                    pack_h2(c[mt][nt][0] * sc, c[mt][nt][1] * sc);
                *(uint32_t*)(Ch + (size_t)(row + 8) * N + col) =
                    pack_h2(c[mt][nt][2] * sc, c[mt][nt][3] * sc);
            }
        }
    }
}

#define QKV_SMEM (2 * 2 * TILE_B)       // 40960
#define OUT_SMEM (2 * 3 * TILE_B)       // 61440

// ---------------------------------------------------------------------------
// fp16 flash attention: Q, K, V, P all single fp16.
// QK: 1 MMA/k16; PV: 1 MMA/k16. Occupancy 2; smem 55.5 KB.
// ---------------------------------------------------------------------------
#define ATROW 144
#define ATILE (64 * ATROW)                 // 9216
#define ASTAGE (2 * ATILE)                 // 18432: K | V
#define QTILE (128 * ATROW)                // 18432
#define ATT_SMEM (2 * ASTAGE + QTILE + 160)   // 55456

__global__ __launch_bounds__(256, 2)
void mma_attn_kernel(const __half* __restrict__ QKV,
                     __half* __restrict__ Oh, __half* __restrict__ Ol) {
    extern __shared__ char sm[];
    const uint32_t sb  = smem_u32(sm);
    const uint32_t qsm = sb + 2 * ASTAGE;
    int* list = (int*)(sm + 2 * ASTAGE + QTILE);

    const int tid  = threadIdx.x;
    const int lane = tid & 31;
    const int w    = tid >> 5;
    const int b    = blockIdx.z;
    const int h    = blockIdx.y;
    const int q0   = blockIdx.x * 128;
    const int g    = lane >> 2;
    const int tq   = lane & 3;

    if (w == 0) {
        unsigned long long mb = g_mbits[b * 32 + lane];
        unsigned act = __ballot_sync(0xffffffffu, mb != 0ull);
        int pos = __popc(act & ((1u << lane) - 1));
        if (mb != 0ull) list[pos] = lane;
        if (lane == 0) list[32] = __popc(act);
    }
    __syncthreads();
    const int ncnt = list[32];

    // stage Q tile (128 rows x 64 fp16, single) into smem
    {
        const int tok0 = b * SEQ + q0;
#pragma unroll
        for (int t = 0; t < 4; t++) {
            const int id  = tid + t * 256;
            const int r   = id >> 3;
            const int seg = id & 7;
            const size_t go = (size_t)(tok0 + r) * QKV3 + h * HD + seg * 8;
            CP_ASYNC16(qsm + r * ATROW + seg * 16, QKV + go);
        }
        CP_COMMIT();
    }

    auto load_tile = [&](int kt, int stg) {
        const int tok0 = b * SEQ + kt * 64;
        const uint32_t base = sb + stg * ASTAGE;
#pragma unroll
        for (int t = 0; t < 4; t++) {
            const int id  = tid + t * 256;
            const int arr = id >> 9;              // 0:K 1:V
            const int rem = id & 511;
            const int r   = rem >> 3;
            const int q   = rem & 7;
            const size_t go = (size_t)(tok0 + r) * QKV3 + h * HD + q * 8;
            const __half* src = arr ? (QKV + go + 2 * HID) : (QKV + go + HID);
            CP_ASYNC16(base + arr * ATILE + r * ATROW + q * 16, src);
        }
        CP_COMMIT();
    };

    float o[8][4];
#pragma unroll
    for (int j = 0; j < 8; j++)
#pragma unroll
        for (int r = 0; r < 4; r++) o[j][r] = 0.0f;
    float mi[2] = {-1e30f, -1e30f}, li[2] = {0.0f, 0.0f};

    if (ncnt > 0) load_tile(list[0], 0);

    const uint32_t qrowoff = qsm + (uint32_t)(w * 16 + (lane & 15)) * ATROW
                           + ((lane >> 4) << 3) * 2;

    for (int it = 0; it < ncnt; it++) {
        if (it + 1 < ncnt) { load_tile(list[it + 1], (it + 1) & 1); CP_WAIT(1); }
        else CP_WAIT(0);
        __syncthreads();
        const uint32_t st = sb + (it & 1) * ASTAGE;
        const int kt = list[it];

        // ---- S = Q @ K^T (single fp16: 1 MMA per fragment) ----
        float s[8][4];
#pragma unroll
        for (int j = 0; j < 8; j++)
#pragma unroll
            for (int r = 0; r < 4; r++) s[j][r] = 0.0f;

#pragma unroll
        for (int kd = 0; kd < 4; kd++) {
            uint32_t qh4[4];
            ldsm_x4(qh4[0], qh4[1], qh4[2], qh4[3], qrowoff + kd * 32);
#pragma unroll
            for (int kg = 0; kg < 4; kg++) {
                uint32_t kh[4];
                const uint32_t off = st + (uint32_t)(kg * 16 + (lane & 7) + ((lane >> 4) << 3)) * ATROW
                                        + (kd * 16 + ((lane >> 3) & 1) * 8) * 2;
                ldsm_x4(kh[0], kh[1], kh[2], kh[3], off);
                mma_f16(s[kg * 2],     qh4, kh[0], kh[1]);
                mma_f16(s[kg * 2 + 1], qh4, kh[2], kh[3]);
            }
        }

        // ---- key-padding mask ----
        const unsigned long long mb = g_mbits[b * 32 + kt];
        if (mb != ~0ull) {
#pragma unroll
            for (int nf = 0; nf < 8; nf++) {
                const int c0 = nf * 8 + tq * 2;
                if (!((mb >> c0) & 1))       { s[nf][0] = -1e30f; s[nf][2] = -1e30f; }
                if (!((mb >> (c0 + 1)) & 1)) { s[nf][1] = -1e30f; s[nf][3] = -1e30f; }
            }
        }

        // ---- online softmax (base-2; Q pre-scaled) ----
#pragma unroll
        for (int r = 0; r < 2; r++) {
            float mx = -1e30f;
#pragma unroll
            for (int nf = 0; nf < 8; nf++)
                mx = fmaxf(mx, fmaxf(s[nf][2 * r], s[nf][2 * r + 1]));
            mx = fmaxf(mx, __shfl_xor_sync(0xffffffffu, mx, 1));
            mx = fmaxf(mx, __shfl_xor_sync(0xffffffffu, mx, 2));
            const float mnew = fmaxf(mi[r], mx);
            const float al = fexp2(mi[r] - mnew);
            mi[r] = mnew;
            li[r] *= al;
#pragma unroll
            for (int nf = 0; nf < 8; nf++) { o[nf][2 * r] *= al; o[nf][2 * r + 1] *= al; }
            float ls = 0.0f;
#pragma unroll
            for (int nf = 0; nf < 8; nf++) {
                const float p0 = fexp2(s[nf][2 * r] - mnew);
                const float p1 = fexp2(s[nf][2 * r + 1] - mnew);
                ls += p0 + p1;
                s[nf][2 * r] = p0;
                s[nf][2 * r + 1] = p1;
            }
            ls += __shfl_xor_sync(0xffffffffu, ls, 1);
            ls += __shfl_xor_sync(0xffffffffu, ls, 2);
            li[r] += ls;
        }

        // ---- pack P into single-fp16 A-fragments ----
        uint32_t ph[4][4];
#pragma unroll
        for (int ks = 0; ks < 4; ks++) {
            ph[ks][0] = pack_h2(s[2 * ks][0],     s[2 * ks][1]);
            ph[ks][1] = pack_h2(s[2 * ks][2],     s[2 * ks][3]);
            ph[ks][2] = pack_h2(s[2 * ks + 1][0], s[2 * ks + 1][1]);
            ph[ks][3] = pack_h2(s[2 * ks + 1][2], s[2 * ks + 1][3]);
        }

        // ---- O += P @ V (single fp16) ----
#pragma unroll
        for (int ks = 0; ks < 4; ks++) {
#pragma unroll
            for (int dg = 0; dg < 4; dg++) {
                uint32_t vh[4];
                const uint32_t off = st + ATILE
                                   + (uint32_t)(ks * 16 + (lane & 15)) * ATROW
                                   + (dg * 16 + ((lane >> 4) << 3)) * 2;
                ldsm_x4t(vh[0], vh[1], vh[2], vh[3], off);
                mma_f16(o[dg * 2],     ph[ks], vh[0], vh[1]);
                mma_f16(o[dg * 2 + 1], ph[ks], vh[2], vh[3]);
            }
        }
        __syncthreads();
    }

    // epilogue: normalize, split to fp16 hi/lo (out-proj input format)
#pragma unroll
    for (int r = 0; r < 2; r++) {
        const float inv = 1.0f / li[r];
        const size_t ob = (size_t)(b * SEQ + q0 + w * 16 + g + r * 8) * HID + h * HD;
#pragma unroll
        for (int nf = 0; nf < 8; nf++) {
            uint32_t hp, lp;
            split_pack_h(o[nf][2 * r] * inv, o[nf][2 * r + 1] * inv, hp, lp);
            *(uint32_t*)(Oh + ob + nf * 8 + tq * 2) = hp;
            *(uint32_t*)(Ol + ob + nf * 8 + tq * 2) = lp;
        }
    }
}

// ---------------------------------------------------------------------------
// Launch
// ---------------------------------------------------------------------------
extern "C" void kernel_launch(void* const* d_in, const int* in_sizes, int n_in,
                              void* d_out, int out_size) {
    const float* hidden = (const float*)d_in[0];
    const void*  maskp  = d_in[1];
    const float* Wqkv   = (const float*)d_in[2];
    const float* Wout   = (const float*)d_in[3];
    const float* bout   = (const float*)d_in[4];
    float*       out    = (float*)d_out;

    void *p_qkv, *p_ah, *p_al, *p_wq, *p_wo;
    cudaGetSymbolAddress(&p_qkv, g_qkv);
    cudaGetSymbolAddress(&p_ah, g_ah);
    cudaGetSymbolAddress(&p_al, g_al);
    cudaGetSymbolAddress(&p_wq, g_wq);
    cudaGetSymbolAddress(&p_wo, g_wo);

    cudaFuncSetAttribute((const void*)f16_gemm_kernel<0, 0>,
                         cudaFuncAttributeMaxDynamicSharedMemorySize, QKV_SMEM);
    cudaFuncSetAttribute((const void*)f16_gemm_kernel<1, 1>,
                         cudaFuncAttributeMaxDynamicSharedMemorySize, OUT_SMEM);
    cudaFuncSetAttribute(mma_attn_kernel,
                         cudaFuncAttributeMaxDynamicSharedMemorySize, ATT_SMEM);

    // 1. mask canonicalize + tile bitmasks
    mask_convert_kernel<<<1, 256>>>(maskp, BATCH * SEQ);

    // 2. fp16 prep
    convA_f16_kernel<<<592, 256>>>(hidden, (__half*)p_ah, MROWS * HID / 4);
    quantWT_f16_kernel<<<dim3(QKV3 / 32, HID / 32), 256>>>(Wqkv, (__half*)p_wq, HID, QKV3);
    quantWT_f16_kernel<<<dim3(HID / 32, HID / 32), 256>>>(Wout, (__half*)p_wo, HID, HID);

    // 3. QKV projection (fp16 single-A, 1 MMA/k16) -> Q (pre-scaled) | K | V single fp16
    f16_gemm_kernel<0, 0><<<dim3(QKV3 / 128, MROWS / 128), 256, QKV_SMEM>>>(
        (const __half*)p_ah, nullptr, (const __half*)p_wq,
        nullptr, nullptr, (__half*)p_qkv,
        MROWS, QKV3, HID);

    // 4. fp16 flash attention (all single fp16) -> fp16 hi/lo attention output
    mma_attn_kernel<<<dim3(SEQ / 128, NH, BATCH), 256, ATT_SMEM>>>(
        (const __half*)p_qkv, (__half*)p_ah, (__half*)p_al);

    // 5. output projection (fp16 pair-A, 2 MMAs/k16, +bias)
    f16_gemm_kernel<1, 1><<<dim3(HID / 128, MROWS / 128), 256, OUT_SMEM>>>(
        (const __half*)p_ah, (const __half*)p_al, (const __half*)p_wo,
        bout, out, nullptr, MROWS, HID, HID);
}

// round 14
// speedup vs baseline: 3.9328x; 1.1129x over previous
#include <cuda_runtime.h>
#include <cuda_bf16.h>
#include <cuda_fp16.h>
#include <cstdint>

#define BATCH 4
#define SEQ   2048
#define NH    16
#define HD    64
#define HID   1024
#define QKV3  3072
#define MROWS (BATCH * SEQ)        // 8192

// 0.125 * log2(e): folded into Q at the QKV epilogue (softmax in base-2 domain)
#define QSF 0.18033688011112042f

// ---------------------------------------------------------------------------
// Scratch (static device globals — allocation-free per harness rules)
// ---------------------------------------------------------------------------
__device__ __half        g_qkv[MROWS * QKV3];          // Q (pre-scaled) | K | V, single fp16
__device__ int           g_mask[BATCH * SEQ];
__device__ unsigned long long g_mbits[BATCH * 32];     // 64-key tile bitmasks
__device__ __half        g_ah[MROWS * HID];            // activation single fp16 (hidden, then attn out)
__device__ __half        g_wq[QKV3 * HID];             // Wqkv^T single fp16 [N,K]
__device__ __half        g_wo[HID * HID];              // Wout^T single fp16 [N,K]

// ---------------------------------------------------------------------------
// PTX helpers (arch-portable sm_80+; tcgen05 unavailable via compute_103;
// s8 mma.sync measured ~4-5x worse rt than HMMA on sm_103 — do not use)
// ---------------------------------------------------------------------------
__device__ __forceinline__ uint32_t smem_u32(const void* p) {
    uint32_t a;
    asm("{ .reg .u64 t; cvta.to.shared.u64 t, %1; cvt.u32.u64 %0, t; }" : "=r"(a) : "l"(p));
    return a;
}
__device__ __forceinline__ void ldsm_x4(uint32_t& r0, uint32_t& r1, uint32_t& r2, uint32_t& r3,
                                        uint32_t addr) {
    asm volatile("ldmatrix.sync.aligned.m8n8.x4.shared.b16 {%0,%1,%2,%3}, [%4];"
                 : "=r"(r0), "=r"(r1), "=r"(r2), "=r"(r3) : "r"(addr));
}
__device__ __forceinline__ void ldsm_x4t(uint32_t& r0, uint32_t& r1, uint32_t& r2, uint32_t& r3,
                                         uint32_t addr) {
    asm volatile("ldmatrix.sync.aligned.m8n8.x4.trans.shared.b16 {%0,%1,%2,%3}, [%4];"
                 : "=r"(r0), "=r"(r1), "=r"(r2), "=r"(r3) : "r"(addr));
}
__device__ __forceinline__ void mma_f16(float* c, const uint32_t* a, uint32_t b0, uint32_t b1) {
    asm volatile(
        "mma.sync.aligned.m16n8k16.row.col.f32.f16.f16.f32 "
        "{%0,%1,%2,%3}, {%4,%5,%6,%7}, {%8,%9}, {%0,%1,%2,%3};"
        : "+f"(c[0]), "+f"(c[1]), "+f"(c[2]), "+f"(c[3])
        : "r"(a[0]), "r"(a[1]), "r"(a[2]), "r"(a[3]), "r"(b0), "r"(b1));
}
__device__ __forceinline__ float fexp2(float x) {
    float y; asm("ex2.approx.f32 %0, %1;" : "=f"(y) : "f"(x)); return y;
}
__device__ __forceinline__ uint32_t pack_h2(float x, float y) {
    __half2 v; v.x = __float2half(x); v.y = __float2half(y);
    return *(uint32_t*)&v;
}
#define CP_ASYNC16(dst, src) \
    asm volatile("cp.async.cg.shared.global [%0], [%1], 16;" :: "r"(dst), "l"(src))
#define CP_COMMIT() asm volatile("cp.async.commit_group;" ::: "memory")
#define CP_WAIT(n)  asm volatile("cp.async.wait_group %0;" :: "n"(n) : "memory")

// ---------------------------------------------------------------------------
// Mask canonicalizer + per-64-key-tile bitmasks
// ---------------------------------------------------------------------------
__global__ void mask_convert_kernel(const void* __restrict__ raw, int n) {
    __shared__ int mode;
    if (threadIdx.x == 0) {
        unsigned w0 = ((const unsigned*)raw)[0];
        if (w0 == 1u || w0 == 0u)    mode = 0;  // int32
        else if (w0 == 0x3F800000u)  mode = 1;  // float32
        else if (w0 == 0x01010101u)  mode = 2;  // uint8
        else if (w0 == 0x3F803F80u)  mode = 3;  // bf16 pair
        else                          mode = 2;
    }
    __syncthreads();
    int m = mode;
    for (int i = threadIdx.x; i < n; i += blockDim.x) {
        int v;
        if (m == 0)      v = (((const int*)raw)[i] != 0);
        else if (m == 1) v = (((const float*)raw)[i] != 0.0f);
        else if (m == 2) v = (((const unsigned char*)raw)[i] != 0);
        else { unsigned short h = ((const unsigned short*)raw)[i]; v = ((h & 0x7FFF) != 0); }
        g_mask[i] = v;
    }
    __syncthreads();
    for (int t = threadIdx.x; t < BATCH * 32; t += blockDim.x) {
        int b = t >> 5, kt = t & 31;
        unsigned long long mb = 0ull;
        for (int j = 0; j < 64; j++)
            mb |= ((unsigned long long)(g_mask[b * SEQ + kt * 64 + j] & 1)) << j;
        g_mbits[t] = mb;
    }
}

// ---------------------------------------------------------------------------
// fp16 prep kernels
// ---------------------------------------------------------------------------
__global__ void convA_f16_kernel(const float* __restrict__ A,
                                 __half* __restrict__ Ah, int n4) {
    int stride = gridDim.x * blockDim.x;
    for (int i = blockIdx.x * blockDim.x + threadIdx.x; i < n4; i += stride) {
        float4 v = ((const float4*)A)[i];
        ((uint32_t*)Ah)[i * 2]     = pack_h2(v.x, v.y);
        ((uint32_t*)Ah)[i * 2 + 1] = pack_h2(v.z, v.w);
    }
}

// W [K,N] fp32 -> W^T [N,K] single fp16
__global__ void quantWT_f16_kernel(const float* __restrict__ W,
                                   __half* __restrict__ WT, int K, int N) {
    __shared__ float tile[32][33];
    int k0 = blockIdx.y * 32, n0 = blockIdx.x * 32;
    int tx = threadIdx.x & 31, ty = threadIdx.x >> 5;
    for (int r = ty; r < 32; r += 8)
        tile[r][tx] = W[(size_t)(k0 + r) * N + n0 + tx];
    __syncthreads();
    for (int r = ty; r < 32; r += 8)
        WT[(size_t)(n0 + r) * K + k0 + tx] = __float2half(tile[tx][r]);
}

// ---------------------------------------------------------------------------
// fp16 single-A GEMM: C = A @ WT^T, 1 MMA/k16.
// MODE 0 (QKV): fp16 output; Q cols pre-scaled by QSF.
// MODE 1 (out-proj): fp32 + bias.
// ---------------------------------------------------------------------------
#define KC        32
#define TROW      80
#define TILE_B    (128 * TROW)          // 10240
#define STAGE_B   (2 * TILE_B)          // 20480: A | B
#define GM_SMEM   (2 * STAGE_B)         // 40960

template <int MODE>
__global__ __launch_bounds__(256, 2)
void f16_gemm_kernel(const __half* __restrict__ Ah, const __half* __restrict__ WT,
                     const float* __restrict__ bias, float* __restrict__ C,
                     __half* __restrict__ Ch,
                     int M, int N, int K) {
    extern __shared__ char smem[];
    const uint32_t sb = smem_u32(smem);
    const int tid   = threadIdx.x;
    const int lane  = tid & 31;
    const int wid   = tid >> 5;
    const int warpM = wid & 3;
    const int warpN = wid >> 2;
    const int m0 = blockIdx.y * 128;
    const int n0 = blockIdx.x * 128;
    const int nch = K / KC;

    auto load_stage = [&](int kc0, int s) {
        const uint32_t stg = sb + s * STAGE_B;
#pragma unroll
        for (int t = 0; t < 4; t++) {
            const int id   = tid + t * 256;
            const int tile = id >> 9;             // 0:A 1:B
            const int rem  = id & 511;
            const int row  = rem >> 2;
            const int q    = rem & 3;
            const __half* src = tile ? (WT + (size_t)(n0 + row) * K + kc0 + q * 8)
                                     : (Ah + (size_t)(m0 + row) * K + kc0 + q * 8);
            CP_ASYNC16(stg + tile * TILE_B + row * TROW + q * 16, src);
        }
        CP_COMMIT();
    };

    float c[2][8][4];
#pragma unroll
    for (int i = 0; i < 2; i++)
#pragma unroll
        for (int j = 0; j < 8; j++)
#pragma unroll
            for (int r = 0; r < 4; r++) c[i][j][r] = 0.0f;

    const int arow = warpM * 32 + (lane & 15);
    const int acol = (lane >> 4) * 8;
    const int brow = warpN * 64 + (lane & 7) + ((lane >> 4) << 3);
    const int bck  = ((lane >> 3) & 1) * 8;

    load_stage(0, 0);
    load_stage(KC, 1);

    for (int ch = 0; ch < nch; ch++) {
        CP_WAIT(1);
        __syncthreads();

        const uint32_t stg = sb + (ch & 1) * STAGE_B;
        const uint32_t ahb = stg;
        const uint32_t bbb = stg + TILE_B;

#pragma unroll
        for (int k16 = 0; k16 < 2; k16++) {
            uint32_t fah[2][4];
#pragma unroll
            for (int mt = 0; mt < 2; mt++) {
                uint32_t off = (uint32_t)(arow + mt * 16) * TROW + (k16 * 16 + acol) * 2;
                ldsm_x4(fah[mt][0], fah[mt][1], fah[mt][2], fah[mt][3], ahb + off);
            }
#pragma unroll
            for (int np = 0; np < 4; np++) {
                uint32_t bf[4];
                uint32_t off = (uint32_t)(brow + np * 16) * TROW + (k16 * 16 + bck) * 2;
                ldsm_x4(bf[0], bf[1], bf[2], bf[3], bbb + off);
#pragma unroll
                for (int mt = 0; mt < 2; mt++)
#pragma unroll
                    for (int half = 0; half < 2; half++)
                        mma_f16(c[mt][np * 2 + half], fah[mt], bf[half * 2], bf[half * 2 + 1]);
            }
        }
        __syncthreads();
        if (ch + 2 < nch) load_stage((ch + 2) * KC, ch & 1);
        else CP_COMMIT();   // placeholder group: keeps CP_WAIT(1) accounting exact
    }

    const int g   = lane >> 2;
    const int tig = lane & 3;
#pragma unroll
    for (int mt = 0; mt < 2; mt++) {
        const int row = m0 + warpM * 32 + mt * 16 + g;
#pragma unroll
        for (int nt = 0; nt < 8; nt++) {
            const int col = n0 + warpN * 64 + nt * 8 + tig * 2;
            if (MODE == 1) {
                float2 v0 = make_float2(c[mt][nt][0] + bias[col], c[mt][nt][1] + bias[col + 1]);
                float2 v1 = make_float2(c[mt][nt][2] + bias[col], c[mt][nt][3] + bias[col + 1]);
                *(float2*)(C + (size_t)row * N + col)       = v0;
                *(float2*)(C + (size_t)(row + 8) * N + col) = v1;
            } else {
                const float sc = (col < HID) ? QSF : 1.0f;    // Q pre-scale
                *(uint32_t*)(Ch + (size_t)row * N + col) =
                    pack_h2(c[mt][nt][0] * sc, c[mt][nt][1] * sc);
                *(uint32_t*)(Ch + (size_t)(row + 8) * N + col) =
                    pack_h2(c[mt][nt][2] * sc, c[mt][nt][3] * sc);
            }
        }
    }
}

// ---------------------------------------------------------------------------
// fp16 flash attention: Q, K, V, P, O all single fp16 paths (fp32 accum +
// softmax). QK: 1 MMA/k16; PV: 1 MMA/k16. Occupancy 2; smem 55.5 KB.
// ---------------------------------------------------------------------------
#define ATROW 144
#define ATILE (64 * ATROW)                 // 9216
#define ASTAGE (2 * ATILE)                 // 18432: K | V
#define QTILE (128 * ATROW)                // 18432
#define ATT_SMEM (2 * ASTAGE + QTILE + 160)   // 55456

__global__ __launch_bounds__(256, 2)
void mma_attn_kernel(const __half* __restrict__ QKV, __half* __restrict__ Oh) {
    extern __shared__ char sm[];
    const uint32_t sb  = smem_u32(sm);
    const uint32_t qsm = sb + 2 * ASTAGE;
    int* list = (int*)(sm + 2 * ASTAGE + QTILE);

    const int tid  = threadIdx.x;
    const int lane = tid & 31;
    const int w    = tid >> 5;
    const int b    = blockIdx.z;
    const int h    = blockIdx.y;
    const int q0   = blockIdx.x * 128;
    const int g    = lane >> 2;
    const int tq   = lane & 3;

    if (w == 0) {
        unsigned long long mb = g_mbits[b * 32 + lane];
        unsigned act = __ballot_sync(0xffffffffu, mb != 0ull);
        int pos = __popc(act & ((1u << lane) - 1));
        if (mb != 0ull) list[pos] = lane;
        if (lane == 0) list[32] = __popc(act);
    }
    __syncthreads();
    const int ncnt = list[32];

    // stage Q tile (128 rows x 64 fp16) into smem
    {
        const int tok0 = b * SEQ + q0;
#pragma unroll
        for (int t = 0; t < 4; t++) {
            const int id  = tid + t * 256;
            const int r   = id >> 3;
            const int seg = id & 7;
            const size_t go = (size_t)(tok0 + r) * QKV3 + h * HD + seg * 8;
            CP_ASYNC16(qsm + r * ATROW + seg * 16, QKV + go);
        }
        CP_COMMIT();
    }

    auto load_tile = [&](int kt, int stg) {
        const int tok0 = b * SEQ + kt * 64;
        const uint32_t base = sb + stg * ASTAGE;
#pragma unroll
        for (int t = 0; t < 4; t++) {
            const int id  = tid + t * 256;
            const int arr = id >> 9;              // 0:K 1:V
            const int rem = id & 511;
            const int r   = rem >> 3;
            const int q   = rem & 7;
            const size_t go = (size_t)(tok0 + r) * QKV3 + h * HD + q * 8;
            const __half* src = arr ? (QKV + go + 2 * HID) : (QKV + go + HID);
            CP_ASYNC16(base + arr * ATILE + r * ATROW + q * 16, src);
        }
        CP_COMMIT();
    };

    float o[8][4];
#pragma unroll
    for (int j = 0; j < 8; j++)
#pragma unroll
        for (int r = 0; r < 4; r++) o[j][r] = 0.0f;
    float mi[2] = {-1e30f, -1e30f}, li[2] = {0.0f, 0.0f};

    if (ncnt > 0) load_tile(list[0], 0);

    const uint32_t qrowoff = qsm + (uint32_t)(w * 16 + (lane & 15)) * ATROW
                           + ((lane >> 4) << 3) * 2;

    for (int it = 0; it < ncnt; it++) {
        if (it + 1 < ncnt) { load_tile(list[it + 1], (it + 1) & 1); CP_WAIT(1); }
        else CP_WAIT(0);
        __syncthreads();
        const uint32_t st = sb + (it & 1) * ASTAGE;
        const int kt = list[it];

        // ---- S = Q @ K^T ----
        float s[8][4];
#pragma unroll
        for (int j = 0; j < 8; j++)
#pragma unroll
            for (int r = 0; r < 4; r++) s[j][r] = 0.0f;

#pragma unroll
        for (int kd = 0; kd < 4; kd++) {
            uint32_t qh4[4];
            ldsm_x4(qh4[0], qh4[1], qh4[2], qh4[3], qrowoff + kd * 32);
#pragma unroll
            for (int kg = 0; kg < 4; kg++) {
                uint32_t kh[4];
                const uint32_t off = st + (uint32_t)(kg * 16 + (lane & 7) + ((lane >> 4) << 3)) * ATROW
                                        + (kd * 16 + ((lane >> 3) & 1) * 8) * 2;
                ldsm_x4(kh[0], kh[1], kh[2], kh[3], off);
                mma_f16(s[kg * 2],     qh4, kh[0], kh[1]);
                mma_f16(s[kg * 2 + 1], qh4, kh[2], kh[3]);
            }
        }

        // ---- key-padding mask ----
        const unsigned long long mb = g_mbits[b * 32 + kt];
        if (mb != ~0ull) {
#pragma unroll
            for (int nf = 0; nf < 8; nf++) {
                const int c0 = nf * 8 + tq * 2;
                if (!((mb >> c0) & 1))       { s[nf][0] = -1e30f; s[nf][2] = -1e30f; }
                if (!((mb >> (c0 + 1)) & 1)) { s[nf][1] = -1e30f; s[nf][3] = -1e30f; }
            }
        }

        // ---- online softmax (base-2; Q pre-scaled) ----
#pragma unroll
        for (int r = 0; r < 2; r++) {
            float mx = -1e30f;
#pragma unroll
            for (int nf = 0; nf < 8; nf++)
                mx = fmaxf(mx, fmaxf(s[nf][2 * r], s[nf][2 * r + 1]));
            mx = fmaxf(mx, __shfl_xor_sync(0xffffffffu, mx, 1));
            mx = fmaxf(mx, __shfl_xor_sync(0xffffffffu, mx, 2));
            const float mnew = fmaxf(mi[r], mx);
            const float al = fexp2(mi[r] - mnew);
            mi[r] = mnew;
            li[r] *= al;
#pragma unroll
            for (int nf = 0; nf < 8; nf++) { o[nf][2 * r] *= al; o[nf][2 * r + 1] *= al; }
            float ls = 0.0f;
#pragma unroll
            for (int nf = 0; nf < 8; nf++) {
                const float p0 = fexp2(s[nf][2 * r] - mnew);
                const float p1 = fexp2(s[nf][2 * r + 1] - mnew);
                ls += p0 + p1;
                s[nf][2 * r] = p0;
                s[nf][2 * r + 1] = p1;
            }
            ls += __shfl_xor_sync(0xffffffffu, ls, 1);
            ls += __shfl_xor_sync(0xffffffffu, ls, 2);
            li[r] += ls;
        }

        // ---- pack P into single-fp16 A-fragments ----
        uint32_t ph[4][4];
#pragma unroll
        for (int ks = 0; ks < 4; ks++) {
            ph[ks][0] = pack_h2(s[2 * ks][0],     s[2 * ks][1]);
            ph[ks][1] = pack_h2(s[2 * ks][2],     s[2 * ks][3]);
            ph[ks][2] = pack_h2(s[2 * ks + 1][0], s[2 * ks + 1][1]);
            ph[ks][3] = pack_h2(s[2 * ks + 1][2], s[2 * ks + 1][3]);
        }

        // ---- O += P @ V ----
#pragma unroll
        for (int ks = 0; ks < 4; ks++) {
#pragma unroll
            for (int dg = 0; dg < 4; dg++) {
                uint32_t vh[4];
                const uint32_t off = st + ATILE
                                   + (uint32_t)(ks * 16 + (lane & 15)) * ATROW
                                   + (dg * 16 + ((lane >> 4) << 3)) * 2;
                ldsm_x4t(vh[0], vh[1], vh[2], vh[3], off);
                mma_f16(o[dg * 2],     ph[ks], vh[0], vh[1]);
                mma_f16(o[dg * 2 + 1], ph[ks], vh[2], vh[3]);
            }
        }
        __syncthreads();
    }

    // epilogue: normalize, single fp16 (out-proj input)
#pragma unroll
    for (int r = 0; r < 2; r++) {
        const float inv = 1.0f / li[r];
        const size_t ob = (size_t)(b * SEQ + q0 + w * 16 + g + r * 8) * HID + h * HD;
#pragma unroll
        for (int nf = 0; nf < 8; nf++)
            *(uint32_t*)(Oh + ob + nf * 8 + tq * 2) =
                pack_h2(o[nf][2 * r] * inv, o[nf][2 * r + 1] * inv);
    }
}

// ---------------------------------------------------------------------------
// Launch
// ---------------------------------------------------------------------------
extern "C" void kernel_launch(void* const* d_in, const int* in_sizes, int n_in,
                              void* d_out, int out_size) {
    const float* hidden = (const float*)d_in[0];
    const void*  maskp  = d_in[1];
    const float* Wqkv   = (const float*)d_in[2];
    const float* Wout   = (const float*)d_in[3];
    const float* bout   = (const float*)d_in[4];
    float*       out    = (float*)d_out;

    void *p_qkv, *p_ah, *p_wq, *p_wo;
    cudaGetSymbolAddress(&p_qkv, g_qkv);
    cudaGetSymbolAddress(&p_ah, g_ah);
    cudaGetSymbolAddress(&p_wq, g_wq);
    cudaGetSymbolAddress(&p_wo, g_wo);

    cudaFuncSetAttribute((const void*)f16_gemm_kernel<0>,
                         cudaFuncAttributeMaxDynamicSharedMemorySize, GM_SMEM);
    cudaFuncSetAttribute((const void*)f16_gemm_kernel<1>,
                         cudaFuncAttributeMaxDynamicSharedMemorySize, GM_SMEM);
    cudaFuncSetAttribute(mma_attn_kernel,
                         cudaFuncAttributeMaxDynamicSharedMemorySize, ATT_SMEM);

    // 1. mask canonicalize + tile bitmasks
    mask_convert_kernel<<<1, 256>>>(maskp, BATCH * SEQ);

    // 2. fp16 prep
    convA_f16_kernel<<<592, 256>>>(hidden, (__half*)p_ah, MROWS * HID / 4);
    quantWT_f16_kernel<<<dim3(QKV3 / 32, HID / 32), 256>>>(Wqkv, (__half*)p_wq, HID, QKV3);
    quantWT_f16_kernel<<<dim3(HID / 32, HID / 32), 256>>>(Wout, (__half*)p_wo, HID, HID);

    // 3. QKV projection (1 MMA/k16) -> Q (pre-scaled) | K | V single fp16
    f16_gemm_kernel<0><<<dim3(QKV3 / 128, MROWS / 128), 256, GM_SMEM>>>(
        (const __half*)p_ah, (const __half*)p_wq,
        nullptr, nullptr, (__half*)p_qkv, MROWS, QKV3, HID);

    // 4. fp16 flash attention -> single fp16 attention output
    mma_attn_kernel<<<dim3(SEQ / 128, NH, BATCH), 256, ATT_SMEM>>>(
        (const __half*)p_qkv, (__half*)p_ah);

    // 5. output projection (1 MMA/k16, +bias)
    f16_gemm_kernel<1><<<dim3(HID / 128, MROWS / 128), 256, GM_SMEM>>>(
        (const __half*)p_ah, (const __half*)p_wo,
        bout, out, nullptr, MROWS, HID, HID);
}

// round 15
// speedup vs baseline: 4.3103x; 1.0960x over previous
#include <cuda_runtime.h>
#include <cuda_bf16.h>
#include <cuda_fp16.h>
#include <cstdint>

#define BATCH 4
#define SEQ   2048
#define NH    16
#define HD    64
#define HID   1024
#define QKV3  3072
#define MROWS (BATCH * SEQ)        // 8192

// 0.125 * log2(e): folded into Q at the QKV epilogue (softmax in base-2 domain)
#define QSF 0.18033688011112042f

// ---------------------------------------------------------------------------
// Scratch (static device globals — allocation-free per harness rules)
// ---------------------------------------------------------------------------
__device__ __half        g_qkv[MROWS * QKV3];          // Q (pre-scaled) | K | V, single fp16
__device__ int           g_mask[BATCH * SEQ];
__device__ unsigned long long g_mbits[BATCH * 32];     // 64-key tile bitmasks
__device__ __half        g_ah[MROWS * HID];            // activation single fp16 (hidden, then attn out)
__device__ __half        g_wq[QKV3 * HID];             // Wqkv^T single fp16 [N,K]
__device__ __half        g_wo[HID * HID];              // Wout^T single fp16 [N,K]

// ---------------------------------------------------------------------------
// PTX helpers (arch-portable sm_80+; tcgen05 unavailable via compute_103;
// s8 mma.sync measured ~4-5x worse rt than HMMA on sm_103 — do not use)
// ---------------------------------------------------------------------------
__device__ __forceinline__ uint32_t smem_u32(const void* p) {
    uint32_t a;
    asm("{ .reg .u64 t; cvta.to.shared.u64 t, %1; cvt.u32.u64 %0, t; }" : "=r"(a) : "l"(p));
    return a;
}
__device__ __forceinline__ void ldsm_x4(uint32_t& r0, uint32_t& r1, uint32_t& r2, uint32_t& r3,
                                        uint32_t addr) {
    asm volatile("ldmatrix.sync.aligned.m8n8.x4.shared.b16 {%0,%1,%2,%3}, [%4];"
                 : "=r"(r0), "=r"(r1), "=r"(r2), "=r"(r3) : "r"(addr));
}
__device__ __forceinline__ void ldsm_x4t(uint32_t& r0, uint32_t& r1, uint32_t& r2, uint32_t& r3,
                                         uint32_t addr) {
    asm volatile("ldmatrix.sync.aligned.m8n8.x4.trans.shared.b16 {%0,%1,%2,%3}, [%4];"
                 : "=r"(r0), "=r"(r1), "=r"(r2), "=r"(r3) : "r"(addr));
}
__device__ __forceinline__ void mma_f16(float* c, const uint32_t* a, uint32_t b0, uint32_t b1) {
    asm volatile(
        "mma.sync.aligned.m16n8k16.row.col.f32.f16.f16.f32 "
        "{%0,%1,%2,%3}, {%4,%5,%6,%7}, {%8,%9}, {%0,%1,%2,%3};"
        : "+f"(c[0]), "+f"(c[1]), "+f"(c[2]), "+f"(c[3])
        : "r"(a[0]), "r"(a[1]), "r"(a[2]), "r"(a[3]), "r"(b0), "r"(b1));
}
__device__ __forceinline__ float fexp2(float x) {
    float y; asm("ex2.approx.f32 %0, %1;" : "=f"(y) : "f"(x)); return y;
}
__device__ __forceinline__ uint32_t pack_h2(float x, float y) {
    __half2 v; v.x = __float2half(x); v.y = __float2half(y);
    return *(uint32_t*)&v;
}
#define CP_ASYNC16(dst, src) \
    asm volatile("cp.async.cg.shared.global [%0], [%1], 16;" :: "r"(dst), "l"(src))
#define CP_COMMIT() asm volatile("cp.async.commit_group;" ::: "memory")
#define CP_WAIT(n)  asm volatile("cp.async.wait_group %0;" :: "n"(n) : "memory")

// ---------------------------------------------------------------------------
// Fused prep kernel: block 0 -> mask canonicalize + tile bitmasks;
// blocks [1, 593) -> hidden fp32->fp16; blocks [593, 3665) -> Wqkv^T fp16;
// blocks [3665, 4689) -> Wout^T fp16. All parts independent.
// ---------------------------------------------------------------------------
#define PREP_CONV_BLKS 592
#define PREP_WQ_BLKS   (QKV3 / 32 * HID / 32)   // 3072
#define PREP_WO_BLKS   (HID / 32 * HID / 32)    // 1024
#define PREP_BLKS      (1 + PREP_CONV_BLKS + PREP_WQ_BLKS + PREP_WO_BLKS)

__device__ __forceinline__ void quantWT_part(const float* __restrict__ W,
                                             __half* __restrict__ WT,
                                             int K, int N, int k0, int n0,
                                             float tile[32][33]) {
    int tx = threadIdx.x & 31, ty = threadIdx.x >> 5;
    for (int r = ty; r < 32; r += 8)
        tile[r][tx] = W[(size_t)(k0 + r) * N + n0 + tx];
    __syncthreads();
    for (int r = ty; r < 32; r += 8)
        WT[(size_t)(n0 + r) * K + k0 + tx] = __float2half(tile[tx][r]);
}

__global__ void prep_kernel(const float* __restrict__ hidden,
                            const float* __restrict__ Wqkv,
                            const float* __restrict__ Wout,
                            const void* __restrict__ maskp) {
    __shared__ float tile[32][33];
    const int bid = blockIdx.x;
    const int tid = threadIdx.x;

    if (bid == 0) {
        // ---- mask canonicalize + bitmasks ----
        __shared__ int mode;
        if (tid == 0) {
            unsigned w0 = ((const unsigned*)maskp)[0];
            if (w0 == 1u || w0 == 0u)    mode = 0;  // int32
            else if (w0 == 0x3F800000u)  mode = 1;  // float32
            else if (w0 == 0x01010101u)  mode = 2;  // uint8
            else if (w0 == 0x3F803F80u)  mode = 3;  // bf16 pair
            else                          mode = 2;
        }
        __syncthreads();
        int m = mode;
        for (int i = tid; i < BATCH * SEQ; i += blockDim.x) {
            int v;
            if (m == 0)      v = (((const int*)maskp)[i] != 0);
            else if (m == 1) v = (((const float*)maskp)[i] != 0.0f);
            else if (m == 2) v = (((const unsigned char*)maskp)[i] != 0);
            else { unsigned short h = ((const unsigned short*)maskp)[i]; v = ((h & 0x7FFF) != 0); }
            g_mask[i] = v;
        }
        __syncthreads();
        for (int t = tid; t < BATCH * 32; t += blockDim.x) {
            int b = t >> 5, kt = t & 31;
            unsigned long long mb = 0ull;
            for (int j = 0; j < 64; j++)
                mb |= ((unsigned long long)(g_mask[b * SEQ + kt * 64 + j] & 1)) << j;
            g_mbits[t] = mb;
        }
    } else if (bid < 1 + PREP_CONV_BLKS) {
        // ---- hidden fp32 -> single fp16 ----
        const int vb = bid - 1;
        const int n4 = MROWS * HID / 4;
        const int stride = PREP_CONV_BLKS * 256;
        for (int i = vb * 256 + tid; i < n4; i += stride) {
            float4 v = ((const float4*)hidden)[i];
            ((uint32_t*)g_ah)[i * 2]     = pack_h2(v.x, v.y);
            ((uint32_t*)g_ah)[i * 2 + 1] = pack_h2(v.z, v.w);
        }
    } else if (bid < 1 + PREP_CONV_BLKS + PREP_WQ_BLKS) {
        // ---- Wqkv [HID, QKV3] -> Wqkv^T fp16 [QKV3, HID] ----
        const int idx = bid - 1 - PREP_CONV_BLKS;
        const int n0 = (idx % (QKV3 / 32)) * 32;
        const int k0 = (idx / (QKV3 / 32)) * 32;
        quantWT_part(Wqkv, g_wq, HID, QKV3, k0, n0, tile);
    } else {
        // ---- Wout [HID, HID] -> Wout^T fp16 [HID, HID] ----
        const int idx = bid - 1 - PREP_CONV_BLKS - PREP_WQ_BLKS;
        const int n0 = (idx % (HID / 32)) * 32;
        const int k0 = (idx / (HID / 32)) * 32;
        quantWT_part(Wout, g_wo, HID, HID, k0, n0, tile);
    }
}

// ---------------------------------------------------------------------------
// fp16 single-A GEMM: C = A @ WT^T, 1 MMA/k16. K-chunks of 64 (16 chunk
// iterations for K=1024 -> half the sync/wait boundaries of KC=32).
// MODE 0 (QKV): fp16 output; Q cols pre-scaled by QSF.
// MODE 1 (out-proj): fp32 + bias.
// ---------------------------------------------------------------------------
#define KC        64
#define TROW      144                   // 128B data + 16B pad (conflict-free ldsm)
#define TILE_B    (128 * TROW)          // 18432
#define STAGE_B   (2 * TILE_B)          // 36864: A | B
#define GM_SMEM   (2 * STAGE_B)         // 73728 -> 2 CTAs/SM

template <int MODE>
__global__ __launch_bounds__(256, 2)
void f16_gemm_kernel(const __half* __restrict__ Ah, const __half* __restrict__ WT,
                     const float* __restrict__ bias, float* __restrict__ C,
                     __half* __restrict__ Ch,
                     int M, int N, int K) {
    extern __shared__ char smem[];
    const uint32_t sb = smem_u32(smem);
    const int tid   = threadIdx.x;
    const int lane  = tid & 31;
    const int wid   = tid >> 5;
    const int warpM = wid & 3;
    const int warpN = wid >> 2;
    const int m0 = blockIdx.y * 128;
    const int n0 = blockIdx.x * 128;
    const int nch = K / KC;              // 16

    // 2048 x 16B per stage, 256 threads -> 8 ops each
    auto load_stage = [&](int kc0, int s) {
        const uint32_t stg = sb + s * STAGE_B;
#pragma unroll
        for (int t = 0; t < 8; t++) {
            const int id   = tid + t * 256;
            const int tile = id >> 10;            // 0:A 1:B
            const int rem  = id & 1023;
            const int row  = rem >> 3;
            const int q    = rem & 7;
            const __half* src = tile ? (WT + (size_t)(n0 + row) * K + kc0 + q * 8)
                                     : (Ah + (size_t)(m0 + row) * K + kc0 + q * 8);
            CP_ASYNC16(stg + tile * TILE_B + row * TROW + q * 16, src);
        }
        CP_COMMIT();
    };

    float c[2][8][4];
#pragma unroll
    for (int i = 0; i < 2; i++)
#pragma unroll
        for (int j = 0; j < 8; j++)
#pragma unroll
            for (int r = 0; r < 4; r++) c[i][j][r] = 0.0f;

    const int arow = warpM * 32 + (lane & 15);
    const int acol = (lane >> 4) * 8;
    const int brow = warpN * 64 + (lane & 7) + ((lane >> 4) << 3);
    const int bck  = ((lane >> 3) & 1) * 8;

    load_stage(0, 0);
    load_stage(KC, 1);

    for (int ch = 0; ch < nch; ch++) {
        CP_WAIT(1);
        __syncthreads();

        const uint32_t stg = sb + (ch & 1) * STAGE_B;
        const uint32_t ahb = stg;
        const uint32_t bbb = stg + TILE_B;

#pragma unroll
        for (int k16 = 0; k16 < 4; k16++) {
            uint32_t fah[2][4];
#pragma unroll
            for (int mt = 0; mt < 2; mt++) {
                uint32_t off = (uint32_t)(arow + mt * 16) * TROW + (k16 * 16 + acol) * 2;
                ldsm_x4(fah[mt][0], fah[mt][1], fah[mt][2], fah[mt][3], ahb + off);
            }
#pragma unroll
            for (int np = 0; np < 4; np++) {
                uint32_t bf[4];
                uint32_t off = (uint32_t)(brow + np * 16) * TROW + (k16 * 16 + bck) * 2;
                ldsm_x4(bf[0], bf[1], bf[2], bf[3], bbb + off);
#pragma unroll
                for (int mt = 0; mt < 2; mt++)
#pragma unroll
                    for (int half = 0; half < 2; half++)
                        mma_f16(c[mt][np * 2 + half], fah[mt], bf[half * 2], bf[half * 2 + 1]);
            }
        }
        __syncthreads();
        if (ch + 2 < nch) load_stage((ch + 2) * KC, ch & 1);
        else CP_COMMIT();   // placeholder group: keeps CP_WAIT(1) accounting exact
    }

    const int g   = lane >> 2;
    const int tig = lane & 3;
#pragma unroll
    for (int mt = 0; mt < 2; mt++) {
        const int row = m0 + warpM * 32 + mt * 16 + g;
#pragma unroll
        for (int nt = 0; nt < 8; nt++) {
            const int col = n0 + warpN * 64 + nt * 8 + tig * 2;
            if (MODE == 1) {
                float2 v0 = make_float2(c[mt][nt][0] + bias[col], c[mt][nt][1] + bias[col + 1]);
                float2 v1 = make_float2(c[mt][nt][2] + bias[col], c[mt][nt][3] + bias[col + 1]);
                *(float2*)(C + (size_t)row * N + col)       = v0;
                *(float2*)(C + (size_t)(row + 8) * N + col) = v1;
            } else {
                const float sc = (col < HID) ? QSF : 1.0f;    // Q pre-scale
                *(uint32_t*)(Ch + (size_t)row * N + col) =
                    pack_h2(c[mt][nt][0] * sc, c[mt][nt][1] * sc);
                *(uint32_t*)(Ch + (size_t)(row + 8) * N + col) =
                    pack_h2(c[mt][nt][2] * sc, c[mt][nt][3] * sc);
            }
        }
    }
}

// ---------------------------------------------------------------------------
// fp16 flash attention (R14-proven, unchanged): Q, K, V, P single fp16 with
// fp32 accum + softmax. Occupancy 2; smem 55.5 KB.
// ---------------------------------------------------------------------------
#define ATROW 144
#define ATILE (64 * ATROW)                 // 9216
#define ASTAGE (2 * ATILE)                 // 18432: K | V
#define QTILE (128 * ATROW)                // 18432
#define ATT_SMEM (2 * ASTAGE + QTILE + 160)   // 55456

__global__ __launch_bounds__(256, 2)
void mma_attn_kernel(const __half* __restrict__ QKV, __half* __restrict__ Oh) {
    extern __shared__ char sm[];
    const uint32_t sb  = smem_u32(sm);
    const uint32_t qsm = sb + 2 * ASTAGE;
    int* list = (int*)(sm + 2 * ASTAGE + QTILE);

    const int tid  = threadIdx.x;
    const int lane = tid & 31;
    const int w    = tid >> 5;
    const int b    = blockIdx.z;
    const int h    = blockIdx.y;
    const int q0   = blockIdx.x * 128;
    const int g    = lane >> 2;
    const int tq   = lane & 3;

    if (w == 0) {
        unsigned long long mb = g_mbits[b * 32 + lane];
        unsigned act = __ballot_sync(0xffffffffu, mb != 0ull);
        int pos = __popc(act & ((1u << lane) - 1));
        if (mb != 0ull) list[pos] = lane;
        if (lane == 0) list[32] = __popc(act);
    }
    __syncthreads();
    const int ncnt = list[32];

    // stage Q tile (128 rows x 64 fp16) into smem
    {
        const int tok0 = b * SEQ + q0;
#pragma unroll
        for (int t = 0; t < 4; t++) {
            const int id  = tid + t * 256;
            const int r   = id >> 3;
            const int seg = id & 7;
            const size_t go = (size_t)(tok0 + r) * QKV3 + h * HD + seg * 8;
            CP_ASYNC16(qsm + r * ATROW + seg * 16, QKV + go);
        }
        CP_COMMIT();
    }

    auto load_tile = [&](int kt, int stg) {
        const int tok0 = b * SEQ + kt * 64;
        const uint32_t base = sb + stg * ASTAGE;
#pragma unroll
        for (int t = 0; t < 4; t++) {
            const int id  = tid + t * 256;
            const int arr = id >> 9;              // 0:K 1:V
            const int rem = id & 511;
            const int r   = rem >> 3;
            const int q   = rem & 7;
            const size_t go = (size_t)(tok0 + r) * QKV3 + h * HD + q * 8;
            const __half* src = arr ? (QKV + go + 2 * HID) : (QKV + go + HID);
            CP_ASYNC16(base + arr * ATILE + r * ATROW + q * 16, src);
        }
        CP_COMMIT();
    };

    float o[8][4];
#pragma unroll
    for (int j = 0; j < 8; j++)
#pragma unroll
        for (int r = 0; r < 4; r++) o[j][r] = 0.0f;
    float mi[2] = {-1e30f, -1e30f}, li[2] = {0.0f, 0.0f};

    if (ncnt > 0) load_tile(list[0], 0);

    const uint32_t qrowoff = qsm + (uint32_t)(w * 16 + (lane & 15)) * ATROW
                           + ((lane >> 4) << 3) * 2;

    for (int it = 0; it < ncnt; it++) {
        if (it + 1 < ncnt) { load_tile(list[it + 1], (it + 1) & 1); CP_WAIT(1); }
        else CP_WAIT(0);
        __syncthreads();
        const uint32_t st = sb + (it & 1) * ASTAGE;
        const int kt = list[it];

        // ---- S = Q @ K^T ----
        float s[8][4];
#pragma unroll
        for (int j = 0; j < 8; j++)
#pragma unroll
            for (int r = 0; r < 4; r++) s[j][r] = 0.0f;

#pragma unroll
        for (int kd = 0; kd < 4; kd++) {
            uint32_t qh4[4];
            ldsm_x4(qh4[0], qh4[1], qh4[2], qh4[3], qrowoff + kd * 32);
#pragma unroll
            for (int kg = 0; kg < 4; kg++) {
                uint32_t kh[4];
                const uint32_t off = st + (uint32_t)(kg * 16 + (lane & 7) + ((lane >> 4) << 3)) * ATROW
                                        + (kd * 16 + ((lane >> 3) & 1) * 8) * 2;
                ldsm_x4(kh[0], kh[1], kh[2], kh[3], off);
                mma_f16(s[kg * 2],     qh4, kh[0], kh[1]);
                mma_f16(s[kg * 2 + 1], qh4, kh[2], kh[3]);
            }
        }

        // ---- key-padding mask ----
        const unsigned long long mb = g_mbits[b * 32 + kt];
        if (mb != ~0ull) {
#pragma unroll
            for (int nf = 0; nf < 8; nf++) {
                const int c0 = nf * 8 + tq * 2;
                if (!((mb >> c0) & 1))       { s[nf][0] = -1e30f; s[nf][2] = -1e30f; }
                if (!((mb >> (c0 + 1)) & 1)) { s[nf][1] = -1e30f; s[nf][3] = -1e30f; }
            }
        }

        // ---- online softmax (base-2; Q pre-scaled) ----
#pragma unroll
        for (int r = 0; r < 2; r++) {
            float mx = -1e30f;
#pragma unroll
            for (int nf = 0; nf < 8; nf++)
                mx = fmaxf(mx, fmaxf(s[nf][2 * r], s[nf][2 * r + 1]));
            mx = fmaxf(mx, __shfl_xor_sync(0xffffffffu, mx, 1));
            mx = fmaxf(mx, __shfl_xor_sync(0xffffffffu, mx, 2));
            const float mnew = fmaxf(mi[r], mx);
            const float al = fexp2(mi[r] - mnew);
            mi[r] = mnew;
            li[r] *= al;
#pragma unroll
            for (int nf = 0; nf < 8; nf++) { o[nf][2 * r] *= al; o[nf][2 * r + 1] *= al; }
            float ls = 0.0f;
#pragma unroll
            for (int nf = 0; nf < 8; nf++) {
                const float p0 = fexp2(s[nf][2 * r] - mnew);
                const float p1 = fexp2(s[nf][2 * r + 1] - mnew);
                ls += p0 + p1;
                s[nf][2 * r] = p0;
                s[nf][2 * r + 1] = p1;
            }
            ls += __shfl_xor_sync(0xffffffffu, ls, 1);
            ls += __shfl_xor_sync(0xffffffffu, ls, 2);
            li[r] += ls;
        }

        // ---- pack P into single-fp16 A-fragments ----
        uint32_t ph[4][4];
#pragma unroll
        for (int ks = 0; ks < 4; ks++) {
            ph[ks][0] = pack_h2(s[2 * ks][0],     s[2 * ks][1]);
            ph[ks][1] = pack_h2(s[2 * ks][2],     s[2 * ks][3]);
            ph[ks][2] = pack_h2(s[2 * ks + 1][0], s[2 * ks + 1][1]);
            ph[ks][3] = pack_h2(s[2 * ks + 1][2], s[2 * ks + 1][3]);
        }

        // ---- O += P @ V ----
#pragma unroll
        for (int ks = 0; ks < 4; ks++) {
#pragma unroll
            for (int dg = 0; dg < 4; dg++) {
                uint32_t vh[4];
                const uint32_t off = st + ATILE
                                   + (uint32_t)(ks * 16 + (lane & 15)) * ATROW
                                   + (dg * 16 + ((lane >> 4) << 3)) * 2;
                ldsm_x4t(vh[0], vh[1], vh[2], vh[3], off);
                mma_f16(o[dg * 2],     ph[ks], vh[0], vh[1]);
                mma_f16(o[dg * 2 + 1], ph[ks], vh[2], vh[3]);
            }
        }
        __syncthreads();
    }

    // epilogue: normalize, single fp16 (out-proj input)
#pragma unroll
    for (int r = 0; r < 2; r++) {
        const float inv = 1.0f / li[r];
        const size_t ob = (size_t)(b * SEQ + q0 + w * 16 + g + r * 8) * HID + h * HD;
#pragma unroll
        for (int nf = 0; nf < 8; nf++)
            *(uint32_t*)(Oh + ob + nf * 8 + tq * 2) =
                pack_h2(o[nf][2 * r] * inv, o[nf][2 * r + 1] * inv);
    }
}

// ---------------------------------------------------------------------------
// Launch
// ---------------------------------------------------------------------------
extern "C" void kernel_launch(void* const* d_in, const int* in_sizes, int n_in,
                              void* d_out, int out_size) {
    const float* hidden = (const float*)d_in[0];
    const void*  maskp  = d_in[1];
    const float* Wqkv   = (const float*)d_in[2];
    const float* Wout   = (const float*)d_in[3];
    const float* bout   = (const float*)d_in[4];
    float*       out    = (float*)d_out;

    void *p_qkv, *p_ah, *p_wq, *p_wo;
    cudaGetSymbolAddress(&p_qkv, g_qkv);
    cudaGetSymbolAddress(&p_ah, g_ah);
    cudaGetSymbolAddress(&p_wq, g_wq);
    cudaGetSymbolAddress(&p_wo, g_wo);

    cudaFuncSetAttribute((const void*)f16_gemm_kernel<0>,
                         cudaFuncAttributeMaxDynamicSharedMemorySize, GM_SMEM);
    cudaFuncSetAttribute((const void*)f16_gemm_kernel<1>,
                         cudaFuncAttributeMaxDynamicSharedMemorySize, GM_SMEM);
    cudaFuncSetAttribute(mma_attn_kernel,
                         cudaFuncAttributeMaxDynamicSharedMemorySize, ATT_SMEM);

    // 1. fused prep: mask + hidden fp16 + both weight transposes (one launch)
    prep_kernel<<<PREP_BLKS, 256>>>(hidden, Wqkv, Wout, maskp);

    // 2. QKV projection (1 MMA/k16, KC=64) -> Q (pre-scaled) | K | V single fp16
    f16_gemm_kernel<0><<<dim3(QKV3 / 128, MROWS / 128), 256, GM_SMEM>>>(
        (const __half*)p_ah, (const __half*)p_wq,
        nullptr, nullptr, (__half*)p_qkv, MROWS, QKV3, HID);

    // 3. fp16 flash attention -> single fp16 attention output
    mma_attn_kernel<<<dim3(SEQ / 128, NH, BATCH), 256, ATT_SMEM>>>(
        (const __half*)p_qkv, (__half*)p_ah);

    // 4. output projection (1 MMA/k16, KC=64, +bias)
    f16_gemm_kernel<1><<<dim3(HID / 128, MROWS / 128), 256, GM_SMEM>>>(
        (const __half*)p_ah, (const __half*)p_wo,
        bout, out, nullptr, MROWS, HID, HID);
}

// round 16
// speedup vs baseline: 4.3199x; 1.0022x over previous
#include <cuda_runtime.h>
#include <cuda_bf16.h>
#include <cuda_fp16.h>
#include <cstdint>

#define BATCH 4
#define SEQ   2048
#define NH    16
#define HD    64
#define HID   1024
#define QKV3  3072
#define MROWS (BATCH * SEQ)        // 8192

// 0.125 * log2(e): folded into Q at the QKV epilogue (softmax in base-2 domain)
#define QSF 0.18033688011112042f

// ---------------------------------------------------------------------------
// Scratch (static device globals — allocation-free per harness rules)
// ---------------------------------------------------------------------------
__device__ __half        g_qkv[MROWS * QKV3];          // Q (pre-scaled) | K | V, single fp16
__device__ int           g_mask[BATCH * SEQ];
__device__ unsigned long long g_mbits[BATCH * 32];     // 64-key tile bitmasks
__device__ __half        g_ah[MROWS * HID];            // activation single fp16 (hidden, then attn out)
__device__ __half        g_wq[QKV3 * HID];             // Wqkv^T single fp16 [N,K]
__device__ __half        g_wo[HID * HID];              // Wout^T single fp16 [N,K]

// ---------------------------------------------------------------------------
// PTX helpers (arch-portable sm_80+; tcgen05 unavailable via compute_103;
// s8 mma.sync measured ~4-5x worse rt than HMMA on sm_103 — do not use)
// ---------------------------------------------------------------------------
__device__ __forceinline__ uint32_t smem_u32(const void* p) {
    uint32_t a;
    asm("{ .reg .u64 t; cvta.to.shared.u64 t, %1; cvt.u32.u64 %0, t; }" : "=r"(a) : "l"(p));
    return a;
}
__device__ __forceinline__ void ldsm_x4(uint32_t& r0, uint32_t& r1, uint32_t& r2, uint32_t& r3,
                                        uint32_t addr) {
    asm volatile("ldmatrix.sync.aligned.m8n8.x4.shared.b16 {%0,%1,%2,%3}, [%4];"
                 : "=r"(r0), "=r"(r1), "=r"(r2), "=r"(r3) : "r"(addr));
}
__device__ __forceinline__ void ldsm_x4t(uint32_t& r0, uint32_t& r1, uint32_t& r2, uint32_t& r3,
                                         uint32_t addr) {
    asm volatile("ldmatrix.sync.aligned.m8n8.x4.trans.shared.b16 {%0,%1,%2,%3}, [%4];"
                 : "=r"(r0), "=r"(r1), "=r"(r2), "=r"(r3) : "r"(addr));
}
__device__ __forceinline__ void mma_f16(float* c, const uint32_t* a, uint32_t b0, uint32_t b1) {
    asm volatile(
        "mma.sync.aligned.m16n8k16.row.col.f32.f16.f16.f32 "
        "{%0,%1,%2,%3}, {%4,%5,%6,%7}, {%8,%9}, {%0,%1,%2,%3};"
        : "+f"(c[0]), "+f"(c[1]), "+f"(c[2]), "+f"(c[3])
        : "r"(a[0]), "r"(a[1]), "r"(a[2]), "r"(a[3]), "r"(b0), "r"(b1));
}
__device__ __forceinline__ float fexp2(float x) {
    float y; asm("ex2.approx.f32 %0, %1;" : "=f"(y) : "f"(x)); return y;
}
__device__ __forceinline__ uint32_t pack_h2(float x, float y) {
    __half2 v; v.x = __float2half(x); v.y = __float2half(y);
    return *(uint32_t*)&v;
}
#define CP_ASYNC16(dst, src) \
    asm volatile("cp.async.cg.shared.global [%0], [%1], 16;" :: "r"(dst), "l"(src))
#define CP_COMMIT() asm volatile("cp.async.commit_group;" ::: "memory")
#define CP_WAIT(n)  asm volatile("cp.async.wait_group %0;" :: "n"(n) : "memory")

// ---------------------------------------------------------------------------
// Fused prep kernel (R15-proven): block 0 -> mask; [1,593) hidden fp16;
// [593,3665) Wqkv^T; [3665,4689) Wout^T.
// ---------------------------------------------------------------------------
#define PREP_CONV_BLKS 592
#define PREP_WQ_BLKS   (QKV3 / 32 * HID / 32)   // 3072
#define PREP_WO_BLKS   (HID / 32 * HID / 32)    // 1024
#define PREP_BLKS      (1 + PREP_CONV_BLKS + PREP_WQ_BLKS + PREP_WO_BLKS)

__device__ __forceinline__ void quantWT_part(const float* __restrict__ W,
                                             __half* __restrict__ WT,
                                             int K, int N, int k0, int n0,
                                             float tile[32][33]) {
    int tx = threadIdx.x & 31, ty = threadIdx.x >> 5;
    for (int r = ty; r < 32; r += 8)
        tile[r][tx] = W[(size_t)(k0 + r) * N + n0 + tx];
    __syncthreads();
    for (int r = ty; r < 32; r += 8)
        WT[(size_t)(n0 + r) * K + k0 + tx] = __float2half(tile[tx][r]);
}

__global__ void prep_kernel(const float* __restrict__ hidden,
                            const float* __restrict__ Wqkv,
                            const float* __restrict__ Wout,
                            const void* __restrict__ maskp) {
    __shared__ float tile[32][33];
    const int bid = blockIdx.x;
    const int tid = threadIdx.x;

    if (bid == 0) {
        __shared__ int mode;
        if (tid == 0) {
            unsigned w0 = ((const unsigned*)maskp)[0];
            if (w0 == 1u || w0 == 0u)    mode = 0;  // int32
            else if (w0 == 0x3F800000u)  mode = 1;  // float32
            else if (w0 == 0x01010101u)  mode = 2;  // uint8
            else if (w0 == 0x3F803F80u)  mode = 3;  // bf16 pair
            else                          mode = 2;
        }
        __syncthreads();
        int m = mode;
        for (int i = tid; i < BATCH * SEQ; i += blockDim.x) {
            int v;
            if (m == 0)      v = (((const int*)maskp)[i] != 0);
            else if (m == 1) v = (((const float*)maskp)[i] != 0.0f);
            else if (m == 2) v = (((const unsigned char*)maskp)[i] != 0);
            else { unsigned short h = ((const unsigned short*)maskp)[i]; v = ((h & 0x7FFF) != 0); }
            g_mask[i] = v;
        }
        __syncthreads();
        for (int t = tid; t < BATCH * 32; t += blockDim.x) {
            int b = t >> 5, kt = t & 31;
            unsigned long long mb = 0ull;
            for (int j = 0; j < 64; j++)
                mb |= ((unsigned long long)(g_mask[b * SEQ + kt * 64 + j] & 1)) << j;
            g_mbits[t] = mb;
        }
    } else if (bid < 1 + PREP_CONV_BLKS) {
        const int vb = bid - 1;
        const int n4 = MROWS * HID / 4;
        const int stride = PREP_CONV_BLKS * 256;
        for (int i = vb * 256 + tid; i < n4; i += stride) {
            float4 v = ((const float4*)hidden)[i];
            ((uint32_t*)g_ah)[i * 2]     = pack_h2(v.x, v.y);
            ((uint32_t*)g_ah)[i * 2 + 1] = pack_h2(v.z, v.w);
        }
    } else if (bid < 1 + PREP_CONV_BLKS + PREP_WQ_BLKS) {
        const int idx = bid - 1 - PREP_CONV_BLKS;
        const int n0 = (idx % (QKV3 / 32)) * 32;
        const int k0 = (idx / (QKV3 / 32)) * 32;
        quantWT_part(Wqkv, g_wq, HID, QKV3, k0, n0, tile);
    } else {
        const int idx = bid - 1 - PREP_CONV_BLKS - PREP_WQ_BLKS;
        const int n0 = (idx % (HID / 32)) * 32;
        const int k0 = (idx / (HID / 32)) * 32;
        quantWT_part(Wout, g_wo, HID, HID, k0, n0, tile);
    }
}

// ---------------------------------------------------------------------------
// fp16 single-A GEMM (R15-proven, unchanged): 1 MMA/k16, KC=64, occ 2.
// ---------------------------------------------------------------------------
#define KC        64
#define TROW      144
#define TILE_B    (128 * TROW)          // 18432
#define STAGE_B   (2 * TILE_B)          // 36864: A | B
#define GM_SMEM   (2 * STAGE_B)         // 73728

template <int MODE>
__global__ __launch_bounds__(256, 2)
void f16_gemm_kernel(const __half* __restrict__ Ah, const __half* __restrict__ WT,
                     const float* __restrict__ bias, float* __restrict__ C,
                     __half* __restrict__ Ch,
                     int M, int N, int K) {
    extern __shared__ char smem[];
    const uint32_t sb = smem_u32(smem);
    const int tid   = threadIdx.x;
    const int lane  = tid & 31;
    const int wid   = tid >> 5;
    const int warpM = wid & 3;
    const int warpN = wid >> 2;
    const int m0 = blockIdx.y * 128;
    const int n0 = blockIdx.x * 128;
    const int nch = K / KC;

    auto load_stage = [&](int kc0, int s) {
        const uint32_t stg = sb + s * STAGE_B;
#pragma unroll
        for (int t = 0; t < 8; t++) {
            const int id   = tid + t * 256;
            const int tile = id >> 10;            // 0:A 1:B
            const int rem  = id & 1023;
            const int row  = rem >> 3;
            const int q    = rem & 7;
            const __half* src = tile ? (WT + (size_t)(n0 + row) * K + kc0 + q * 8)
                                     : (Ah + (size_t)(m0 + row) * K + kc0 + q * 8);
            CP_ASYNC16(stg + tile * TILE_B + row * TROW + q * 16, src);
        }
        CP_COMMIT();
    };

    float c[2][8][4];
#pragma unroll
    for (int i = 0; i < 2; i++)
#pragma unroll
        for (int j = 0; j < 8; j++)
#pragma unroll
            for (int r = 0; r < 4; r++) c[i][j][r] = 0.0f;

    const int arow = warpM * 32 + (lane & 15);
    const int acol = (lane >> 4) * 8;
    const int brow = warpN * 64 + (lane & 7) + ((lane >> 4) << 3);
    const int bck  = ((lane >> 3) & 1) * 8;

    load_stage(0, 0);
    load_stage(KC, 1);

    for (int ch = 0; ch < nch; ch++) {
        CP_WAIT(1);
        __syncthreads();

        const uint32_t stg = sb + (ch & 1) * STAGE_B;
        const uint32_t ahb = stg;
        const uint32_t bbb = stg + TILE_B;

#pragma unroll
        for (int k16 = 0; k16 < 4; k16++) {
            uint32_t fah[2][4];
#pragma unroll
            for (int mt = 0; mt < 2; mt++) {
                uint32_t off = (uint32_t)(arow + mt * 16) * TROW + (k16 * 16 + acol) * 2;
                ldsm_x4(fah[mt][0], fah[mt][1], fah[mt][2], fah[mt][3], ahb + off);
            }
#pragma unroll
            for (int np = 0; np < 4; np++) {
                uint32_t bf[4];
                uint32_t off = (uint32_t)(brow + np * 16) * TROW + (k16 * 16 + bck) * 2;
                ldsm_x4(bf[0], bf[1], bf[2], bf[3], bbb + off);
#pragma unroll
                for (int mt = 0; mt < 2; mt++)
#pragma unroll
                    for (int half = 0; half < 2; half++)
                        mma_f16(c[mt][np * 2 + half], fah[mt], bf[half * 2], bf[half * 2 + 1]);
            }
        }
        __syncthreads();
        if (ch + 2 < nch) load_stage((ch + 2) * KC, ch & 1);
        else CP_COMMIT();   // placeholder group: keeps CP_WAIT(1) accounting exact
    }

    const int g   = lane >> 2;
    const int tig = lane & 3;
#pragma unroll
    for (int mt = 0; mt < 2; mt++) {
        const int row = m0 + warpM * 32 + mt * 16 + g;
#pragma unroll
        for (int nt = 0; nt < 8; nt++) {
            const int col = n0 + warpN * 64 + nt * 8 + tig * 2;
            if (MODE == 1) {
                float2 v0 = make_float2(c[mt][nt][0] + bias[col], c[mt][nt][1] + bias[col + 1]);
                float2 v1 = make_float2(c[mt][nt][2] + bias[col], c[mt][nt][3] + bias[col + 1]);
                *(float2*)(C + (size_t)row * N + col)       = v0;
                *(float2*)(C + (size_t)(row + 8) * N + col) = v1;
            } else {
                const float sc = (col < HID) ? QSF : 1.0f;
                *(uint32_t*)(Ch + (size_t)row * N + col) =
                    pack_h2(c[mt][nt][0] * sc, c[mt][nt][1] * sc);
                *(uint32_t*)(Ch + (size_t)(row + 8) * N + col) =
                    pack_h2(c[mt][nt][2] * sc, c[mt][nt][3] * sc);
            }
        }
    }
}

// ---------------------------------------------------------------------------
// Persistent fp16 flash attention: 304 CTAs loop over 1024 (b,h,q-tile)
// items. Per-tile: o-rescale skipped by warp vote when no row max rises
// (bit-identical when taken); l cross-lane reduction deferred to epilogue.
// ---------------------------------------------------------------------------
#define ATROW 144
#define ATILE (64 * ATROW)                 // 9216
#define ASTAGE (2 * ATILE)                 // 18432: K | V
#define QTILE (128 * ATROW)                // 18432
#define ATT_SMEM (2 * ASTAGE + QTILE + 160)   // 55456
#define NITEMS (BATCH * NH * (SEQ / 128))  // 1024
#define ATT_GRID 304

__global__ __launch_bounds__(256, 2)
void mma_attn_kernel(const __half* __restrict__ QKV, __half* __restrict__ Oh) {
    extern __shared__ char sm[];
    const uint32_t sb  = smem_u32(sm);
    const uint32_t qsm = sb + 2 * ASTAGE;
    int* list = (int*)(sm + 2 * ASTAGE + QTILE);

    const int tid  = threadIdx.x;
    const int lane = tid & 31;
    const int w    = tid >> 5;
    const int g    = lane >> 2;
    const int tq   = lane & 3;

    const uint32_t qrowoff = qsm + (uint32_t)(w * 16 + (lane & 15)) * ATROW
                           + ((lane >> 4) << 3) * 2;

    for (int item = blockIdx.x; item < NITEMS; item += gridDim.x) {
        const int b  = item >> 8;
        const int h  = (item >> 4) & 15;
        const int q0 = (item & 15) << 7;

        __syncthreads();   // smem/list reuse fence between items
        if (w == 0) {
            unsigned long long mb = g_mbits[b * 32 + lane];
            unsigned act = __ballot_sync(0xffffffffu, mb != 0ull);
            int pos = __popc(act & ((1u << lane) - 1));
            if (mb != 0ull) list[pos] = lane;
            if (lane == 0) list[32] = __popc(act);
        }

        // stage Q tile (128 rows x 64 fp16)
        {
            const int tok0 = b * SEQ + q0;
#pragma unroll
            for (int t = 0; t < 4; t++) {
                const int id  = tid + t * 256;
                const int r   = id >> 3;
                const int seg = id & 7;
                const size_t go = (size_t)(tok0 + r) * QKV3 + h * HD + seg * 8;
                CP_ASYNC16(qsm + r * ATROW + seg * 16, QKV + go);
            }
            CP_COMMIT();
        }
        __syncthreads();
        const int ncnt = list[32];

        auto load_tile = [&](int kt, int stg) {
            const int tok0 = b * SEQ + kt * 64;
            const uint32_t base = sb + stg * ASTAGE;
#pragma unroll
            for (int t = 0; t < 4; t++) {
                const int id  = tid + t * 256;
                const int arr = id >> 9;              // 0:K 1:V
                const int rem = id & 511;
                const int r   = rem >> 3;
                const int q   = rem & 7;
                const size_t go = (size_t)(tok0 + r) * QKV3 + h * HD + q * 8;
                const __half* src = arr ? (QKV + go + 2 * HID) : (QKV + go + HID);
                CP_ASYNC16(base + arr * ATILE + r * ATROW + q * 16, src);
            }
            CP_COMMIT();
        };

        float o[8][4];
#pragma unroll
        for (int j = 0; j < 8; j++)
#pragma unroll
            for (int r = 0; r < 4; r++) o[j][r] = 0.0f;
        float mi[2] = {-1e30f, -1e30f}, li[2] = {0.0f, 0.0f};   // li: per-lane partial

        if (ncnt > 0) load_tile(list[0], 0);

        for (int it = 0; it < ncnt; it++) {
            if (it + 1 < ncnt) { load_tile(list[it + 1], (it + 1) & 1); CP_WAIT(1); }
            else CP_WAIT(0);
            __syncthreads();
            const uint32_t st = sb + (it & 1) * ASTAGE;
            const int kt = list[it];

            // ---- S = Q @ K^T ----
            float s[8][4];
#pragma unroll
            for (int j = 0; j < 8; j++)
#pragma unroll
                for (int r = 0; r < 4; r++) s[j][r] = 0.0f;

#pragma unroll
            for (int kd = 0; kd < 4; kd++) {
                uint32_t qh4[4];
                ldsm_x4(qh4[0], qh4[1], qh4[2], qh4[3], qrowoff + kd * 32);
#pragma unroll
                for (int kg = 0; kg < 4; kg++) {
                    uint32_t kh[4];
                    const uint32_t off = st + (uint32_t)(kg * 16 + (lane & 7) + ((lane >> 4) << 3)) * ATROW
                                            + (kd * 16 + ((lane >> 3) & 1) * 8) * 2;
                    ldsm_x4(kh[0], kh[1], kh[2], kh[3], off);
                    mma_f16(s[kg * 2],     qh4, kh[0], kh[1]);
                    mma_f16(s[kg * 2 + 1], qh4, kh[2], kh[3]);
                }
            }

            // ---- key-padding mask ----
            const unsigned long long mb = g_mbits[b * 32 + kt];
            if (mb != ~0ull) {
#pragma unroll
                for (int nf = 0; nf < 8; nf++) {
                    const int c0 = nf * 8 + tq * 2;
                    if (!((mb >> c0) & 1))       { s[nf][0] = -1e30f; s[nf][2] = -1e30f; }
                    if (!((mb >> (c0 + 1)) & 1)) { s[nf][1] = -1e30f; s[nf][3] = -1e30f; }
                }
            }

            // ---- online softmax (base-2; Q pre-scaled) ----
#pragma unroll
            for (int r = 0; r < 2; r++) {
                float mx = -1e30f;
#pragma unroll
                for (int nf = 0; nf < 8; nf++)
                    mx = fmaxf(mx, fmaxf(s[nf][2 * r], s[nf][2 * r + 1]));
                mx = fmaxf(mx, __shfl_xor_sync(0xffffffffu, mx, 1));
                mx = fmaxf(mx, __shfl_xor_sync(0xffffffffu, mx, 2));
                const float mnew = fmaxf(mi[r], mx);
                const float al = fexp2(mi[r] - mnew);
                mi[r] = mnew;
                li[r] *= al;
                // skip o-rescale when no lane's row max rose (al==1 exactly)
                if (__any_sync(0xffffffffu, al != 1.0f)) {
#pragma unroll
                    for (int nf = 0; nf < 8; nf++) { o[nf][2 * r] *= al; o[nf][2 * r + 1] *= al; }
                }
                float ls = 0.0f;
#pragma unroll
                for (int nf = 0; nf < 8; nf++) {
                    const float p0 = fexp2(s[nf][2 * r] - mnew);
                    const float p1 = fexp2(s[nf][2 * r + 1] - mnew);
                    ls += p0 + p1;
                    s[nf][2 * r] = p0;
                    s[nf][2 * r + 1] = p1;
                }
                li[r] += ls;        // per-lane partial; reduced at epilogue
            }

            // ---- pack P into single-fp16 A-fragments ----
            uint32_t ph[4][4];
#pragma unroll
            for (int ks = 0; ks < 4; ks++) {
                ph[ks][0] = pack_h2(s[2 * ks][0],     s[2 * ks][1]);
                ph[ks][1] = pack_h2(s[2 * ks][2],     s[2 * ks][3]);
                ph[ks][2] = pack_h2(s[2 * ks + 1][0], s[2 * ks + 1][1]);
                ph[ks][3] = pack_h2(s[2 * ks + 1][2], s[2 * ks + 1][3]);
            }

            // ---- O += P @ V ----
#pragma unroll
            for (int ks = 0; ks < 4; ks++) {
#pragma unroll
                for (int dg = 0; dg < 4; dg++) {
                    uint32_t vh[4];
                    const uint32_t off = st + ATILE
                                       + (uint32_t)(ks * 16 + (lane & 15)) * ATROW
                                       + (dg * 16 + ((lane >> 4) << 3)) * 2;
                    ldsm_x4t(vh[0], vh[1], vh[2], vh[3], off);
                    mma_f16(o[dg * 2],     ph[ks], vh[0], vh[1]);
                    mma_f16(o[dg * 2 + 1], ph[ks], vh[2], vh[3]);
                }
            }
            __syncthreads();
        }

        // ---- epilogue: reduce li across the 4 tq lanes, normalize, store ----
#pragma unroll
        for (int r = 0; r < 2; r++) {
            float lt = li[r];
            lt += __shfl_xor_sync(0xffffffffu, lt, 1);
            lt += __shfl_xor_sync(0xffffffffu, lt, 2);
            const float inv = 1.0f / lt;
            const size_t ob = (size_t)(b * SEQ + q0 + w * 16 + g + r * 8) * HID + h * HD;
#pragma unroll
            for (int nf = 0; nf < 8; nf++)
                *(uint32_t*)(Oh + ob + nf * 8 + tq * 2) =
                    pack_h2(o[nf][2 * r] * inv, o[nf][2 * r + 1] * inv);
        }
    }
}

// ---------------------------------------------------------------------------
// Launch
// ---------------------------------------------------------------------------
extern "C" void kernel_launch(void* const* d_in, const int* in_sizes, int n_in,
                              void* d_out, int out_size) {
    const float* hidden = (const float*)d_in[0];
    const void*  maskp  = d_in[1];
    const float* Wqkv   = (const float*)d_in[2];
    const float* Wout   = (const float*)d_in[3];
    const float* bout   = (const float*)d_in[4];
    float*       out    = (float*)d_out;

    void *p_qkv, *p_ah, *p_wq, *p_wo;
    cudaGetSymbolAddress(&p_qkv, g_qkv);
    cudaGetSymbolAddress(&p_ah, g_ah);
    cudaGetSymbolAddress(&p_wq, g_wq);
    cudaGetSymbolAddress(&p_wo, g_wo);

    cudaFuncSetAttribute((const void*)f16_gemm_kernel<0>,
                         cudaFuncAttributeMaxDynamicSharedMemorySize, GM_SMEM);
    cudaFuncSetAttribute((const void*)f16_gemm_kernel<1>,
                         cudaFuncAttributeMaxDynamicSharedMemorySize, GM_SMEM);
    cudaFuncSetAttribute(mma_attn_kernel,
                         cudaFuncAttributeMaxDynamicSharedMemorySize, ATT_SMEM);

    // 1. fused prep: mask + hidden fp16 + both weight transposes
    prep_kernel<<<PREP_BLKS, 256>>>(hidden, Wqkv, Wout, maskp);

    // 2. QKV projection (1 MMA/k16, KC=64) -> Q (pre-scaled) | K | V single fp16
    f16_gemm_kernel<0><<<dim3(QKV3 / 128, MROWS / 128), 256, GM_SMEM>>>(
        (const __half*)p_ah, (const __half*)p_wq,
        nullptr, nullptr, (__half*)p_qkv, MROWS, QKV3, HID);

    // 3. persistent fp16 flash attention -> single fp16 attention output
    mma_attn_kernel<<<ATT_GRID, 256, ATT_SMEM>>>(
        (const __half*)p_qkv, (__half*)p_ah);

    // 4. output projection (1 MMA/k16, KC=64, +bias)
    f16_gemm_kernel<1><<<dim3(HID / 128, MROWS / 128), 256, GM_SMEM>>>(
        (const __half*)p_ah, (const __half*)p_wo,
        bout, out, nullptr, MROWS, HID, HID);
}

// round 17
// speedup vs baseline: 4.4967x; 1.0409x over previous
#include <cuda_runtime.h>
#include <cuda_bf16.h>
#include <cuda_fp16.h>
#include <cstdint>

#define BATCH 4
#define SEQ   2048
#define NH    16
#define HD    64
#define HID   1024
#define QKV3  3072
#define MROWS (BATCH * SEQ)        // 8192

// 0.125 * log2(e): folded into Q at the QKV epilogue (softmax in base-2 domain)
#define QSF 0.18033688011112042f

// ---------------------------------------------------------------------------
// Scratch (static device globals — allocation-free per harness rules)
// ---------------------------------------------------------------------------
__device__ __half        g_qkv[MROWS * QKV3];          // Q (pre-scaled) | K | V, single fp16
__device__ int           g_mask[BATCH * SEQ];
__device__ unsigned long long g_mbits[BATCH * 32];     // 64-key tile bitmasks
__device__ __half        g_ah[MROWS * HID];            // activation single fp16 (hidden, then attn out)
__device__ __half        g_wq[QKV3 * HID];             // Wqkv^T single fp16 [N,K]
__device__ __half        g_wo[HID * HID];              // Wout^T single fp16 [N,K]

// ---------------------------------------------------------------------------
// PTX helpers (arch-portable sm_80+; tcgen05 unavailable via compute_103;
// s8 mma.sync measured ~4-5x worse rt than HMMA on sm_103 — do not use)
// ---------------------------------------------------------------------------
__device__ __forceinline__ uint32_t smem_u32(const void* p) {
    uint32_t a;
    asm("{ .reg .u64 t; cvta.to.shared.u64 t, %1; cvt.u32.u64 %0, t; }" : "=r"(a) : "l"(p));
    return a;
}
__device__ __forceinline__ void ldsm_x4(uint32_t& r0, uint32_t& r1, uint32_t& r2, uint32_t& r3,
                                        uint32_t addr) {
    asm volatile("ldmatrix.sync.aligned.m8n8.x4.shared.b16 {%0,%1,%2,%3}, [%4];"
                 : "=r"(r0), "=r"(r1), "=r"(r2), "=r"(r3) : "r"(addr));
}
__device__ __forceinline__ void ldsm_x4t(uint32_t& r0, uint32_t& r1, uint32_t& r2, uint32_t& r3,
                                         uint32_t addr) {
    asm volatile("ldmatrix.sync.aligned.m8n8.x4.trans.shared.b16 {%0,%1,%2,%3}, [%4];"
                 : "=r"(r0), "=r"(r1), "=r"(r2), "=r"(r3) : "r"(addr));
}
__device__ __forceinline__ void mma_f16(float* c, const uint32_t* a, uint32_t b0, uint32_t b1) {
    asm volatile(
        "mma.sync.aligned.m16n8k16.row.col.f32.f16.f16.f32 "
        "{%0,%1,%2,%3}, {%4,%5,%6,%7}, {%8,%9}, {%0,%1,%2,%3};"
        : "+f"(c[0]), "+f"(c[1]), "+f"(c[2]), "+f"(c[3])
        : "r"(a[0]), "r"(a[1]), "r"(a[2]), "r"(a[3]), "r"(b0), "r"(b1));
}
__device__ __forceinline__ float fexp2(float x) {
    float y; asm("ex2.approx.f32 %0, %1;" : "=f"(y) : "f"(x)); return y;
}
__device__ __forceinline__ uint32_t pack_h2(float x, float y) {
    __half2 v; v.x = __float2half(x); v.y = __float2half(y);
    return *(uint32_t*)&v;
}
__device__ __forceinline__ uint32_t exp2_h2(uint32_t p) {
    asm("ex2.approx.f16x2 %0, %0;" : "+r"(p));
    return p;
}
#define ONE2 0x3C003C00u      // half2(1.0, 1.0)
#define CP_ASYNC16(dst, src) \
    asm volatile("cp.async.cg.shared.global [%0], [%1], 16;" :: "r"(dst), "l"(src))
#define CP_COMMIT() asm volatile("cp.async.commit_group;" ::: "memory")
#define CP_WAIT(n)  asm volatile("cp.async.wait_group %0;" :: "n"(n) : "memory")

// ---------------------------------------------------------------------------
// Fused prep kernel (R15-proven): block 0 -> mask; [1,593) hidden fp16;
// [593,3665) Wqkv^T; [3665,4689) Wout^T.
// ---------------------------------------------------------------------------
#define PREP_CONV_BLKS 592
#define PREP_WQ_BLKS   (QKV3 / 32 * HID / 32)   // 3072
#define PREP_WO_BLKS   (HID / 32 * HID / 32)    // 1024
#define PREP_BLKS      (1 + PREP_CONV_BLKS + PREP_WQ_BLKS + PREP_WO_BLKS)

__device__ __forceinline__ void quantWT_part(const float* __restrict__ W,
                                             __half* __restrict__ WT,
                                             int K, int N, int k0, int n0,
                                             float tile[32][33]) {
    int tx = threadIdx.x & 31, ty = threadIdx.x >> 5;
    for (int r = ty; r < 32; r += 8)
        tile[r][tx] = W[(size_t)(k0 + r) * N + n0 + tx];
    __syncthreads();
    for (int r = ty; r < 32; r += 8)
        WT[(size_t)(n0 + r) * K + k0 + tx] = __float2half(tile[tx][r]);
}

__global__ void prep_kernel(const float* __restrict__ hidden,
                            const float* __restrict__ Wqkv,
                            const float* __restrict__ Wout,
                            const void* __restrict__ maskp) {
    __shared__ float tile[32][33];
    const int bid = blockIdx.x;
    const int tid = threadIdx.x;

    if (bid == 0) {
        __shared__ int mode;
        if (tid == 0) {
            unsigned w0 = ((const unsigned*)maskp)[0];
            if (w0 == 1u || w0 == 0u)    mode = 0;  // int32
            else if (w0 == 0x3F800000u)  mode = 1;  // float32
            else if (w0 == 0x01010101u)  mode = 2;  // uint8
            else if (w0 == 0x3F803F80u)  mode = 3;  // bf16 pair
            else                          mode = 2;
        }
        __syncthreads();
        int m = mode;
        for (int i = tid; i < BATCH * SEQ; i += blockDim.x) {
            int v;
            if (m == 0)      v = (((const int*)maskp)[i] != 0);
            else if (m == 1) v = (((const float*)maskp)[i] != 0.0f);
            else if (m == 2) v = (((const unsigned char*)maskp)[i] != 0);
            else { unsigned short h = ((const unsigned short*)maskp)[i]; v = ((h & 0x7FFF) != 0); }
            g_mask[i] = v;
        }
        __syncthreads();
        for (int t = tid; t < BATCH * 32; t += blockDim.x) {
            int b = t >> 5, kt = t & 31;
            unsigned long long mb = 0ull;
            for (int j = 0; j < 64; j++)
                mb |= ((unsigned long long)(g_mask[b * SEQ + kt * 64 + j] & 1)) << j;
            g_mbits[t] = mb;
        }
    } else if (bid < 1 + PREP_CONV_BLKS) {
        const int vb = bid - 1;
        const int n4 = MROWS * HID / 4;
        const int stride = PREP_CONV_BLKS * 256;
        for (int i = vb * 256 + tid; i < n4; i += stride) {
            float4 v = ((const float4*)hidden)[i];
            ((uint32_t*)g_ah)[i * 2]     = pack_h2(v.x, v.y);
            ((uint32_t*)g_ah)[i * 2 + 1] = pack_h2(v.z, v.w);
        }
    } else if (bid < 1 + PREP_CONV_BLKS + PREP_WQ_BLKS) {
        const int idx = bid - 1 - PREP_CONV_BLKS;
        const int n0 = (idx % (QKV3 / 32)) * 32;
        const int k0 = (idx / (QKV3 / 32)) * 32;
        quantWT_part(Wqkv, g_wq, HID, QKV3, k0, n0, tile);
    } else {
        const int idx = bid - 1 - PREP_CONV_BLKS - PREP_WQ_BLKS;
        const int n0 = (idx % (HID / 32)) * 32;
        const int k0 = (idx / (HID / 32)) * 32;
        quantWT_part(Wout, g_wo, HID, HID, k0, n0, tile);
    }
}

// ---------------------------------------------------------------------------
// fp16 single-A GEMM (R15-proven, unchanged): 1 MMA/k16, KC=64, occ 2.
// ---------------------------------------------------------------------------
#define KC        64
#define TROW      144
#define TILE_B    (128 * TROW)          // 18432
#define STAGE_B   (2 * TILE_B)          // 36864: A | B
#define GM_SMEM   (2 * STAGE_B)         // 73728

template <int MODE>
__global__ __launch_bounds__(256, 2)
void f16_gemm_kernel(const __half* __restrict__ Ah, const __half* __restrict__ WT,
                     const float* __restrict__ bias, float* __restrict__ C,
                     __half* __restrict__ Ch,
                     int M, int N, int K) {
    extern __shared__ char smem[];
    const uint32_t sb = smem_u32(smem);
    const int tid   = threadIdx.x;
    const int lane  = tid & 31;
    const int wid   = tid >> 5;
    const int warpM = wid & 3;
    const int warpN = wid >> 2;
    const int m0 = blockIdx.y * 128;
    const int n0 = blockIdx.x * 128;
    const int nch = K / KC;

    auto load_stage = [&](int kc0, int s) {
        const uint32_t stg = sb + s * STAGE_B;
#pragma unroll
        for (int t = 0; t < 8; t++) {
            const int id   = tid + t * 256;
            const int tile = id >> 10;            // 0:A 1:B
            const int rem  = id & 1023;
            const int row  = rem >> 3;
            const int q    = rem & 7;
            const __half* src = tile ? (WT + (size_t)(n0 + row) * K + kc0 + q * 8)
                                     : (Ah + (size_t)(m0 + row) * K + kc0 + q * 8);
            CP_ASYNC16(stg + tile * TILE_B + row * TROW + q * 16, src);
        }
        CP_COMMIT();
    };

    float c[2][8][4];
#pragma unroll
    for (int i = 0; i < 2; i++)
#pragma unroll
        for (int j = 0; j < 8; j++)
#pragma unroll
            for (int r = 0; r < 4; r++) c[i][j][r] = 0.0f;

    const int arow = warpM * 32 + (lane & 15);
    const int acol = (lane >> 4) * 8;
    const int brow = warpN * 64 + (lane & 7) + ((lane >> 4) << 3);
    const int bck  = ((lane >> 3) & 1) * 8;

    load_stage(0, 0);
    load_stage(KC, 1);

    for (int ch = 0; ch < nch; ch++) {
        CP_WAIT(1);
        __syncthreads();

        const uint32_t stg = sb + (ch & 1) * STAGE_B;
        const uint32_t ahb = stg;
        const uint32_t bbb = stg + TILE_B;

#pragma unroll
        for (int k16 = 0; k16 < 4; k16++) {
            uint32_t fah[2][4];
#pragma unroll
            for (int mt = 0; mt < 2; mt++) {
                uint32_t off = (uint32_t)(arow + mt * 16) * TROW + (k16 * 16 + acol) * 2;
                ldsm_x4(fah[mt][0], fah[mt][1], fah[mt][2], fah[mt][3], ahb + off);
            }
#pragma unroll
            for (int np = 0; np < 4; np++) {
                uint32_t bf[4];
                uint32_t off = (uint32_t)(brow + np * 16) * TROW + (k16 * 16 + bck) * 2;
                ldsm_x4(bf[0], bf[1], bf[2], bf[3], bbb + off);
#pragma unroll
                for (int mt = 0; mt < 2; mt++)
#pragma unroll
                    for (int half = 0; half < 2; half++)
                        mma_f16(c[mt][np * 2 + half], fah[mt], bf[half * 2], bf[half * 2 + 1]);
            }
        }
        __syncthreads();
        if (ch + 2 < nch) load_stage((ch + 2) * KC, ch & 1);
        else CP_COMMIT();   // placeholder group: keeps CP_WAIT(1) accounting exact
    }

    const int g   = lane >> 2;
    const int tig = lane & 3;
#pragma unroll
    for (int mt = 0; mt < 2; mt++) {
        const int row = m0 + warpM * 32 + mt * 16 + g;
#pragma unroll
        for (int nt = 0; nt < 8; nt++) {
            const int col = n0 + warpN * 64 + nt * 8 + tig * 2;
            if (MODE == 1) {
                float2 v0 = make_float2(c[mt][nt][0] + bias[col], c[mt][nt][1] + bias[col + 1]);
                float2 v1 = make_float2(c[mt][nt][2] + bias[col], c[mt][nt][3] + bias[col + 1]);
                *(float2*)(C + (size_t)row * N + col)       = v0;
                *(float2*)(C + (size_t)(row + 8) * N + col) = v1;
            } else {
                const float sc = (col < HID) ? QSF : 1.0f;
                *(uint32_t*)(Ch + (size_t)row * N + col) =
                    pack_h2(c[mt][nt][0] * sc, c[mt][nt][1] * sc);
                *(uint32_t*)(Ch + (size_t)(row + 8) * N + col) =
                    pack_h2(c[mt][nt][2] * sc, c[mt][nt][3] * sc);
            }
        }
    }
}

// ---------------------------------------------------------------------------
// Persistent fp16 flash attention:
//  - fp16x2 exp fused with P-pack (half the MUFU ops; P identical to what PV
//    consumes, l summed from those same values -> consistent normalization)
//  - l computed by ones-column MMA (no ls adds, no cross-lane l shuffles)
//  - triple-buffered K/V ring -> single barrier per tile
// ---------------------------------------------------------------------------
#define ATROW 144
#define ATILE (64 * ATROW)                 // 9216
#define ASTAGE (2 * ATILE)                 // 18432: K | V
#define QTILE (128 * ATROW)                // 18432
#define ATT_SMEM (3 * ASTAGE + QTILE + 160)   // 73888
#define NITEMS (BATCH * NH * (SEQ / 128))  // 1024
#define ATT_GRID 304

__global__ __launch_bounds__(256, 2)
void mma_attn_kernel(const __half* __restrict__ QKV, __half* __restrict__ Oh) {
    extern __shared__ char sm[];
    const uint32_t sb  = smem_u32(sm);
    const uint32_t qsm = sb + 3 * ASTAGE;
    int* list = (int*)(sm + 3 * ASTAGE + QTILE);

    const int tid  = threadIdx.x;
    const int lane = tid & 31;
    const int w    = tid >> 5;
    const int g    = lane >> 2;
    const int tq   = lane & 3;

    const uint32_t qrowoff = qsm + (uint32_t)(w * 16 + (lane & 15)) * ATROW
                           + ((lane >> 4) << 3) * 2;

    for (int item = blockIdx.x; item < NITEMS; item += gridDim.x) {
        const int b  = item >> 8;
        const int h  = (item >> 4) & 15;
        const int q0 = (item & 15) << 7;

        __syncthreads();   // smem/list reuse fence between items
        if (w == 0) {
            unsigned long long mb = g_mbits[b * 32 + lane];
            unsigned act = __ballot_sync(0xffffffffu, mb != 0ull);
            int pos = __popc(act & ((1u << lane) - 1));
            if (mb != 0ull) list[pos] = lane;
            if (lane == 0) list[32] = __popc(act);
        }

        // stage Q tile (128 rows x 64 fp16)
        {
            const int tok0 = b * SEQ + q0;
#pragma unroll
            for (int t = 0; t < 4; t++) {
                const int id  = tid + t * 256;
                const int r   = id >> 3;
                const int seg = id & 7;
                const size_t go = (size_t)(tok0 + r) * QKV3 + h * HD + seg * 8;
                CP_ASYNC16(qsm + r * ATROW + seg * 16, QKV + go);
            }
            CP_COMMIT();
        }
        __syncthreads();
        const int ncnt = list[32];

        auto load_tile = [&](int kt, int stg) {
            const int tok0 = b * SEQ + kt * 64;
            const uint32_t base = sb + stg * ASTAGE;
#pragma unroll
            for (int t = 0; t < 4; t++) {
                const int id  = tid + t * 256;
                const int arr = id >> 9;              // 0:K 1:V
                const int rem = id & 511;
                const int r   = rem >> 3;
                const int q   = rem & 7;
                const size_t go = (size_t)(tok0 + r) * QKV3 + h * HD + q * 8;
                const __half* src = arr ? (QKV + go + 2 * HID) : (QKV + go + HID);
                CP_ASYNC16(base + arr * ATILE + r * ATROW + q * 16, src);
            }
            CP_COMMIT();
        };

        float o[8][4];
#pragma unroll
        for (int j = 0; j < 8; j++)
#pragma unroll
            for (int r = 0; r < 4; r++) o[j][r] = 0.0f;
        float mi[2] = {-1e30f, -1e30f};
        float lacc[4] = {0.0f, 0.0f, 0.0f, 0.0f};   // l fragment via ones-MMA

        if (ncnt > 0) load_tile(list[0], 0);

        int buf = 0;                                 // ring position of current tile
        for (int it = 0; it < ncnt; it++) {
            if (it + 1 < ncnt) { load_tile(list[it + 1], (buf + 1) % 3); CP_WAIT(1); }
            else CP_WAIT(0);
            __syncthreads();   // single barrier per tile (triple-buffered ring)
            const uint32_t st = sb + buf * ASTAGE;
            const int kt = list[it];

            // ---- S = Q @ K^T ----
            float s[8][4];
#pragma unroll
            for (int j = 0; j < 8; j++)
#pragma unroll
                for (int r = 0; r < 4; r++) s[j][r] = 0.0f;

#pragma unroll
            for (int kd = 0; kd < 4; kd++) {
                uint32_t qh4[4];
                ldsm_x4(qh4[0], qh4[1], qh4[2], qh4[3], qrowoff + kd * 32);
#pragma unroll
                for (int kg = 0; kg < 4; kg++) {
                    uint32_t kh[4];
                    const uint32_t off = st + (uint32_t)(kg * 16 + (lane & 7) + ((lane >> 4) << 3)) * ATROW
                                            + (kd * 16 + ((lane >> 3) & 1) * 8) * 2;
                    ldsm_x4(kh[0], kh[1], kh[2], kh[3], off);
                    mma_f16(s[kg * 2],     qh4, kh[0], kh[1]);
                    mma_f16(s[kg * 2 + 1], qh4, kh[2], kh[3]);
                }
            }

            // ---- key-padding mask ----
            const unsigned long long mb = g_mbits[b * 32 + kt];
            if (mb != ~0ull) {
#pragma unroll
                for (int nf = 0; nf < 8; nf++) {
                    const int c0 = nf * 8 + tq * 2;
                    if (!((mb >> c0) & 1))       { s[nf][0] = -1e30f; s[nf][2] = -1e30f; }
                    if (!((mb >> (c0 + 1)) & 1)) { s[nf][1] = -1e30f; s[nf][3] = -1e30f; }
                }
            }

            // ---- online softmax: fp16x2 exp fused with P pack ----
            uint32_t ph[4][4];
#pragma unroll
            for (int r = 0; r < 2; r++) {
                float mx = -1e30f;
#pragma unroll
                for (int nf = 0; nf < 8; nf++)
                    mx = fmaxf(mx, fmaxf(s[nf][2 * r], s[nf][2 * r + 1]));
                mx = fmaxf(mx, __shfl_xor_sync(0xffffffffu, mx, 1));
                mx = fmaxf(mx, __shfl_xor_sync(0xffffffffu, mx, 2));
                const float mnew = fmaxf(mi[r], mx);
                const float al = fexp2(mi[r] - mnew);
                mi[r] = mnew;
                lacc[2 * r]     *= al;
                lacc[2 * r + 1] *= al;
                if (__any_sync(0xffffffffu, al != 1.0f)) {
#pragma unroll
                    for (int nf = 0; nf < 8; nf++) { o[nf][2 * r] *= al; o[nf][2 * r + 1] *= al; }
                }
#pragma unroll
                for (int nf = 0; nf < 8; nf++) {
                    uint32_t pp = pack_h2(s[nf][2 * r] - mnew, s[nf][2 * r + 1] - mnew);
                    ph[nf >> 1][(nf & 1) * 2 + r] = exp2_h2(pp);
                }
            }

            // ---- O += P @ V;  l += P @ 1 (ones-MMA, no shuffles) ----
#pragma unroll
            for (int ks = 0; ks < 4; ks++) {
                mma_f16(lacc, ph[ks], ONE2, ONE2);   // row sums -> lacc[0](row g), lacc[2](row g+8)
#pragma unroll
                for (int dg = 0; dg < 4; dg++) {
                    uint32_t vh[4];
                    const uint32_t off = st + ATILE
                                       + (uint32_t)(ks * 16 + (lane & 15)) * ATROW
                                       + (dg * 16 + ((lane >> 4) << 3)) * 2;
                    ldsm_x4t(vh[0], vh[1], vh[2], vh[3], off);
                    mma_f16(o[dg * 2],     ph[ks], vh[0], vh[1]);
                    mma_f16(o[dg * 2 + 1], ph[ks], vh[2], vh[3]);
                }
            }
            buf = (buf + 1) % 3;
            // no trailing barrier: next prefetch targets a buffer no laggard reads
        }

        // ---- epilogue: lane-local l (all columns equal), normalize, store ----
#pragma unroll
        for (int r = 0; r < 2; r++) {
            const float inv = 1.0f / lacc[2 * r];
            const size_t ob = (size_t)(b * SEQ + q0 + w * 16 + g + r * 8) * HID + h * HD;
#pragma unroll
            for (int nf = 0; nf < 8; nf++)
                *(uint32_t*)(Oh + ob + nf * 8 + tq * 2) =
                    pack_h2(o[nf][2 * r] * inv, o[nf][2 * r + 1] * inv);
        }
    }
}

// ---------------------------------------------------------------------------
// Launch
// ---------------------------------------------------------------------------
extern "C" void kernel_launch(void* const* d_in, const int* in_sizes, int n_in,
                              void* d_out, int out_size) {
    const float* hidden = (const float*)d_in[0];
    const void*  maskp  = d_in[1];
    const float* Wqkv   = (const float*)d_in[2];
    const float* Wout   = (const float*)d_in[3];
    const float* bout   = (const float*)d_in[4];
    float*       out    = (float*)d_out;

    void *p_qkv, *p_ah, *p_wq, *p_wo;
    cudaGetSymbolAddress(&p_qkv, g_qkv);
    cudaGetSymbolAddress(&p_ah, g_ah);
    cudaGetSymbolAddress(&p_wq, g_wq);
    cudaGetSymbolAddress(&p_wo, g_wo);

    cudaFuncSetAttribute((const void*)f16_gemm_kernel<0>,
                         cudaFuncAttributeMaxDynamicSharedMemorySize, GM_SMEM);
    cudaFuncSetAttribute((const void*)f16_gemm_kernel<1>,
                         cudaFuncAttributeMaxDynamicSharedMemorySize, GM_SMEM);
    cudaFuncSetAttribute(mma_attn_kernel,
                         cudaFuncAttributeMaxDynamicSharedMemorySize, ATT_SMEM);

    // 1. fused prep: mask + hidden fp16 + both weight transposes
    prep_kernel<<<PREP_BLKS, 256>>>(hidden, Wqkv, Wout, maskp);

    // 2. QKV projection (1 MMA/k16, KC=64) -> Q (pre-scaled) | K | V single fp16
    f16_gemm_kernel<0><<<dim3(QKV3 / 128, MROWS / 128), 256, GM_SMEM>>>(
        (const __half*)p_ah, (const __half*)p_wq,
        nullptr, nullptr, (__half*)p_qkv, MROWS, QKV3, HID);

    // 3. persistent fp16 flash attention -> single fp16 attention output
    mma_attn_kernel<<<ATT_GRID, 256, ATT_SMEM>>>(
        (const __half*)p_qkv, (__half*)p_ah);

    // 4. output projection (1 MMA/k16, KC=64, +bias)
    f16_gemm_kernel<1><<<dim3(HID / 128, MROWS / 128), 256, GM_SMEM>>>(
        (const __half*)p_ah, (const __half*)p_wo,
        bout, out, nullptr, MROWS, HID, HID);
}